// round 1
// baseline (speedup 1.0000x reference)
#include <cuda_runtime.h>
#include <cuda_bf16.h>
#include <mma.h>

using namespace nvcuda;

// Problem shape (fixed)
#define BB   4
#define LL   4096
#define DD   1024
#define DFF_ 4096
#define MM   (BB*LL)        // 16384 token rows

// Scan chunking
#define NCH   32
#define CHUNK 128           // NCH*CHUNK == LL

// ---------------- scratch (device globals: allocation-free) ----------------
__device__ float g_xn [MM*DD];     // rmsnorm1(x)
__device__ float g_a  [MM*DD];     // sigmoid(forget)
__device__ float g_i  [MM*DD];     // tanh(input)
__device__ float g_g  [MM*DD];     // sigmoid(igate)
__device__ float g_o  [MM*DD];     // sigmoid(ogate)
__device__ float g_x1 [MM*DD];     // residual-1 output
__device__ float g_xn2[MM*DD];     // rmsnorm2(x1)
__device__ float g_fc [MM*DFF_];   // fc, then hff in-place
__device__ float g_P  [BB*NCH*DD];
__device__ float g_H  [BB*NCH*DD];
__device__ float g_I  [BB*NCH*DD];

// ---------------- RMSNorm: one block per row ----------------
__global__ void rmsnorm_kernel(const float* __restrict__ x, const float* __restrict__ w,
                               float* __restrict__ out)
{
    int row = blockIdx.x;
    int tid = threadIdx.x; // 256 threads, 4 floats each
    const float4* xv = reinterpret_cast<const float4*>(x + (size_t)row * DD);
    const float4* wv = reinterpret_cast<const float4*>(w);
    float4 v = xv[tid];
    float ss = v.x*v.x + v.y*v.y + v.z*v.z + v.w*v.w;
    #pragma unroll
    for (int o = 16; o > 0; o >>= 1) ss += __shfl_xor_sync(0xffffffffu, ss, o);
    __shared__ float red[8];
    __shared__ float s_scale;
    if ((tid & 31) == 0) red[tid >> 5] = ss;
    __syncthreads();
    if (tid == 0) {
        float t = 0.f;
        #pragma unroll
        for (int i = 0; i < 8; i++) t += red[i];
        s_scale = rsqrtf(t / (float)DD + 1e-6f);
    }
    __syncthreads();
    float s = s_scale;
    float4 w4 = wv[tid];
    float4 o4;
    o4.x = v.x * s * w4.x;
    o4.y = v.y * s * w4.y;
    o4.z = v.z * s * w4.z;
    o4.w = v.w * s * w4.w;
    reinterpret_cast<float4*>(out + (size_t)row * DD)[tid] = o4;
}

// ---------------- GEMM: C = epilogue(A @ B + bias), bf16x3 split ----------------
// A: [M,K] row-major fp32, B: [K,N] row-major fp32.
// ACT: 0=none, 1=sigmoid, 2=tanh, 3=aux*silu(v)  (SwiGLU combine), 4=v+aux (residual)
constexpr int BM = 128, BN = 128, BK = 32, NTHREADS = 256;
constexpr int LDA_S = BK + 16;   // 48  (96B rows, 32B aligned)
constexpr int LDB_S = BN + 16;   // 144 (288B rows, 32B aligned)
constexpr int LDC_S = BN + 8;    // 136 (544B rows, 32B aligned)
constexpr int SMEM_LOAD  = (2*BM*LDA_S + 2*BK*LDB_S) * 2; // 43008 B
constexpr int SMEM_STAGE = BM * LDC_S * 4;                // 69632 B
constexpr int SMEM_BYTES = (SMEM_STAGE > SMEM_LOAD) ? SMEM_STAGE : SMEM_LOAD;

__device__ __forceinline__ float sigmoidf_(float v) { return 1.f / (1.f + expf(-v)); }

template<int ACT>
__global__ void gemm_bf16x3(const float* __restrict__ A, const float* __restrict__ B,
                            const float* __restrict__ bias, const float* __restrict__ aux,
                            float* __restrict__ C, int M, int N, int K)
{
    extern __shared__ __align__(128) char smem[];
    __nv_bfloat16* sa_hi = (__nv_bfloat16*)smem;
    __nv_bfloat16* sa_lo = sa_hi + BM * LDA_S;
    __nv_bfloat16* sb_hi = sa_lo + BM * LDA_S;
    __nv_bfloat16* sb_lo = sb_hi + BK * LDB_S;

    const int tid = threadIdx.x;
    const int wid = tid >> 5;
    const int wm0 = (wid & 1) * 64;   // warp grid 2 (m) x 4 (n); warp tile 64x32
    const int wn0 = (wid >> 1) * 32;
    const int m0 = blockIdx.y * BM;
    const int n0 = blockIdx.x * BN;

    wmma::fragment<wmma::accumulator, 16, 16, 16, float> acc[4][2];
    #pragma unroll
    for (int i = 0; i < 4; i++)
        #pragma unroll
        for (int j = 0; j < 2; j++) wmma::fill_fragment(acc[i][j], 0.f);

    for (int k0 = 0; k0 < K; k0 += BK) {
        // A tile: BM x BK
        #pragma unroll
        for (int i = tid; i < BM * BK; i += NTHREADS) {
            int r = i >> 5, c = i & 31;
            float v = A[(size_t)(m0 + r) * K + (k0 + c)];
            __nv_bfloat16 h = __float2bfloat16(v);
            sa_hi[r * LDA_S + c] = h;
            sa_lo[r * LDA_S + c] = __float2bfloat16(v - __bfloat162float(h));
        }
        // B tile: BK x BN
        #pragma unroll
        for (int i = tid; i < BK * BN; i += NTHREADS) {
            int r = i >> 7, c = i & 127;
            float v = B[(size_t)(k0 + r) * N + (n0 + c)];
            __nv_bfloat16 h = __float2bfloat16(v);
            sb_hi[r * LDB_S + c] = h;
            sb_lo[r * LDB_S + c] = __float2bfloat16(v - __bfloat162float(h));
        }
        __syncthreads();
        #pragma unroll
        for (int kk = 0; kk < BK; kk += 16) {
            wmma::fragment<wmma::matrix_a, 16, 16, 16, __nv_bfloat16, wmma::row_major> ah[4], al[4];
            wmma::fragment<wmma::matrix_b, 16, 16, 16, __nv_bfloat16, wmma::row_major> bh[2], bl[2];
            #pragma unroll
            for (int i = 0; i < 4; i++) {
                wmma::load_matrix_sync(ah[i], sa_hi + (wm0 + i * 16) * LDA_S + kk, LDA_S);
                wmma::load_matrix_sync(al[i], sa_lo + (wm0 + i * 16) * LDA_S + kk, LDA_S);
            }
            #pragma unroll
            for (int j = 0; j < 2; j++) {
                wmma::load_matrix_sync(bh[j], sb_hi + kk * LDB_S + wn0 + j * 16, LDB_S);
                wmma::load_matrix_sync(bl[j], sb_lo + kk * LDB_S + wn0 + j * 16, LDB_S);
            }
            #pragma unroll
            for (int i = 0; i < 4; i++)
                #pragma unroll
                for (int j = 0; j < 2; j++) {
                    wmma::mma_sync(acc[i][j], al[i], bh[j], acc[i][j]);
                    wmma::mma_sync(acc[i][j], ah[i], bl[j], acc[i][j]);
                    wmma::mma_sync(acc[i][j], ah[i], bh[j], acc[i][j]);
                }
        }
        __syncthreads();
    }

    // epilogue via smem staging (per-element bias + activation, coalesced store)
    float* stage = (float*)smem;
    #pragma unroll
    for (int i = 0; i < 4; i++)
        #pragma unroll
        for (int j = 0; j < 2; j++)
            wmma::store_matrix_sync(stage + (wm0 + i * 16) * LDC_S + wn0 + j * 16,
                                    acc[i][j], LDC_S, wmma::mem_row_major);
    __syncthreads();
    for (int i = tid; i < BM * BN; i += NTHREADS) {
        int r = i >> 7, c = i & 127;
        float v = stage[r * LDC_S + c] + bias[n0 + c];
        size_t idx = (size_t)(m0 + r) * N + (n0 + c);
        if (ACT == 1)      v = sigmoidf_(v);
        else if (ACT == 2) v = tanhf(v);
        else if (ACT == 3) v = aux[idx] * (v * sigmoidf_(v));  // hff = fc * silu(fc_act)
        else if (ACT == 4) v += aux[idx];                      // + x1 residual
        C[idx] = v;
    }
}

// ---------------- chunked linear-recurrence scan ----------------
// h_t = a_t * h_{t-1} + b_t over L, h_{-1} = h0[d]; b_t = tanh(i)*sigmoid(g)
__global__ void scan_pass1(const float* __restrict__ aG, const float* __restrict__ iT,
                           const float* __restrict__ gS,
                           float* __restrict__ Pb, float* __restrict__ Hb)
{
    int g = blockIdx.x * blockDim.x + threadIdx.x;   // B*NCH*D threads
    int d = g & (DD - 1);
    int c = (g >> 10) & (NCH - 1);
    int b = g >> 15;
    size_t base = ((size_t)b * LL + (size_t)c * CHUNK) * DD + d;
    float P = 1.f, h = 0.f;
    #pragma unroll 4
    for (int t = 0; t < CHUNK; t++) {
        size_t idx = base + (size_t)t * DD;
        float a  = aG[idx];
        float bv = iT[idx] * gS[idx];
        P *= a;
        h = fmaf(a, h, bv);
    }
    Pb[g] = P;
    Hb[g] = h;
}

__global__ void scan_pass2(const float* __restrict__ Pb, const float* __restrict__ Hb,
                           const float* __restrict__ h0, float* __restrict__ Ib)
{
    int g = blockIdx.x * blockDim.x + threadIdx.x;   // B*D threads
    int d = g & (DD - 1);
    int b = g >> 10;
    float h = h0[d];
    #pragma unroll
    for (int c = 0; c < NCH; c++) {
        int j = (b * NCH + c) * DD + d;
        Ib[j] = h;
        h = fmaf(Pb[j], h, Hb[j]);
    }
}

__global__ void scan_pass3(const float* __restrict__ aG, const float* __restrict__ iT,
                           const float* __restrict__ gS, const float* __restrict__ oS,
                           const float* __restrict__ x,  const float* __restrict__ Ib,
                           float* __restrict__ x1)
{
    int g = blockIdx.x * blockDim.x + threadIdx.x;
    int d = g & (DD - 1);
    int c = (g >> 10) & (NCH - 1);
    int b = g >> 15;
    size_t base = ((size_t)b * LL + (size_t)c * CHUNK) * DD + d;
    float h = Ib[g];
    #pragma unroll 4
    for (int t = 0; t < CHUNK; t++) {
        size_t idx = base + (size_t)t * DD;
        float a  = aG[idx];
        float bv = iT[idx] * gS[idx];
        h = fmaf(a, h, bv);
        float y = tanhf(h) * oS[idx];     // oS already sigmoid()'d in GEMM epilogue
        x1[idx] = y + x[idx];
    }
}

// ---------------- launcher ----------------
extern "C" void kernel_launch(void* const* d_in, const int* in_sizes, int n_in,
                              void* d_out, int out_size)
{
    (void)in_sizes; (void)n_in; (void)out_size;
    const float* x   = (const float*)d_in[0];
    const float* wf  = (const float*)d_in[1];
    const float* bf_ = (const float*)d_in[2];
    const float* wi  = (const float*)d_in[3];
    const float* bi_ = (const float*)d_in[4];
    const float* wg  = (const float*)d_in[5];
    const float* bg_ = (const float*)d_in[6];
    const float* wo  = (const float*)d_in[7];
    const float* bo_ = (const float*)d_in[8];
    const float* h0  = (const float*)d_in[9];
    const float* n1w = (const float*)d_in[10];
    const float* n2w = (const float*)d_in[11];
    const float* wfc = (const float*)d_in[12];
    const float* bfc = (const float*)d_in[13];
    const float* wfa = (const float*)d_in[14];
    const float* bfa = (const float*)d_in[15];
    const float* wou = (const float*)d_in[16];
    const float* bou = (const float*)d_in[17];
    float* out = (float*)d_out;

    float *xn, *ga, *gi, *gg, *go, *x1, *xn2, *fc, *P, *H, *I;
    cudaGetSymbolAddress((void**)&xn,  g_xn);
    cudaGetSymbolAddress((void**)&ga,  g_a);
    cudaGetSymbolAddress((void**)&gi,  g_i);
    cudaGetSymbolAddress((void**)&gg,  g_g);
    cudaGetSymbolAddress((void**)&go,  g_o);
    cudaGetSymbolAddress((void**)&x1,  g_x1);
    cudaGetSymbolAddress((void**)&xn2, g_xn2);
    cudaGetSymbolAddress((void**)&fc,  g_fc);
    cudaGetSymbolAddress((void**)&P,   g_P);
    cudaGetSymbolAddress((void**)&H,   g_H);
    cudaGetSymbolAddress((void**)&I,   g_I);

    cudaFuncSetAttribute(gemm_bf16x3<0>, cudaFuncAttributeMaxDynamicSharedMemorySize, SMEM_BYTES);
    cudaFuncSetAttribute(gemm_bf16x3<1>, cudaFuncAttributeMaxDynamicSharedMemorySize, SMEM_BYTES);
    cudaFuncSetAttribute(gemm_bf16x3<2>, cudaFuncAttributeMaxDynamicSharedMemorySize, SMEM_BYTES);
    cudaFuncSetAttribute(gemm_bf16x3<3>, cudaFuncAttributeMaxDynamicSharedMemorySize, SMEM_BYTES);
    cudaFuncSetAttribute(gemm_bf16x3<4>, cudaFuncAttributeMaxDynamicSharedMemorySize, SMEM_BYTES);

    // 1) norm1
    rmsnorm_kernel<<<MM, 256>>>(x, n1w, xn);

    // 2) gate GEMMs with fused activations
    dim3 gD(DD / BN, MM / BM);
    gemm_bf16x3<1><<<gD, NTHREADS, SMEM_BYTES>>>(xn, wf, bf_, nullptr, ga, MM, DD, DD); // sigmoid
    gemm_bf16x3<2><<<gD, NTHREADS, SMEM_BYTES>>>(xn, wi, bi_, nullptr, gi, MM, DD, DD); // tanh
    gemm_bf16x3<1><<<gD, NTHREADS, SMEM_BYTES>>>(xn, wg, bg_, nullptr, gg, MM, DD, DD); // sigmoid
    gemm_bf16x3<1><<<gD, NTHREADS, SMEM_BYTES>>>(xn, wo, bo_, nullptr, go, MM, DD, DD); // sigmoid

    // 3) chunked scan + output gate + residual -> x1
    scan_pass1<<<(BB * NCH * DD) / 256, 256>>>(ga, gi, gg, P, H);
    scan_pass2<<<(BB * DD) / 256, 256>>>(P, H, h0, I);
    scan_pass3<<<(BB * NCH * DD) / 256, 256>>>(ga, gi, gg, go, x, I, x1);

    // 4) norm2
    rmsnorm_kernel<<<MM, 256>>>(x1, n2w, xn2);

    // 5) FFN: fc, then hff = fc * silu(fc_act) fused into second GEMM (in-place)
    dim3 gF(DFF_ / BN, MM / BM);
    gemm_bf16x3<0><<<gF, NTHREADS, SMEM_BYTES>>>(xn2, wfc, bfc, nullptr, fc, MM, DFF_, DD);
    gemm_bf16x3<3><<<gF, NTHREADS, SMEM_BYTES>>>(xn2, wfa, bfa, fc,      fc, MM, DFF_, DD);

    // 6) down-proj with fused +b_out +x1 straight to d_out
    dim3 gO(DD / BN, MM / BM);
    gemm_bf16x3<4><<<gO, NTHREADS, SMEM_BYTES>>>(fc, wou, bou, x1, out, MM, DD, DFF_);
}

// round 3
// speedup vs baseline: 7.0929x; 7.0929x over previous
#include <cuda_runtime.h>
#include <cuda_fp16.h>
#include <cstdint>

// Problem shape (fixed)
#define BB   4
#define LL   4096
#define DD   1024
#define DFF_ 4096
#define MM   (BB*LL)        // 16384 token rows
#define NCH  32
#define CHUNK 128

// ---------------- scratch (device globals: allocation-free) ----------------
__device__ float g_a  [MM*DD];
__device__ float g_i  [MM*DD];
__device__ float g_g  [MM*DD];
__device__ float g_o  [MM*DD];
__device__ float g_x1 [MM*DD];
__device__ float g_fc [MM*DFF_];
__device__ float g_P  [BB*NCH*DD];
__device__ float g_H  [BB*NCH*DD];
__device__ float g_I  [BB*NCH*DD];
__device__ float g_bgates[4*DD];

__device__ __half g_xn [MM*DD];
__device__ __half g_xn2[MM*DD];
__device__ __half g_hff[MM*DFF_];
__device__ __half g_wgates[4*DD*DD];   // [4096,1024] K-major (concat f,i,g,o)
__device__ __half g_wfct[DFF_*DD];     // [4096,1024]
__device__ __half g_wfat[DFF_*DD];     // [4096,1024]
__device__ __half g_wout[DD*DFF_];     // [1024,4096]

// ---------------- asm helpers ----------------
__device__ __forceinline__ uint32_t smem_to_u32(const void* p) {
    uint32_t a;
    asm("{ .reg .u64 t; cvta.to.shared.u64 t, %1; cvt.u32.u64 %0, t; }" : "=r"(a) : "l"(p));
    return a;
}
__device__ __forceinline__ void cp_async16(uint32_t sa, const void* gp) {
    asm volatile("cp.async.cg.shared.global [%0], [%1], 16;" :: "r"(sa), "l"(gp));
}
__device__ __forceinline__ void cp_commit() {
    asm volatile("cp.async.commit_group;" ::: "memory");
}
__device__ __forceinline__ void ldsm4(uint32_t* d, uint32_t addr) {
    asm volatile("ldmatrix.sync.aligned.m8n8.x4.shared.b16 {%0,%1,%2,%3}, [%4];"
        : "=r"(d[0]), "=r"(d[1]), "=r"(d[2]), "=r"(d[3]) : "r"(addr));
}
__device__ __forceinline__ void mma_f16(float* c, const uint32_t* a, const uint32_t* b) {
    asm volatile("mma.sync.aligned.m16n8k16.row.col.f32.f16.f16.f32 "
        "{%0,%1,%2,%3}, {%4,%5,%6,%7}, {%8,%9}, {%0,%1,%2,%3};"
        : "+f"(c[0]), "+f"(c[1]), "+f"(c[2]), "+f"(c[3])
        : "r"(a[0]), "r"(a[1]), "r"(a[2]), "r"(a[3]), "r"(b[0]), "r"(b[1]));
}
__device__ __forceinline__ float sigmoidf_(float v) { return 1.f / (1.f + expf(-v)); }

// swizzled 16B-chunk offset inside a [rows][32] fp16 tile (64B rows)
// conflict-free for ldmatrix 8-row phases AND bijective per row.
__device__ __forceinline__ uint32_t swz16(int row, int c) {
    return (uint32_t)((row * 4 + (c ^ (row & 3) ^ ((row >> 2) & 3))) << 4);
}

// ---------------- RMSNorm -> fp16 ----------------
__global__ void rmsnorm_h(const float* __restrict__ x, const float* __restrict__ w,
                          __half* __restrict__ o)
{
    int row = blockIdx.x;
    int tid = threadIdx.x; // 256 threads x 4 floats
    const float4* xv = reinterpret_cast<const float4*>(x + (size_t)row * DD);
    const float4* wv = reinterpret_cast<const float4*>(w);
    float4 v = xv[tid];
    float ss = v.x*v.x + v.y*v.y + v.z*v.z + v.w*v.w;
    #pragma unroll
    for (int of = 16; of > 0; of >>= 1) ss += __shfl_xor_sync(0xffffffffu, ss, of);
    __shared__ float red[8];
    __shared__ float s_scale;
    if ((tid & 31) == 0) red[tid >> 5] = ss;
    __syncthreads();
    if (tid == 0) {
        float t = 0.f;
        #pragma unroll
        for (int i = 0; i < 8; i++) t += red[i];
        s_scale = rsqrtf(t / (float)DD + 1e-6f);
    }
    __syncthreads();
    float s = s_scale;
    float4 w4 = wv[tid];
    __half2* ov = reinterpret_cast<__half2*>(o + (size_t)row * DD);
    ov[tid*2]   = __floats2half2_rn(v.x*s*w4.x, v.y*s*w4.y);
    ov[tid*2+1] = __floats2half2_rn(v.z*s*w4.z, v.w*s*w4.w);
}

// ---------------- weight transpose to [N,K] fp16 ----------------
__global__ void wt_h(const float* __restrict__ W, __half* __restrict__ T, int K, int N)
{
    __shared__ float t[32][33];
    int n0 = blockIdx.x * 32, k0 = blockIdx.y * 32;
    int tx = threadIdx.x, ty = threadIdx.y; // (32, 8)
    #pragma unroll
    for (int i = 0; i < 32; i += 8)
        t[ty + i][tx] = W[(size_t)(k0 + ty + i) * N + n0 + tx];
    __syncthreads();
    #pragma unroll
    for (int i = 0; i < 32; i += 8)
        T[(size_t)(n0 + ty + i) * K + k0 + tx] = __float2half_rn(t[tx][ty + i]);
}

// ---------------- pipelined HMMA GEMM ----------------
// C[M,N] = ACT(A @ B'^T + bias)   A: fp16 [M,K] row-major, B': fp16 [N,K] row-major
// ACT: 0 plain->C | 3 aux*silu(v)->Ch fp16 | 4 v+aux->C | 5 gates: per-1024-segment act -> C,C1,C2,C3
constexpr int BM = 128, BN = 256, BK = 32, STAGES = 5, NT = 256;
constexpr int ASTG = BM * BK * 2;       // 8 KB
constexpr int BSTG = BN * BK * 2;       // 16 KB
constexpr int STG  = ASTG + BSTG;       // 24 KB
constexpr int GSMEM = STAGES * STG;     // 120 KB

template<int ACT>
__global__ __launch_bounds__(NT, 1) void tc_gemm(
    const __half* __restrict__ A, const __half* __restrict__ Bw,
    const float* __restrict__ bias, const float* __restrict__ aux,
    float* __restrict__ C, __half* __restrict__ Ch,
    float* __restrict__ C1, float* __restrict__ C2, float* __restrict__ C3,
    int M, int N, int K)
{
    extern __shared__ __align__(128) char smem[];
    uint32_t su = smem_to_u32(smem);
    int tid = threadIdx.x, wid = tid >> 5, lane = tid & 31;

    // supertile raster (GM=8 along m) for L2 reuse
    int tn = N / BN;
    int per = 8 * tn, grp = blockIdx.x / per, rr = blockIdx.x % per;
    int m0 = (grp * 8 + (rr % 8)) * BM;
    int n0 = (rr / 8) * BN;

    const __half* Ab = A  + (size_t)m0 * K;
    const __half* Bb = Bw + (size_t)n0 * K;

    // precomputed cp.async offsets (per thread)
    uint32_t sAo[2], sBo[4];
    size_t   gAo[2], gBo[4];
    #pragma unroll
    for (int j = 0; j < 2; j++) {
        int idx = tid + j * NT, r = idx >> 2, c = idx & 3;
        sAo[j] = swz16(r, c); gAo[j] = (size_t)r * K + c * 8;
    }
    #pragma unroll
    for (int j = 0; j < 4; j++) {
        int idx = tid + j * NT, r = idx >> 2, c = idx & 3;
        sBo[j] = swz16(r, c); gBo[j] = (size_t)r * K + c * 8;
    }

    // precomputed ldmatrix offsets (per thread)
    int wm = (wid & 1) * 64, wn = (wid >> 1) * 64;
    uint32_t offA[2][4], offB[2][4];
    #pragma unroll
    for (int kk = 0; kk < 2; kk++) {
        #pragma unroll
        for (int i = 0; i < 4; i++) {
            offA[kk][i] = swz16(wm + i*16 + (lane & 15), kk*2 + (lane >> 4));
            offB[kk][i] = swz16(wn + i*16 + (lane & 7) + ((lane >> 4) << 3),
                                kk*2 + ((lane >> 3) & 1));
        }
    }

    float acc[4][8][4];
    #pragma unroll
    for (int i = 0; i < 4; i++)
        #pragma unroll
        for (int j = 0; j < 8; j++)
            #pragma unroll
            for (int q = 0; q < 4; q++) acc[i][j][q] = 0.f;

    const int NK = K / BK;

    // prologue: fill STAGES-1 stages
    #pragma unroll
    for (int s = 0; s < STAGES - 1; s++) {
        uint32_t sA = su + s * STG, sB = sA + ASTG;
        int k0 = s * BK;
        #pragma unroll
        for (int j = 0; j < 2; j++) cp_async16(sA + sAo[j], Ab + gAo[j] + k0);
        #pragma unroll
        for (int j = 0; j < 4; j++) cp_async16(sB + sBo[j], Bb + gBo[j] + k0);
        cp_commit();
    }

    int cs = 0, ls = STAGES - 1;
    for (int kt = 0; kt < NK; kt++) {
        asm volatile("cp.async.wait_group %0;" :: "n"(STAGES - 2) : "memory");
        __syncthreads();

        // issue loads for tile kt+STAGES-1 into the stage computed last iter
        int lt = kt + STAGES - 1;
        if (lt < NK) {
            uint32_t sA = su + ls * STG, sB = sA + ASTG;
            int k0 = lt * BK;
            #pragma unroll
            for (int j = 0; j < 2; j++) cp_async16(sA + sAo[j], Ab + gAo[j] + k0);
            #pragma unroll
            for (int j = 0; j < 4; j++) cp_async16(sB + sBo[j], Bb + gBo[j] + k0);
        }
        cp_commit();
        if (++ls == STAGES) ls = 0;

        // compute current stage
        uint32_t sA = su + cs * STG, sB = sA + ASTG;
        if (++cs == STAGES) cs = 0;
        #pragma unroll
        for (int kk = 0; kk < 2; kk++) {
            uint32_t a[4][4];
            #pragma unroll
            for (int i = 0; i < 4; i++) ldsm4(a[i], sA + offA[kk][i]);
            #pragma unroll
            for (int p = 0; p < 4; p++) {
                uint32_t b[4];
                ldsm4(b, sB + offB[kk][p]);
                #pragma unroll
                for (int i = 0; i < 4; i++) {
                    mma_f16(acc[i][2*p],     a[i], b);
                    mma_f16(acc[i][2*p + 1], a[i], b + 2);
                }
            }
        }
    }

    // ---- epilogue: registers -> global, fused bias + activation ----
    #pragma unroll
    for (int i = 0; i < 4; i++) {
        int r0 = m0 + wm + i * 16 + (lane >> 2);
        #pragma unroll
        for (int j = 0; j < 8; j++) {
            int c0 = n0 + wn + j * 8 + (lane & 3) * 2;
            float b0 = bias[c0], b1 = bias[c0 + 1];
            #pragma unroll
            for (int h = 0; h < 2; h++) {
                int r = r0 + h * 8;
                float v0 = acc[i][j][2*h]     + b0;
                float v1 = acc[i][j][2*h + 1] + b1;
                size_t idx = (size_t)r * N + c0;
                if (ACT == 0) {
                    *reinterpret_cast<float2*>(&C[idx]) = make_float2(v0, v1);
                } else if (ACT == 3) {
                    float2 au = *reinterpret_cast<const float2*>(&aux[idx]);
                    v0 = au.x * (v0 * sigmoidf_(v0));
                    v1 = au.y * (v1 * sigmoidf_(v1));
                    *reinterpret_cast<__half2*>(&Ch[idx]) = __floats2half2_rn(v0, v1);
                } else if (ACT == 4) {
                    float2 au = *reinterpret_cast<const float2*>(&aux[idx]);
                    *reinterpret_cast<float2*>(&C[idx]) = make_float2(v0 + au.x, v1 + au.y);
                } else if (ACT == 5) {
                    int seg = c0 >> 10;          // which gate (tile fully inside a segment)
                    int nl  = c0 & 1023;
                    float* dst = (seg == 0) ? C : (seg == 1) ? C1 : (seg == 2) ? C2 : C3;
                    if (seg == 1) { v0 = tanhf(v0);      v1 = tanhf(v1); }
                    else          { v0 = sigmoidf_(v0);  v1 = sigmoidf_(v1); }
                    *reinterpret_cast<float2*>(&dst[(size_t)r * DD + nl]) = make_float2(v0, v1);
                }
            }
        }
    }
}

// ---------------- chunked linear-recurrence scan ----------------
__global__ void scan_pass1(const float* __restrict__ aG, const float* __restrict__ iT,
                           const float* __restrict__ gS,
                           float* __restrict__ Pb, float* __restrict__ Hb)
{
    int g = blockIdx.x * blockDim.x + threadIdx.x;
    int d = g & (DD - 1);
    int c = (g >> 10) & (NCH - 1);
    int b = g >> 15;
    size_t base = ((size_t)b * LL + (size_t)c * CHUNK) * DD + d;
    float P = 1.f, h = 0.f;
    #pragma unroll 4
    for (int t = 0; t < CHUNK; t++) {
        size_t idx = base + (size_t)t * DD;
        float a  = aG[idx];
        float bv = iT[idx] * gS[idx];
        P *= a;
        h = fmaf(a, h, bv);
    }
    Pb[g] = P;
    Hb[g] = h;
}

__global__ void scan_pass2(const float* __restrict__ Pb, const float* __restrict__ Hb,
                           const float* __restrict__ h0, float* __restrict__ Ib)
{
    int g = blockIdx.x * blockDim.x + threadIdx.x;
    int d = g & (DD - 1);
    int b = g >> 10;
    float h = h0[d];
    #pragma unroll
    for (int c = 0; c < NCH; c++) {
        int j = (b * NCH + c) * DD + d;
        Ib[j] = h;
        h = fmaf(Pb[j], h, Hb[j]);
    }
}

__global__ void scan_pass3(const float* __restrict__ aG, const float* __restrict__ iT,
                           const float* __restrict__ gS, const float* __restrict__ oS,
                           const float* __restrict__ x,  const float* __restrict__ Ib,
                           float* __restrict__ x1)
{
    int g = blockIdx.x * blockDim.x + threadIdx.x;
    int d = g & (DD - 1);
    int c = (g >> 10) & (NCH - 1);
    int b = g >> 15;
    size_t base = ((size_t)b * LL + (size_t)c * CHUNK) * DD + d;
    float h = Ib[g];
    #pragma unroll 4
    for (int t = 0; t < CHUNK; t++) {
        size_t idx = base + (size_t)t * DD;
        float a  = aG[idx];
        float bv = iT[idx] * gS[idx];
        h = fmaf(a, h, bv);
        float y = tanhf(h) * oS[idx];
        x1[idx] = y + x[idx];
    }
}

// ---------------- launcher ----------------
extern "C" void kernel_launch(void* const* d_in, const int* in_sizes, int n_in,
                              void* d_out, int out_size)
{
    (void)in_sizes; (void)n_in; (void)out_size;
    const float* x   = (const float*)d_in[0];
    const float* wf  = (const float*)d_in[1];
    const float* bf_ = (const float*)d_in[2];
    const float* wi  = (const float*)d_in[3];
    const float* bi_ = (const float*)d_in[4];
    const float* wg  = (const float*)d_in[5];
    const float* bg_ = (const float*)d_in[6];
    const float* wo  = (const float*)d_in[7];
    const float* bo_ = (const float*)d_in[8];
    const float* h0  = (const float*)d_in[9];
    const float* n1w = (const float*)d_in[10];
    const float* n2w = (const float*)d_in[11];
    const float* wfc = (const float*)d_in[12];
    const float* bfc = (const float*)d_in[13];
    const float* wfa = (const float*)d_in[14];
    const float* bfa = (const float*)d_in[15];
    const float* wou = (const float*)d_in[16];
    const float* bou = (const float*)d_in[17];
    float* out = (float*)d_out;

    float *ga, *gi, *gg, *go, *x1, *fc, *P, *H, *I, *bg4;
    cudaGetSymbolAddress((void**)&ga,  g_a);
    cudaGetSymbolAddress((void**)&gi,  g_i);
    cudaGetSymbolAddress((void**)&gg,  g_g);
    cudaGetSymbolAddress((void**)&go,  g_o);
    cudaGetSymbolAddress((void**)&x1,  g_x1);
    cudaGetSymbolAddress((void**)&fc,  g_fc);
    cudaGetSymbolAddress((void**)&P,   g_P);
    cudaGetSymbolAddress((void**)&H,   g_H);
    cudaGetSymbolAddress((void**)&I,   g_I);
    cudaGetSymbolAddress((void**)&bg4, g_bgates);

    __half *xn, *xn2, *hff, *wgt, *wfct, *wfat, *wout_;
    cudaGetSymbolAddress((void**)&xn,   g_xn);
    cudaGetSymbolAddress((void**)&xn2,  g_xn2);
    cudaGetSymbolAddress((void**)&hff,  g_hff);
    cudaGetSymbolAddress((void**)&wgt,  g_wgates);
    cudaGetSymbolAddress((void**)&wfct, g_wfct);
    cudaGetSymbolAddress((void**)&wfat, g_wfat);
    cudaGetSymbolAddress((void**)&wout_,g_wout);

    cudaFuncSetAttribute(tc_gemm<0>, cudaFuncAttributeMaxDynamicSharedMemorySize, GSMEM);
    cudaFuncSetAttribute(tc_gemm<3>, cudaFuncAttributeMaxDynamicSharedMemorySize, GSMEM);
    cudaFuncSetAttribute(tc_gemm<4>, cudaFuncAttributeMaxDynamicSharedMemorySize, GSMEM);
    cudaFuncSetAttribute(tc_gemm<5>, cudaFuncAttributeMaxDynamicSharedMemorySize, GSMEM);

    // 0) weights: transpose + fp16; concat gate weights/biases
    dim3 tb(32, 8);
    wt_h<<<dim3(DD/32,   DD/32),   tb>>>(wf,  wgt + 0*DD*DD, DD,   DD);
    wt_h<<<dim3(DD/32,   DD/32),   tb>>>(wi,  wgt + 1*DD*DD, DD,   DD);
    wt_h<<<dim3(DD/32,   DD/32),   tb>>>(wg,  wgt + 2*DD*DD, DD,   DD);
    wt_h<<<dim3(DD/32,   DD/32),   tb>>>(wo,  wgt + 3*DD*DD, DD,   DD);
    wt_h<<<dim3(DFF_/32, DD/32),   tb>>>(wfc, wfct,  DD,   DFF_);
    wt_h<<<dim3(DFF_/32, DD/32),   tb>>>(wfa, wfat,  DD,   DFF_);
    wt_h<<<dim3(DD/32,   DFF_/32), tb>>>(wou, wout_, DFF_, DD);
    cudaMemcpyAsync(bg4 + 0*DD, bf_, DD*sizeof(float), cudaMemcpyDeviceToDevice);
    cudaMemcpyAsync(bg4 + 1*DD, bi_, DD*sizeof(float), cudaMemcpyDeviceToDevice);
    cudaMemcpyAsync(bg4 + 2*DD, bg_, DD*sizeof(float), cudaMemcpyDeviceToDevice);
    cudaMemcpyAsync(bg4 + 3*DD, bo_, DD*sizeof(float), cudaMemcpyDeviceToDevice);

    // 1) norm1 -> fp16
    rmsnorm_h<<<MM, 256>>>(x, n1w, xn);

    // 2) all four gate GEMMs as one N=4096 GEMM with per-segment activation
    int gGates = (MM/BM) * ((4*DD)/BN);   // 128 * 16
    tc_gemm<5><<<gGates, NT, GSMEM>>>(xn, wgt, bg4, nullptr,
                                      ga, nullptr, gi, gg, go, MM, 4*DD, DD);

    // 3) chunked scan + output gate + residual -> x1
    scan_pass1<<<(BB*NCH*DD)/256, 256>>>(ga, gi, gg, P, H);
    scan_pass2<<<(BB*DD)/256, 256>>>(P, H, h0, I);
    scan_pass3<<<(BB*NCH*DD)/256, 256>>>(ga, gi, gg, go, x, I, x1);

    // 4) norm2 -> fp16
    rmsnorm_h<<<MM, 256>>>(x1, n2w, xn2);

    // 5) FFN: fc (fp32), then hff = fc * silu(fc_act) -> fp16 (A operand of down-proj)
    int gFF = (MM/BM) * (DFF_/BN);        // 128 * 16
    tc_gemm<0><<<gFF, NT, GSMEM>>>(xn2, wfct, bfc, nullptr, fc, nullptr,
                                   nullptr, nullptr, nullptr, MM, DFF_, DD);
    tc_gemm<3><<<gFF, NT, GSMEM>>>(xn2, wfat, bfa, fc, nullptr, hff,
                                   nullptr, nullptr, nullptr, MM, DFF_, DD);

    // 6) down-proj with fused +b_out +x1 straight to d_out
    int gOut = (MM/BM) * (DD/BN);         // 128 * 4
    tc_gemm<4><<<gOut, NT, GSMEM>>>(hff, wout_, bou, x1, out, nullptr,
                                    nullptr, nullptr, nullptr, MM, DD, DFF_);
}

// round 4
// speedup vs baseline: 7.6158x; 1.0737x over previous
#include <cuda_runtime.h>
#include <cuda_fp16.h>
#include <cstdint>

// Problem shape (fixed)
#define BB   4
#define LL   4096
#define DD   1024
#define DFF_ 4096
#define MM   (BB*LL)        // 16384 token rows
#define NCH  32
#define CHUNK 128

// ---------------- scratch (device globals: allocation-free) ----------------
__device__ float g_a  [MM*DD];      // sigmoid(forget)
__device__ float g_bv [MM*DD];      // tanh(input)*sigmoid(igate)
__device__ float g_o  [MM*DD];      // sigmoid(ogate)
__device__ float g_x1 [MM*DD];
__device__ float g_P  [BB*NCH*DD];
__device__ float g_H  [BB*NCH*DD];
__device__ float g_I  [BB*NCH*DD];
__device__ float g_bg [4*DD];       // gate bias, layout [f | i,g interleaved | o]
__device__ float g_bff[2*DFF_];     // ffn bias, interleaved [bfc_j, bfa_j]

__device__ __half g_xn [MM*DD];
__device__ __half g_xn2[MM*DD];
__device__ __half g_hff[MM*DFF_];
__device__ __half g_wgt[4*DD*DD];   // [4096,1024] K-major, rows [f | i,g ilv | o]
__device__ __half g_wff[2*DFF_*DD]; // [8192,1024] K-major, rows interleaved (fc,fca)
__device__ __half g_wout[DD*DFF_];  // [1024,4096] K-major

// ---------------- asm helpers ----------------
__device__ __forceinline__ uint32_t smem_to_u32(const void* p) {
    uint32_t a;
    asm("{ .reg .u64 t; cvta.to.shared.u64 t, %1; cvt.u32.u64 %0, t; }" : "=r"(a) : "l"(p));
    return a;
}
__device__ __forceinline__ void cp_async16(uint32_t sa, const void* gp) {
    asm volatile("cp.async.cg.shared.global [%0], [%1], 16;" :: "r"(sa), "l"(gp));
}
__device__ __forceinline__ void cp_commit() {
    asm volatile("cp.async.commit_group;" ::: "memory");
}
__device__ __forceinline__ void ldsm4(uint32_t* d, uint32_t addr) {
    asm volatile("ldmatrix.sync.aligned.m8n8.x4.shared.b16 {%0,%1,%2,%3}, [%4];"
        : "=r"(d[0]), "=r"(d[1]), "=r"(d[2]), "=r"(d[3]) : "r"(addr));
}
__device__ __forceinline__ void mma_f16(float* c, const uint32_t* a, const uint32_t* b) {
    asm volatile("mma.sync.aligned.m16n8k16.row.col.f32.f16.f16.f32 "
        "{%0,%1,%2,%3}, {%4,%5,%6,%7}, {%8,%9}, {%0,%1,%2,%3};"
        : "+f"(c[0]), "+f"(c[1]), "+f"(c[2]), "+f"(c[3])
        : "r"(a[0]), "r"(a[1]), "r"(a[2]), "r"(a[3]), "r"(b[0]), "r"(b[1]));
}
__device__ __forceinline__ float sigmoidf_(float v) { return 1.f / (1.f + expf(-v)); }

// SW128-style swizzle for [rows][64 fp16] tiles (128B rows, 8 x 16B chunks)
__device__ __forceinline__ uint32_t swz(int row, int c) {
    return (uint32_t)(row * 128 + (((c) ^ (row & 7)) << 4));
}

// ---------------- RMSNorm -> fp16 ----------------
__global__ void rmsnorm_h(const float* __restrict__ x, const float* __restrict__ w,
                          __half* __restrict__ o)
{
    int row = blockIdx.x;
    int tid = threadIdx.x; // 256 threads x 4 floats
    const float4* xv = reinterpret_cast<const float4*>(x + (size_t)row * DD);
    const float4* wv = reinterpret_cast<const float4*>(w);
    float4 v = xv[tid];
    float ss = v.x*v.x + v.y*v.y + v.z*v.z + v.w*v.w;
    #pragma unroll
    for (int of = 16; of > 0; of >>= 1) ss += __shfl_xor_sync(0xffffffffu, ss, of);
    __shared__ float red[8];
    __shared__ float s_scale;
    if ((tid & 31) == 0) red[tid >> 5] = ss;
    __syncthreads();
    if (tid == 0) {
        float t = 0.f;
        #pragma unroll
        for (int i = 0; i < 8; i++) t += red[i];
        s_scale = rsqrtf(t / (float)DD + 1e-6f);
    }
    __syncthreads();
    float s = s_scale;
    float4 w4 = wv[tid];
    __half2* ov = reinterpret_cast<__half2*>(o + (size_t)row * DD);
    ov[tid*2]   = __floats2half2_rn(v.x*s*w4.x, v.y*s*w4.y);
    ov[tid*2+1] = __floats2half2_rn(v.z*s*w4.z, v.w*s*w4.w);
}

// ---------------- weight packing ----------------
// plain transpose: W[K,N] fp32 -> T[N,K] fp16
__global__ void wt_h(const float* __restrict__ W, __half* __restrict__ T, int K, int N)
{
    __shared__ float t[32][33];
    int n0 = blockIdx.x * 32, k0 = blockIdx.y * 32;
    int tx = threadIdx.x, ty = threadIdx.y; // (32,8)
    #pragma unroll
    for (int i = 0; i < 32; i += 8)
        t[ty + i][tx] = W[(size_t)(k0 + ty + i) * N + n0 + tx];
    __syncthreads();
    #pragma unroll
    for (int i = 0; i < 32; i += 8)
        T[(size_t)(n0 + ty + i) * K + k0 + tx] = __float2half_rn(t[tx][ty + i]);
}
// interleaved transpose: out row 2j from S0 col j, row 2j+1 from S1 col j
__global__ void wt_pair(const float* __restrict__ S0, const float* __restrict__ S1,
                        __half* __restrict__ T, int K, int Nsrc)
{
    __shared__ float t[32][33];
    int n0 = blockIdx.x * 32, k0 = blockIdx.y * 32;
    int tx = threadIdx.x, ty = threadIdx.y;
    const float* S = ((n0 + tx) & 1) ? S1 : S0;
    int col = (n0 + tx) >> 1;
    #pragma unroll
    for (int i = 0; i < 32; i += 8)
        t[ty + i][tx] = S[(size_t)(k0 + ty + i) * Nsrc + col];
    __syncthreads();
    #pragma unroll
    for (int i = 0; i < 32; i += 8)
        T[(size_t)(n0 + ty + i) * K + k0 + tx] = __float2half_rn(t[tx][ty + i]);
}
__global__ void pack_bias(const float* __restrict__ bf, const float* __restrict__ bi,
                          const float* __restrict__ bg, const float* __restrict__ bo,
                          const float* __restrict__ bfc, const float* __restrict__ bfa,
                          float* __restrict__ BG, float* __restrict__ BFF)
{
    int n = blockIdx.x * blockDim.x + threadIdx.x;
    if (n < 4 * DD) {
        float v;
        if (n < DD)            v = bf[n];
        else if (n < 3 * DD) { int t = n - DD; v = (t & 1) ? bg[t >> 1] : bi[t >> 1]; }
        else                   v = bo[n - 3 * DD];
        BG[n] = v;
    }
    if (n < 2 * DFF_)
        BFF[n] = (n & 1) ? bfa[n >> 1] : bfc[n >> 1];
}

// ---------------- pipelined HMMA GEMM, BK=64, 4 stages ----------------
// C[M,N] = ACT(A @ B'^T + bias)  A fp16 [M,K] row-major, B' fp16 [N,K] row-major
// ACT 4: v+aux -> C (down-proj)
// ACT 5: gates, N=4096 layout [f | i,g ilv | o]: -> C(a), C1(bv), C2(o)
// ACT 6: fused FFN-up, N=8192 ilv (fc,fca): hff=fc*silu(fca) -> Ch fp16
constexpr int BM = 128, BN = 256, BK = 64, STAGES = 4, NT = 256;
constexpr int ASTG = BM * BK * 2;     // 16 KB
constexpr int BSTG = BN * BK * 2;     // 32 KB
constexpr int STG  = ASTG + BSTG;     // 48 KB
constexpr int GSMEM = STAGES * STG;   // 192 KB

template<int ACT>
__global__ __launch_bounds__(NT, 1) void tc_gemm(
    const __half* __restrict__ A, const __half* __restrict__ Bw,
    const float* __restrict__ bias, const float* __restrict__ aux,
    float* __restrict__ C, __half* __restrict__ Ch,
    float* __restrict__ C1, float* __restrict__ C2,
    int M, int N, int K)
{
    extern __shared__ __align__(128) char smem[];
    uint32_t su = smem_to_u32(smem);
    int tid = threadIdx.x, wid = tid >> 5, lane = tid & 31;

    // supertile raster (8 m-tiles per group) for L2 reuse
    int tn = N / BN;
    int per = 8 * tn, grp = blockIdx.x / per, rr = blockIdx.x % per;
    int m0 = (grp * 8 + (rr % 8)) * BM;
    int n0 = (rr / 8) * BN;

    const __half* Ab = A  + (size_t)m0 * K;
    const __half* Bb = Bw + (size_t)n0 * K;

    // cp.async offsets
    uint32_t sAo[4], gAo[4], sBo[8], gBo[8];
    #pragma unroll
    for (int j = 0; j < 4; j++) {
        int idx = tid + j * NT, r = idx >> 3, c = idx & 7;
        sAo[j] = swz(r, c); gAo[j] = (uint32_t)(r * K + c * 8);
    }
    #pragma unroll
    for (int j = 0; j < 8; j++) {
        int idx = tid + j * NT, r = idx >> 3, c = idx & 7;
        sBo[j] = swz(r, c); gBo[j] = (uint32_t)(r * K + c * 8);
    }

    // ldmatrix address components
    int wm = (wid & 1) * 64, wn = (wid >> 1) * 64;
    int rA128[4], rA7[4], rB128[4], rB7[4];
    int cA = lane >> 4;                                  // 0..1
    int cB = (lane >> 3) & 1;                            // 0..1
    #pragma unroll
    for (int i = 0; i < 4; i++) {
        int ra = wm + i * 16 + (lane & 15);
        rA128[i] = ra * 128; rA7[i] = ra & 7;
        int rb = wn + i * 16 + (lane & 7) + ((lane >> 4) << 3);
        rB128[i] = rb * 128; rB7[i] = rb & 7;
    }

    float acc[4][8][4];
    #pragma unroll
    for (int i = 0; i < 4; i++)
        #pragma unroll
        for (int j = 0; j < 8; j++)
            #pragma unroll
            for (int q = 0; q < 4; q++) acc[i][j][q] = 0.f;

    const int NK = K / BK;

    #pragma unroll
    for (int s = 0; s < STAGES - 1; s++) {
        uint32_t sA = su + s * STG, sB = sA + ASTG;
        int k0 = s * BK;
        #pragma unroll
        for (int j = 0; j < 4; j++) cp_async16(sA + sAo[j], Ab + gAo[j] + k0);
        #pragma unroll
        for (int j = 0; j < 8; j++) cp_async16(sB + sBo[j], Bb + gBo[j] + k0);
        cp_commit();
    }

    int cs = 0, ls = STAGES - 1;
    for (int kt = 0; kt < NK; kt++) {
        asm volatile("cp.async.wait_group %0;" :: "n"(STAGES - 2) : "memory");
        __syncthreads();

        int lt = kt + STAGES - 1;
        if (lt < NK) {
            uint32_t sA = su + ls * STG, sB = sA + ASTG;
            int k0 = lt * BK;
            #pragma unroll
            for (int j = 0; j < 4; j++) cp_async16(sA + sAo[j], Ab + gAo[j] + k0);
            #pragma unroll
            for (int j = 0; j < 8; j++) cp_async16(sB + sBo[j], Bb + gBo[j] + k0);
        }
        cp_commit();
        if (++ls == STAGES) ls = 0;

        uint32_t sA = su + cs * STG, sB = sA + ASTG;
        if (++cs == STAGES) cs = 0;
        #pragma unroll
        for (int kk = 0; kk < 4; kk++) {
            uint32_t a[4][4], b[4][4];
            #pragma unroll
            for (int i = 0; i < 4; i++)
                ldsm4(a[i], sA + rA128[i] + (((kk * 2 + cA) ^ rA7[i]) << 4));
            #pragma unroll
            for (int p = 0; p < 4; p++)
                ldsm4(b[p], sB + rB128[p] + (((kk * 2 + cB) ^ rB7[p]) << 4));
            #pragma unroll
            for (int p = 0; p < 4; p++)
                #pragma unroll
                for (int i = 0; i < 4; i++) {
                    mma_f16(acc[i][2*p],     a[i], b[p]);
                    mma_f16(acc[i][2*p + 1], a[i], b[p] + 2);
                }
        }
    }

    // ---- fused epilogue ----
    #pragma unroll
    for (int i = 0; i < 4; i++) {
        int r0 = m0 + wm + i * 16 + (lane >> 2);
        #pragma unroll
        for (int j = 0; j < 8; j++) {
            int c0 = n0 + wn + j * 8 + (lane & 3) * 2;
            float b0 = bias[c0], b1 = bias[c0 + 1];
            #pragma unroll
            for (int h = 0; h < 2; h++) {
                int r = r0 + h * 8;
                float v0 = acc[i][j][2*h]     + b0;
                float v1 = acc[i][j][2*h + 1] + b1;
                if (ACT == 4) {
                    size_t idx = (size_t)r * N + c0;
                    float2 au = *reinterpret_cast<const float2*>(&aux[idx]);
                    *reinterpret_cast<float2*>(&C[idx]) = make_float2(v0 + au.x, v1 + au.y);
                } else if (ACT == 5) {
                    if (c0 < 1024) {
                        *reinterpret_cast<float2*>(&C[(size_t)r * DD + c0]) =
                            make_float2(sigmoidf_(v0), sigmoidf_(v1));
                    } else if (c0 < 3072) {
                        C1[(size_t)r * DD + ((c0 - 1024) >> 1)] = tanhf(v0) * sigmoidf_(v1);
                    } else {
                        *reinterpret_cast<float2*>(&C2[(size_t)r * DD + (c0 - 3072)]) =
                            make_float2(sigmoidf_(v0), sigmoidf_(v1));
                    }
                } else if (ACT == 6) {
                    Ch[(size_t)r * DFF_ + (c0 >> 1)] =
                        __float2half_rn(v0 * (v1 * sigmoidf_(v1)));
                }
            }
        }
    }
}

// ---------------- chunked linear-recurrence scan ----------------
__global__ void scan_pass1(const float* __restrict__ aG, const float* __restrict__ bV,
                           float* __restrict__ Pb, float* __restrict__ Hb)
{
    int g = blockIdx.x * blockDim.x + threadIdx.x;
    int d = g & (DD - 1);
    int c = (g >> 10) & (NCH - 1);
    int b = g >> 15;
    size_t base = ((size_t)b * LL + (size_t)c * CHUNK) * DD + d;
    float P = 1.f, h = 0.f;
    #pragma unroll 4
    for (int t = 0; t < CHUNK; t++) {
        size_t idx = base + (size_t)t * DD;
        float a = aG[idx];
        P *= a;
        h = fmaf(a, h, bV[idx]);
    }
    Pb[g] = P;
    Hb[g] = h;
}

__global__ void scan_pass2(const float* __restrict__ Pb, const float* __restrict__ Hb,
                           const float* __restrict__ h0, float* __restrict__ Ib)
{
    int g = blockIdx.x * blockDim.x + threadIdx.x;
    int d = g & (DD - 1);
    int b = g >> 10;
    float h = h0[d];
    #pragma unroll
    for (int c = 0; c < NCH; c++) {
        int j = (b * NCH + c) * DD + d;
        Ib[j] = h;
        h = fmaf(Pb[j], h, Hb[j]);
    }
}

__global__ void scan_pass3(const float* __restrict__ aG, const float* __restrict__ bV,
                           const float* __restrict__ oS, const float* __restrict__ x,
                           const float* __restrict__ Ib, float* __restrict__ x1)
{
    int g = blockIdx.x * blockDim.x + threadIdx.x;
    int d = g & (DD - 1);
    int c = (g >> 10) & (NCH - 1);
    int b = g >> 15;
    size_t base = ((size_t)b * LL + (size_t)c * CHUNK) * DD + d;
    float h = Ib[g];
    #pragma unroll 4
    for (int t = 0; t < CHUNK; t++) {
        size_t idx = base + (size_t)t * DD;
        h = fmaf(aG[idx], h, bV[idx]);
        x1[idx] = tanhf(h) * oS[idx] + x[idx];
    }
}

// ---------------- launcher ----------------
extern "C" void kernel_launch(void* const* d_in, const int* in_sizes, int n_in,
                              void* d_out, int out_size)
{
    (void)in_sizes; (void)n_in; (void)out_size;
    const float* x   = (const float*)d_in[0];
    const float* wf  = (const float*)d_in[1];
    const float* bf_ = (const float*)d_in[2];
    const float* wi  = (const float*)d_in[3];
    const float* bi_ = (const float*)d_in[4];
    const float* wg  = (const float*)d_in[5];
    const float* bg_ = (const float*)d_in[6];
    const float* wo  = (const float*)d_in[7];
    const float* bo_ = (const float*)d_in[8];
    const float* h0  = (const float*)d_in[9];
    const float* n1w = (const float*)d_in[10];
    const float* n2w = (const float*)d_in[11];
    const float* wfc = (const float*)d_in[12];
    const float* bfc = (const float*)d_in[13];
    const float* wfa = (const float*)d_in[14];
    const float* bfa = (const float*)d_in[15];
    const float* wou = (const float*)d_in[16];
    const float* bou = (const float*)d_in[17];
    float* out = (float*)d_out;

    float *ga, *gbv, *go, *x1, *P, *H, *I, *bg4, *bff;
    cudaGetSymbolAddress((void**)&ga,  g_a);
    cudaGetSymbolAddress((void**)&gbv, g_bv);
    cudaGetSymbolAddress((void**)&go,  g_o);
    cudaGetSymbolAddress((void**)&x1,  g_x1);
    cudaGetSymbolAddress((void**)&P,   g_P);
    cudaGetSymbolAddress((void**)&H,   g_H);
    cudaGetSymbolAddress((void**)&I,   g_I);
    cudaGetSymbolAddress((void**)&bg4, g_bg);
    cudaGetSymbolAddress((void**)&bff, g_bff);

    __half *xn, *xn2, *hff, *wgt, *wff, *wout_;
    cudaGetSymbolAddress((void**)&xn,   g_xn);
    cudaGetSymbolAddress((void**)&xn2,  g_xn2);
    cudaGetSymbolAddress((void**)&hff,  g_hff);
    cudaGetSymbolAddress((void**)&wgt,  g_wgt);
    cudaGetSymbolAddress((void**)&wff,  g_wff);
    cudaGetSymbolAddress((void**)&wout_,g_wout);

    cudaFuncSetAttribute(tc_gemm<4>, cudaFuncAttributeMaxDynamicSharedMemorySize, GSMEM);
    cudaFuncSetAttribute(tc_gemm<5>, cudaFuncAttributeMaxDynamicSharedMemorySize, GSMEM);
    cudaFuncSetAttribute(tc_gemm<6>, cudaFuncAttributeMaxDynamicSharedMemorySize, GSMEM);

    // 0) weight/bias packing
    dim3 tb(32, 8);
    wt_h   <<<dim3(DD/32,        DD/32),   tb>>>(wf,       wgt,              DD,   DD);
    wt_pair<<<dim3((2*DD)/32,    DD/32),   tb>>>(wi, wg,   wgt + 1024*DD,    DD,   DD);
    wt_h   <<<dim3(DD/32,        DD/32),   tb>>>(wo,       wgt + 3072*DD,    DD,   DD);
    wt_pair<<<dim3((2*DFF_)/32,  DD/32),   tb>>>(wfc, wfa, wff,              DD,   DFF_);
    wt_h   <<<dim3(DD/32,        DFF_/32), tb>>>(wou,      wout_,            DFF_, DD);
    pack_bias<<<(2*DFF_)/256, 256>>>(bf_, bi_, bg_, bo_, bfc, bfa, bg4, bff);

    // 1) norm1 -> fp16
    rmsnorm_h<<<MM, 256>>>(x, n1w, xn);

    // 2) gate GEMM (N=4096) -> a, bv, o
    int gGates = (MM/BM) * ((4*DD)/BN);
    tc_gemm<5><<<gGates, NT, GSMEM>>>(xn, wgt, bg4, nullptr, ga, nullptr, gbv, go,
                                      MM, 4*DD, DD);

    // 3) scan + output gate + residual -> x1
    scan_pass1<<<(BB*NCH*DD)/256, 256>>>(ga, gbv, P, H);
    scan_pass2<<<(BB*DD)/256, 256>>>(P, H, h0, I);
    scan_pass3<<<(BB*NCH*DD)/256, 256>>>(ga, gbv, go, x, I, x1);

    // 4) norm2 -> fp16
    rmsnorm_h<<<MM, 256>>>(x1, n2w, xn2);

    // 5) fused FFN-up (N=8192, interleaved) -> hff fp16
    int gFF = (MM/BM) * ((2*DFF_)/BN);
    tc_gemm<6><<<gFF, NT, GSMEM>>>(xn2, wff, bff, nullptr, nullptr, hff, nullptr, nullptr,
                                   MM, 2*DFF_, DD);

    // 6) down-proj + b_out + x1 -> d_out
    int gOut = (MM/BM) * (DD/BN);
    tc_gemm<4><<<gOut, NT, GSMEM>>>(hff, wout_, bou, x1, out, nullptr, nullptr, nullptr,
                                    MM, DD, DFF_);
}

// round 5
// speedup vs baseline: 8.8068x; 1.1564x over previous
#include <cuda_runtime.h>
#include <cuda_fp16.h>
#include <cstdint>

// Problem shape (fixed)
#define BB   4
#define LL   4096
#define DD   1024
#define DFF_ 4096
#define MM   (BB*LL)        // 16384 token rows
#define NCH  32
#define CHUNK 128

// ---------------- scratch (device globals: allocation-free) ----------------
__device__ float g_a  [MM*DD];      // sigmoid(forget)
__device__ float g_bv [MM*DD];      // tanh(input)*sigmoid(igate)
__device__ float g_o  [MM*DD];      // sigmoid(ogate)
__device__ float g_x1 [MM*DD];
__device__ float g_P  [BB*NCH*DD];
__device__ float g_H  [BB*NCH*DD];
__device__ float g_I  [BB*NCH*DD];
__device__ float g_bg [4*DD];       // gate bias, layout [f | i,g interleaved | o]
__device__ float g_bff[2*DFF_];     // ffn bias, interleaved [bfc_j, bfa_j]

__device__ __half g_xn [MM*DD];
__device__ __half g_xn2[MM*DD];
__device__ __half g_hff[MM*DFF_];
__device__ __half g_wgt[4*DD*DD];   // [4096,1024] K-major, rows [f | i,g ilv | o]
__device__ __half g_wff[2*DFF_*DD]; // [8192,1024] K-major, rows interleaved (fc,fca)
__device__ __half g_wout[DD*DFF_];  // [1024,4096] K-major

// ---------------- asm helpers ----------------
__device__ __forceinline__ uint32_t smem_to_u32(const void* p) {
    uint32_t a;
    asm("{ .reg .u64 t; cvta.to.shared.u64 t, %1; cvt.u32.u64 %0, t; }" : "=r"(a) : "l"(p));
    return a;
}
__device__ __forceinline__ void cp_async16(uint32_t sa, const void* gp) {
    asm volatile("cp.async.cg.shared.global [%0], [%1], 16;" :: "r"(sa), "l"(gp));
}
__device__ __forceinline__ void cp_commit() {
    asm volatile("cp.async.commit_group;" ::: "memory");
}
__device__ __forceinline__ void ldsm4(uint32_t* d, uint32_t addr) {
    asm volatile("ldmatrix.sync.aligned.m8n8.x4.shared.b16 {%0,%1,%2,%3}, [%4];"
        : "=r"(d[0]), "=r"(d[1]), "=r"(d[2]), "=r"(d[3]) : "r"(addr));
}
__device__ __forceinline__ void mma_f16(float* c, const uint32_t* a, const uint32_t* b) {
    asm volatile("mma.sync.aligned.m16n8k16.row.col.f32.f16.f16.f32 "
        "{%0,%1,%2,%3}, {%4,%5,%6,%7}, {%8,%9}, {%0,%1,%2,%3};"
        : "+f"(c[0]), "+f"(c[1]), "+f"(c[2]), "+f"(c[3])
        : "r"(a[0]), "r"(a[1]), "r"(a[2]), "r"(a[3]), "r"(b[0]), "r"(b[1]));
}
__device__ __forceinline__ float sigmoidf_(float v) { return 1.f / (1.f + expf(-v)); }

// SW128-style swizzle for [rows][64 fp16] tiles (128B rows, 8 x 16B chunks)
__device__ __forceinline__ uint32_t swz(int row, int c) {
    return (uint32_t)(row * 128 + (((c) ^ (row & 7)) << 4));
}

// ---------------- RMSNorm -> fp16 ----------------
__global__ void rmsnorm_h(const float* __restrict__ x, const float* __restrict__ w,
                          __half* __restrict__ o)
{
    int row = blockIdx.x;
    int tid = threadIdx.x; // 256 threads x 4 floats
    const float4* xv = reinterpret_cast<const float4*>(x + (size_t)row * DD);
    const float4* wv = reinterpret_cast<const float4*>(w);
    float4 v = xv[tid];
    float ss = v.x*v.x + v.y*v.y + v.z*v.z + v.w*v.w;
    #pragma unroll
    for (int of = 16; of > 0; of >>= 1) ss += __shfl_xor_sync(0xffffffffu, ss, of);
    __shared__ float red[8];
    __shared__ float s_scale;
    if ((tid & 31) == 0) red[tid >> 5] = ss;
    __syncthreads();
    if (tid == 0) {
        float t = 0.f;
        #pragma unroll
        for (int i = 0; i < 8; i++) t += red[i];
        s_scale = rsqrtf(t / (float)DD + 1e-6f);
    }
    __syncthreads();
    float s = s_scale;
    float4 w4 = wv[tid];
    __half2* ov = reinterpret_cast<__half2*>(o + (size_t)row * DD);
    ov[tid*2]   = __floats2half2_rn(v.x*s*w4.x, v.y*s*w4.y);
    ov[tid*2+1] = __floats2half2_rn(v.z*s*w4.z, v.w*s*w4.w);
}

// ---------------- weight packing ----------------
__global__ void wt_h(const float* __restrict__ W, __half* __restrict__ T, int K, int N)
{
    __shared__ float t[32][33];
    int n0 = blockIdx.x * 32, k0 = blockIdx.y * 32;
    int tx = threadIdx.x, ty = threadIdx.y; // (32,8)
    #pragma unroll
    for (int i = 0; i < 32; i += 8)
        t[ty + i][tx] = W[(size_t)(k0 + ty + i) * N + n0 + tx];
    __syncthreads();
    #pragma unroll
    for (int i = 0; i < 32; i += 8)
        T[(size_t)(n0 + ty + i) * K + k0 + tx] = __float2half_rn(t[tx][ty + i]);
}
__global__ void wt_pair(const float* __restrict__ S0, const float* __restrict__ S1,
                        __half* __restrict__ T, int K, int Nsrc)
{
    __shared__ float t[32][33];
    int n0 = blockIdx.x * 32, k0 = blockIdx.y * 32;
    int tx = threadIdx.x, ty = threadIdx.y;
    const float* S = ((n0 + tx) & 1) ? S1 : S0;
    int col = (n0 + tx) >> 1;
    #pragma unroll
    for (int i = 0; i < 32; i += 8)
        t[ty + i][tx] = S[(size_t)(k0 + ty + i) * Nsrc + col];
    __syncthreads();
    #pragma unroll
    for (int i = 0; i < 32; i += 8)
        T[(size_t)(n0 + ty + i) * K + k0 + tx] = __float2half_rn(t[tx][ty + i]);
}
__global__ void pack_bias(const float* __restrict__ bf, const float* __restrict__ bi,
                          const float* __restrict__ bg, const float* __restrict__ bo,
                          const float* __restrict__ bfc, const float* __restrict__ bfa,
                          float* __restrict__ BG, float* __restrict__ BFF)
{
    int n = blockIdx.x * blockDim.x + threadIdx.x;
    if (n < 4 * DD) {
        float v;
        if (n < DD)            v = bf[n];
        else if (n < 3 * DD) { int t = n - DD; v = (t & 1) ? bg[t >> 1] : bi[t >> 1]; }
        else                   v = bo[n - 3 * DD];
        BG[n] = v;
    }
    if (n < 2 * DFF_)
        BFF[n] = (n & 1) ? bfa[n >> 1] : bfc[n >> 1];
}

// ---------------- pipelined HMMA GEMM: 512 threads, warp tile 64x32 ----------------
// C[M,N] = ACT(A @ B'^T + bias)  A fp16 [M,K] row-major, B' fp16 [N,K] row-major
// ACT 4: v+aux -> C (down-proj)
// ACT 5: gates, N=4096 layout [f | i,g ilv | o]: -> C(a), C1(bv), C2(o)
// ACT 6: fused FFN-up, N=8192 ilv (fc,fca): hff=fc*silu(fca) -> Ch fp16
constexpr int BM = 128, BN = 256, BK = 64, STAGES = 4, NT = 512;
constexpr int ASTG = BM * BK * 2;     // 16 KB
constexpr int BSTG = BN * BK * 2;     // 32 KB
constexpr int STG  = ASTG + BSTG;     // 48 KB
constexpr int GSMEM = STAGES * STG;   // 192 KB

template<int ACT>
__global__ __launch_bounds__(NT, 1) void tc_gemm(
    const __half* __restrict__ A, const __half* __restrict__ Bw,
    const float* __restrict__ bias, const float* __restrict__ aux,
    float* __restrict__ C, __half* __restrict__ Ch,
    float* __restrict__ C1, float* __restrict__ C2,
    int M, int N, int K)
{
    extern __shared__ __align__(128) char smem[];
    uint32_t su = smem_to_u32(smem);
    int tid = threadIdx.x, wid = tid >> 5, lane = tid & 31;

    // supertile raster (8 m-tiles per group) for L2 reuse
    int tn = N / BN;
    int per = 8 * tn, grp = blockIdx.x / per, rr = blockIdx.x % per;
    int m0 = (grp * 8 + (rr % 8)) * BM;
    int n0 = (rr / 8) * BN;

    const __half* Ab = A  + (size_t)m0 * K;
    const __half* Bb = Bw + (size_t)n0 * K;

    // cp.async offsets: A 2 chunks/thread, B 4 chunks/thread
    uint32_t sAo[2], gAo[2], sBo[4], gBo[4];
    #pragma unroll
    for (int j = 0; j < 2; j++) {
        int idx = tid + j * NT, r = idx >> 3, c = idx & 7;
        sAo[j] = swz(r, c); gAo[j] = (uint32_t)(r * K + c * 8);
    }
    #pragma unroll
    for (int j = 0; j < 4; j++) {
        int idx = tid + j * NT, r = idx >> 3, c = idx & 7;
        sBo[j] = swz(r, c); gBo[j] = (uint32_t)(r * K + c * 8);
    }

    // warp layout: 2 (m) x 8 (n); warp tile 64x32
    int wm = (wid & 1) * 64, wn = (wid >> 1) * 32;
    int rA128[4], rA7[4], rB128[2], rB7[2];
    int cA = lane >> 4;           // 0..1
    int cB = (lane >> 3) & 1;     // 0..1
    #pragma unroll
    for (int i = 0; i < 4; i++) {
        int ra = wm + i * 16 + (lane & 15);
        rA128[i] = ra * 128; rA7[i] = ra & 7;
    }
    #pragma unroll
    for (int p = 0; p < 2; p++) {
        int rb = wn + p * 16 + (lane & 7) + ((lane >> 4) << 3);
        rB128[p] = rb * 128; rB7[p] = rb & 7;
    }

    float acc[4][4][4];
    #pragma unroll
    for (int i = 0; i < 4; i++)
        #pragma unroll
        for (int j = 0; j < 4; j++)
            #pragma unroll
            for (int q = 0; q < 4; q++) acc[i][j][q] = 0.f;

    const int NK = K / BK;

    #pragma unroll
    for (int s = 0; s < STAGES - 1; s++) {
        uint32_t sA = su + s * STG, sB = sA + ASTG;
        int k0 = s * BK;
        #pragma unroll
        for (int j = 0; j < 2; j++) cp_async16(sA + sAo[j], Ab + gAo[j] + k0);
        #pragma unroll
        for (int j = 0; j < 4; j++) cp_async16(sB + sBo[j], Bb + gBo[j] + k0);
        cp_commit();
    }

    int cs = 0, ls = STAGES - 1;
    for (int kt = 0; kt < NK; kt++) {
        asm volatile("cp.async.wait_group %0;" :: "n"(STAGES - 2) : "memory");
        __syncthreads();

        int lt = kt + STAGES - 1;
        if (lt < NK) {
            uint32_t sA = su + ls * STG, sB = sA + ASTG;
            int k0 = lt * BK;
            #pragma unroll
            for (int j = 0; j < 2; j++) cp_async16(sA + sAo[j], Ab + gAo[j] + k0);
            #pragma unroll
            for (int j = 0; j < 4; j++) cp_async16(sB + sBo[j], Bb + gBo[j] + k0);
        }
        cp_commit();
        if (++ls == STAGES) ls = 0;

        uint32_t sA = su + cs * STG, sB = sA + ASTG;
        if (++cs == STAGES) cs = 0;
        #pragma unroll
        for (int kk = 0; kk < 4; kk++) {
            uint32_t a[4][4], b[2][4];
            #pragma unroll
            for (int i = 0; i < 4; i++)
                ldsm4(a[i], sA + rA128[i] + (((kk * 2 + cA) ^ rA7[i]) << 4));
            #pragma unroll
            for (int p = 0; p < 2; p++)
                ldsm4(b[p], sB + rB128[p] + (((kk * 2 + cB) ^ rB7[p]) << 4));
            #pragma unroll
            for (int p = 0; p < 2; p++)
                #pragma unroll
                for (int i = 0; i < 4; i++) {
                    mma_f16(acc[i][2*p],     a[i], b[p]);
                    mma_f16(acc[i][2*p + 1], a[i], b[p] + 2);
                }
        }
    }

    // ---- fused epilogue ----
    #pragma unroll
    for (int i = 0; i < 4; i++) {
        int r0 = m0 + wm + i * 16 + (lane >> 2);
        #pragma unroll
        for (int j = 0; j < 4; j++) {
            int c0 = n0 + wn + j * 8 + (lane & 3) * 2;
            float b0 = bias[c0], b1 = bias[c0 + 1];
            #pragma unroll
            for (int h = 0; h < 2; h++) {
                int r = r0 + h * 8;
                float v0 = acc[i][j][2*h]     + b0;
                float v1 = acc[i][j][2*h + 1] + b1;
                if (ACT == 4) {
                    size_t idx = (size_t)r * N + c0;
                    float2 au = *reinterpret_cast<const float2*>(&aux[idx]);
                    *reinterpret_cast<float2*>(&C[idx]) = make_float2(v0 + au.x, v1 + au.y);
                } else if (ACT == 5) {
                    if (c0 < 1024) {
                        *reinterpret_cast<float2*>(&C[(size_t)r * DD + c0]) =
                            make_float2(sigmoidf_(v0), sigmoidf_(v1));
                    } else if (c0 < 3072) {
                        C1[(size_t)r * DD + ((c0 - 1024) >> 1)] = tanhf(v0) * sigmoidf_(v1);
                    } else {
                        *reinterpret_cast<float2*>(&C2[(size_t)r * DD + (c0 - 3072)]) =
                            make_float2(sigmoidf_(v0), sigmoidf_(v1));
                    }
                } else if (ACT == 6) {
                    Ch[(size_t)r * DFF_ + (c0 >> 1)] =
                        __float2half_rn(v0 * (v1 * sigmoidf_(v1)));
                }
            }
        }
    }
}

// ---------------- chunked linear-recurrence scan ----------------
__global__ void scan_pass1(const float* __restrict__ aG, const float* __restrict__ bV,
                           float* __restrict__ Pb, float* __restrict__ Hb)
{
    int g = blockIdx.x * blockDim.x + threadIdx.x;
    int d = g & (DD - 1);
    int c = (g >> 10) & (NCH - 1);
    int b = g >> 15;
    size_t base = ((size_t)b * LL + (size_t)c * CHUNK) * DD + d;
    float P = 1.f, h = 0.f;
    #pragma unroll 4
    for (int t = 0; t < CHUNK; t++) {
        size_t idx = base + (size_t)t * DD;
        float a = aG[idx];
        P *= a;
        h = fmaf(a, h, bV[idx]);
    }
    Pb[g] = P;
    Hb[g] = h;
}

__global__ void scan_pass2(const float* __restrict__ Pb, const float* __restrict__ Hb,
                           const float* __restrict__ h0, float* __restrict__ Ib)
{
    int g = blockIdx.x * blockDim.x + threadIdx.x;
    int d = g & (DD - 1);
    int b = g >> 10;
    float h = h0[d];
    #pragma unroll
    for (int c = 0; c < NCH; c++) {
        int j = (b * NCH + c) * DD + d;
        Ib[j] = h;
        h = fmaf(Pb[j], h, Hb[j]);
    }
}

__global__ void scan_pass3(const float* __restrict__ aG, const float* __restrict__ bV,
                           const float* __restrict__ oS, const float* __restrict__ x,
                           const float* __restrict__ Ib, float* __restrict__ x1)
{
    int g = blockIdx.x * blockDim.x + threadIdx.x;
    int d = g & (DD - 1);
    int c = (g >> 10) & (NCH - 1);
    int b = g >> 15;
    size_t base = ((size_t)b * LL + (size_t)c * CHUNK) * DD + d;
    float h = Ib[g];
    #pragma unroll 4
    for (int t = 0; t < CHUNK; t++) {
        size_t idx = base + (size_t)t * DD;
        h = fmaf(aG[idx], h, bV[idx]);
        x1[idx] = tanhf(h) * oS[idx] + x[idx];
    }
}

// ---------------- launcher ----------------
extern "C" void kernel_launch(void* const* d_in, const int* in_sizes, int n_in,
                              void* d_out, int out_size)
{
    (void)in_sizes; (void)n_in; (void)out_size;
    const float* x   = (const float*)d_in[0];
    const float* wf  = (const float*)d_in[1];
    const float* bf_ = (const float*)d_in[2];
    const float* wi  = (const float*)d_in[3];
    const float* bi_ = (const float*)d_in[4];
    const float* wg  = (const float*)d_in[5];
    const float* bg_ = (const float*)d_in[6];
    const float* wo  = (const float*)d_in[7];
    const float* bo_ = (const float*)d_in[8];
    const float* h0  = (const float*)d_in[9];
    const float* n1w = (const float*)d_in[10];
    const float* n2w = (const float*)d_in[11];
    const float* wfc = (const float*)d_in[12];
    const float* bfc = (const float*)d_in[13];
    const float* wfa = (const float*)d_in[14];
    const float* bfa = (const float*)d_in[15];
    const float* wou = (const float*)d_in[16];
    const float* bou = (const float*)d_in[17];
    float* out = (float*)d_out;

    float *ga, *gbv, *go, *x1, *P, *H, *I, *bg4, *bff;
    cudaGetSymbolAddress((void**)&ga,  g_a);
    cudaGetSymbolAddress((void**)&gbv, g_bv);
    cudaGetSymbolAddress((void**)&go,  g_o);
    cudaGetSymbolAddress((void**)&x1,  g_x1);
    cudaGetSymbolAddress((void**)&P,   g_P);
    cudaGetSymbolAddress((void**)&H,   g_H);
    cudaGetSymbolAddress((void**)&I,   g_I);
    cudaGetSymbolAddress((void**)&bg4, g_bg);
    cudaGetSymbolAddress((void**)&bff, g_bff);

    __half *xn, *xn2, *hff, *wgt, *wff, *wout_;
    cudaGetSymbolAddress((void**)&xn,   g_xn);
    cudaGetSymbolAddress((void**)&xn2,  g_xn2);
    cudaGetSymbolAddress((void**)&hff,  g_hff);
    cudaGetSymbolAddress((void**)&wgt,  g_wgt);
    cudaGetSymbolAddress((void**)&wff,  g_wff);
    cudaGetSymbolAddress((void**)&wout_,g_wout);

    cudaFuncSetAttribute(tc_gemm<4>, cudaFuncAttributeMaxDynamicSharedMemorySize, GSMEM);
    cudaFuncSetAttribute(tc_gemm<5>, cudaFuncAttributeMaxDynamicSharedMemorySize, GSMEM);
    cudaFuncSetAttribute(tc_gemm<6>, cudaFuncAttributeMaxDynamicSharedMemorySize, GSMEM);

    // 0) weight/bias packing
    dim3 tb(32, 8);
    wt_h   <<<dim3(DD/32,        DD/32),   tb>>>(wf,       wgt,              DD,   DD);
    wt_pair<<<dim3((2*DD)/32,    DD/32),   tb>>>(wi, wg,   wgt + 1024*DD,    DD,   DD);
    wt_h   <<<dim3(DD/32,        DD/32),   tb>>>(wo,       wgt + 3072*DD,    DD,   DD);
    wt_pair<<<dim3((2*DFF_)/32,  DD/32),   tb>>>(wfc, wfa, wff,              DD,   DFF_);
    wt_h   <<<dim3(DD/32,        DFF_/32), tb>>>(wou,      wout_,            DFF_, DD);
    pack_bias<<<(2*DFF_)/256, 256>>>(bf_, bi_, bg_, bo_, bfc, bfa, bg4, bff);

    // 1) norm1 -> fp16
    rmsnorm_h<<<MM, 256>>>(x, n1w, xn);

    // 2) gate GEMM (N=4096) -> a, bv, o
    int gGates = (MM/BM) * ((4*DD)/BN);
    tc_gemm<5><<<gGates, NT, GSMEM>>>(xn, wgt, bg4, nullptr, ga, nullptr, gbv, go,
                                      MM, 4*DD, DD);

    // 3) scan + output gate + residual -> x1
    scan_pass1<<<(BB*NCH*DD)/256, 256>>>(ga, gbv, P, H);
    scan_pass2<<<(BB*DD)/256, 256>>>(P, H, h0, I);
    scan_pass3<<<(BB*NCH*DD)/256, 256>>>(ga, gbv, go, x, I, x1);

    // 4) norm2 -> fp16
    rmsnorm_h<<<MM, 256>>>(x1, n2w, xn2);

    // 5) fused FFN-up (N=8192, interleaved) -> hff fp16
    int gFF = (MM/BM) * ((2*DFF_)/BN);
    tc_gemm<6><<<gFF, NT, GSMEM>>>(xn2, wff, bff, nullptr, nullptr, hff, nullptr, nullptr,
                                   MM, 2*DFF_, DD);

    // 6) down-proj + b_out + x1 -> d_out
    int gOut = (MM/BM) * (DD/BN);
    tc_gemm<4><<<gOut, NT, GSMEM>>>(hff, wout_, bou, x1, out, nullptr, nullptr, nullptr,
                                    MM, DD, DFF_);
}

// round 6
// speedup vs baseline: 10.1738x; 1.1552x over previous
#include <cuda_runtime.h>
#include <cuda_fp16.h>
#include <cstdint>

// Problem shape (fixed)
#define BB   4
#define LL   4096
#define DD   1024
#define DFF_ 4096
#define MM   (BB*LL)        // 16384 token rows
#define NCH  32
#define CHUNK 128

// ---------------- scratch (device globals: allocation-free) ----------------
__device__ float g_a  [MM*DD];      // sigmoid(forget)
__device__ float g_bv [MM*DD];      // tanh(input)*sigmoid(igate)
__device__ float g_o  [MM*DD];      // sigmoid(ogate)
__device__ float g_x1 [MM*DD];
__device__ float g_P  [BB*NCH*DD];
__device__ float g_H  [BB*NCH*DD];
__device__ float g_I  [BB*NCH*DD];
__device__ float g_bg [4*DD];       // gate bias, layout [f | i,g interleaved | o]
__device__ float g_bff[2*DFF_];     // ffn bias, interleaved [bfc_j, bfa_j]

__device__ __half g_xn [MM*DD];
__device__ __half g_xn2[MM*DD];
__device__ __half g_hff[MM*DFF_];
__device__ __half g_wgt[4*DD*DD];   // [4096,1024] K-major, rows [f | i,g ilv | o]
__device__ __half g_wff[2*DFF_*DD]; // [8192,1024] K-major, rows interleaved (fc,fca)
__device__ __half g_wout[DD*DFF_];  // [1024,4096] K-major

// ---------------- asm helpers ----------------
__device__ __forceinline__ uint32_t smem_to_u32(const void* p) {
    uint32_t a;
    asm("{ .reg .u64 t; cvta.to.shared.u64 t, %1; cvt.u32.u64 %0, t; }" : "=r"(a) : "l"(p));
    return a;
}
__device__ __forceinline__ void cp_async16(uint32_t sa, const void* gp) {
    asm volatile("cp.async.cg.shared.global [%0], [%1], 16;" :: "r"(sa), "l"(gp));
}
__device__ __forceinline__ void cp_commit() {
    asm volatile("cp.async.commit_group;" ::: "memory");
}
__device__ __forceinline__ void ldsm4(uint32_t* d, uint32_t addr) {
    asm volatile("ldmatrix.sync.aligned.m8n8.x4.shared.b16 {%0,%1,%2,%3}, [%4];"
        : "=r"(d[0]), "=r"(d[1]), "=r"(d[2]), "=r"(d[3]) : "r"(addr));
}
__device__ __forceinline__ void mma_f16(float* c, const uint32_t* a, const uint32_t* b) {
    asm volatile("mma.sync.aligned.m16n8k16.row.col.f32.f16.f16.f32 "
        "{%0,%1,%2,%3}, {%4,%5,%6,%7}, {%8,%9}, {%0,%1,%2,%3};"
        : "+f"(c[0]), "+f"(c[1]), "+f"(c[2]), "+f"(c[3])
        : "r"(a[0]), "r"(a[1]), "r"(a[2]), "r"(a[3]), "r"(b[0]), "r"(b[1]));
}
__device__ __forceinline__ float sigmoidf_(float v) { return 1.f / (1.f + expf(-v)); }

// SW128-style swizzle for [rows][64 fp16] tiles (128B rows, 8 x 16B chunks)
__device__ __forceinline__ uint32_t swz(int row, int c) {
    return (uint32_t)(row * 128 + (((c) ^ (row & 7)) << 4));
}

// ---------------- RMSNorm -> fp16 ----------------
__global__ void rmsnorm_h(const float* __restrict__ x, const float* __restrict__ w,
                          __half* __restrict__ o)
{
    int row = blockIdx.x;
    int tid = threadIdx.x; // 256 threads x 4 floats
    const float4* xv = reinterpret_cast<const float4*>(x + (size_t)row * DD);
    const float4* wv = reinterpret_cast<const float4*>(w);
    float4 v = xv[tid];
    float ss = v.x*v.x + v.y*v.y + v.z*v.z + v.w*v.w;
    #pragma unroll
    for (int of = 16; of > 0; of >>= 1) ss += __shfl_xor_sync(0xffffffffu, ss, of);
    __shared__ float red[8];
    __shared__ float s_scale;
    if ((tid & 31) == 0) red[tid >> 5] = ss;
    __syncthreads();
    if (tid == 0) {
        float t = 0.f;
        #pragma unroll
        for (int i = 0; i < 8; i++) t += red[i];
        s_scale = rsqrtf(t / (float)DD + 1e-6f);
    }
    __syncthreads();
    float s = s_scale;
    float4 w4 = wv[tid];
    __half2* ov = reinterpret_cast<__half2*>(o + (size_t)row * DD);
    ov[tid*2]   = __floats2half2_rn(v.x*s*w4.x, v.y*s*w4.y);
    ov[tid*2+1] = __floats2half2_rn(v.z*s*w4.z, v.w*s*w4.w);
}

// ---------------- weight packing ----------------
__global__ void wt_h(const float* __restrict__ W, __half* __restrict__ T, int K, int N)
{
    __shared__ float t[32][33];
    int n0 = blockIdx.x * 32, k0 = blockIdx.y * 32;
    int tx = threadIdx.x, ty = threadIdx.y; // (32,8)
    #pragma unroll
    for (int i = 0; i < 32; i += 8)
        t[ty + i][tx] = W[(size_t)(k0 + ty + i) * N + n0 + tx];
    __syncthreads();
    #pragma unroll
    for (int i = 0; i < 32; i += 8)
        T[(size_t)(n0 + ty + i) * K + k0 + tx] = __float2half_rn(t[tx][ty + i]);
}
__global__ void wt_pair(const float* __restrict__ S0, const float* __restrict__ S1,
                        __half* __restrict__ T, int K, int Nsrc)
{
    __shared__ float t[32][33];
    int n0 = blockIdx.x * 32, k0 = blockIdx.y * 32;
    int tx = threadIdx.x, ty = threadIdx.y;
    const float* S = ((n0 + tx) & 1) ? S1 : S0;
    int col = (n0 + tx) >> 1;
    #pragma unroll
    for (int i = 0; i < 32; i += 8)
        t[ty + i][tx] = S[(size_t)(k0 + ty + i) * Nsrc + col];
    __syncthreads();
    #pragma unroll
    for (int i = 0; i < 32; i += 8)
        T[(size_t)(n0 + ty + i) * K + k0 + tx] = __float2half_rn(t[tx][ty + i]);
}
__global__ void pack_bias(const float* __restrict__ bf, const float* __restrict__ bi,
                          const float* __restrict__ bg, const float* __restrict__ bo,
                          const float* __restrict__ bfc, const float* __restrict__ bfa,
                          float* __restrict__ BG, float* __restrict__ BFF)
{
    int n = blockIdx.x * blockDim.x + threadIdx.x;
    if (n < 4 * DD) {
        float v;
        if (n < DD)            v = bf[n];
        else if (n < 3 * DD) { int t = n - DD; v = (t & 1) ? bg[t >> 1] : bi[t >> 1]; }
        else                   v = bo[n - 3 * DD];
        BG[n] = v;
    }
    if (n < 2 * DFF_)
        BFF[n] = (n & 1) ? bfa[n >> 1] : bfc[n >> 1];
}

// ---------------- pipelined HMMA GEMM: 256 threads, 2 CTAs/SM ----------------
// C[M,N] = ACT(A @ B'^T + bias)  A fp16 [M,K] row-major, B' fp16 [N,K] row-major
// ACT 4: v+aux -> C (down-proj)
// ACT 5: gates, N=4096 layout [f | i,g ilv | o]: -> C(a), C1(bv), C2(o)
// ACT 6: fused FFN-up, N=8192 ilv (fc,fca): hff=fc*silu(fca) -> Ch fp16
constexpr int BM = 128, BN = 128, BK = 64, STAGES = 3, NT = 256;
constexpr int ASTG = BM * BK * 2;     // 16 KB
constexpr int BSTG = BN * BK * 2;     // 16 KB
constexpr int STG  = ASTG + BSTG;     // 32 KB
constexpr int GSMEM = STAGES * STG;   // 96 KB -> 2 CTAs/SM

template<int ACT>
__global__ __launch_bounds__(NT, 2) void tc_gemm(
    const __half* __restrict__ A, const __half* __restrict__ Bw,
    const float* __restrict__ bias, const float* __restrict__ aux,
    float* __restrict__ C, __half* __restrict__ Ch,
    float* __restrict__ C1, float* __restrict__ C2,
    int M, int N, int K)
{
    extern __shared__ __align__(128) char smem[];
    uint32_t su = smem_to_u32(smem);
    int tid = threadIdx.x, wid = tid >> 5, lane = tid & 31;

    // supertile raster (8 m-tiles per group) for L2 reuse
    int tn = N / BN;
    int per = 8 * tn, grp = blockIdx.x / per, rr = blockIdx.x % per;
    int m0 = (grp * 8 + (rr % 8)) * BM;
    int n0 = (rr / 8) * BN;

    const __half* Ab = A  + (size_t)m0 * K;
    const __half* Bb = Bw + (size_t)n0 * K;

    // cp.async offsets: A 4 chunks/thread, B 4 chunks/thread (16B chunks)
    uint32_t sAo[4], gAo[4], sBo[4], gBo[4];
    #pragma unroll
    for (int j = 0; j < 4; j++) {
        int idx = tid + j * NT, r = idx >> 3, c = idx & 7;
        sAo[j] = swz(r, c); gAo[j] = (uint32_t)(r * K + c * 8);
        sBo[j] = sAo[j];    gBo[j] = gAo[j];
    }

    // warp layout: 2 (m) x 4 (n); warp tile 64x32
    int wm = (wid & 1) * 64, wn = (wid >> 1) * 32;
    int rA128[4], rA7[4], rB128[2], rB7[2];
    int cA = lane >> 4;           // 0..1
    int cB = (lane >> 3) & 1;     // 0..1
    #pragma unroll
    for (int i = 0; i < 4; i++) {
        int ra = wm + i * 16 + (lane & 15);
        rA128[i] = ra * 128; rA7[i] = ra & 7;
    }
    #pragma unroll
    for (int p = 0; p < 2; p++) {
        int rb = wn + p * 16 + (lane & 7) + ((lane >> 4) << 3);
        rB128[p] = rb * 128; rB7[p] = rb & 7;
    }

    float acc[4][4][4];
    #pragma unroll
    for (int i = 0; i < 4; i++)
        #pragma unroll
        for (int j = 0; j < 4; j++)
            #pragma unroll
            for (int q = 0; q < 4; q++) acc[i][j][q] = 0.f;

    const int NK = K / BK;

    #pragma unroll
    for (int s = 0; s < STAGES - 1; s++) {
        uint32_t sA = su + s * STG, sB = sA + ASTG;
        int k0 = s * BK;
        #pragma unroll
        for (int j = 0; j < 4; j++) {
            cp_async16(sA + sAo[j], Ab + gAo[j] + k0);
            cp_async16(sB + sBo[j], Bb + gBo[j] + k0);
        }
        cp_commit();
    }

    int cs = 0, ls = STAGES - 1;
    for (int kt = 0; kt < NK; kt++) {
        asm volatile("cp.async.wait_group %0;" :: "n"(STAGES - 2) : "memory");
        __syncthreads();

        int lt = kt + STAGES - 1;
        if (lt < NK) {
            uint32_t sA = su + ls * STG, sB = sA + ASTG;
            int k0 = lt * BK;
            #pragma unroll
            for (int j = 0; j < 4; j++) {
                cp_async16(sA + sAo[j], Ab + gAo[j] + k0);
                cp_async16(sB + sBo[j], Bb + gBo[j] + k0);
            }
        }
        cp_commit();
        if (++ls == STAGES) ls = 0;

        uint32_t sA = su + cs * STG, sB = sA + ASTG;
        if (++cs == STAGES) cs = 0;
        #pragma unroll
        for (int kk = 0; kk < 4; kk++) {
            uint32_t a[4][4], b[2][4];
            #pragma unroll
            for (int i = 0; i < 4; i++)
                ldsm4(a[i], sA + rA128[i] + (((kk * 2 + cA) ^ rA7[i]) << 4));
            #pragma unroll
            for (int p = 0; p < 2; p++)
                ldsm4(b[p], sB + rB128[p] + (((kk * 2 + cB) ^ rB7[p]) << 4));
            #pragma unroll
            for (int p = 0; p < 2; p++)
                #pragma unroll
                for (int i = 0; i < 4; i++) {
                    mma_f16(acc[i][2*p],     a[i], b[p]);
                    mma_f16(acc[i][2*p + 1], a[i], b[p] + 2);
                }
        }
    }

    // ---- fused epilogue ----
    #pragma unroll
    for (int i = 0; i < 4; i++) {
        int r0 = m0 + wm + i * 16 + (lane >> 2);
        #pragma unroll
        for (int j = 0; j < 4; j++) {
            int c0 = n0 + wn + j * 8 + (lane & 3) * 2;
            float b0 = bias[c0], b1 = bias[c0 + 1];
            #pragma unroll
            for (int h = 0; h < 2; h++) {
                int r = r0 + h * 8;
                float v0 = acc[i][j][2*h]     + b0;
                float v1 = acc[i][j][2*h + 1] + b1;
                if (ACT == 4) {
                    size_t idx = (size_t)r * N + c0;
                    float2 au = *reinterpret_cast<const float2*>(&aux[idx]);
                    *reinterpret_cast<float2*>(&C[idx]) = make_float2(v0 + au.x, v1 + au.y);
                } else if (ACT == 5) {
                    if (c0 < 1024) {
                        *reinterpret_cast<float2*>(&C[(size_t)r * DD + c0]) =
                            make_float2(sigmoidf_(v0), sigmoidf_(v1));
                    } else if (c0 < 3072) {
                        C1[(size_t)r * DD + ((c0 - 1024) >> 1)] = tanhf(v0) * sigmoidf_(v1);
                    } else {
                        *reinterpret_cast<float2*>(&C2[(size_t)r * DD + (c0 - 3072)]) =
                            make_float2(sigmoidf_(v0), sigmoidf_(v1));
                    }
                } else if (ACT == 6) {
                    Ch[(size_t)r * DFF_ + (c0 >> 1)] =
                        __float2half_rn(v0 * (v1 * sigmoidf_(v1)));
                }
            }
        }
    }
}

// ---------------- chunked linear-recurrence scan ----------------
__global__ void scan_pass1(const float* __restrict__ aG, const float* __restrict__ bV,
                           float* __restrict__ Pb, float* __restrict__ Hb)
{
    int g = blockIdx.x * blockDim.x + threadIdx.x;
    int d = g & (DD - 1);
    int c = (g >> 10) & (NCH - 1);
    int b = g >> 15;
    size_t base = ((size_t)b * LL + (size_t)c * CHUNK) * DD + d;
    float P = 1.f, h = 0.f;
    #pragma unroll 4
    for (int t = 0; t < CHUNK; t++) {
        size_t idx = base + (size_t)t * DD;
        float a = aG[idx];
        P *= a;
        h = fmaf(a, h, bV[idx]);
    }
    Pb[g] = P;
    Hb[g] = h;
}

__global__ void scan_pass2(const float* __restrict__ Pb, const float* __restrict__ Hb,
                           const float* __restrict__ h0, float* __restrict__ Ib)
{
    int g = blockIdx.x * blockDim.x + threadIdx.x;
    int d = g & (DD - 1);
    int b = g >> 10;
    float h = h0[d];
    #pragma unroll
    for (int c = 0; c < NCH; c++) {
        int j = (b * NCH + c) * DD + d;
        Ib[j] = h;
        h = fmaf(Pb[j], h, Hb[j]);
    }
}

__global__ void scan_pass3(const float* __restrict__ aG, const float* __restrict__ bV,
                           const float* __restrict__ oS, const float* __restrict__ x,
                           const float* __restrict__ Ib, float* __restrict__ x1)
{
    int g = blockIdx.x * blockDim.x + threadIdx.x;
    int d = g & (DD - 1);
    int c = (g >> 10) & (NCH - 1);
    int b = g >> 15;
    size_t base = ((size_t)b * LL + (size_t)c * CHUNK) * DD + d;
    float h = Ib[g];
    #pragma unroll 4
    for (int t = 0; t < CHUNK; t++) {
        size_t idx = base + (size_t)t * DD;
        h = fmaf(aG[idx], h, bV[idx]);
        x1[idx] = tanhf(h) * oS[idx] + x[idx];
    }
}

// ---------------- launcher ----------------
extern "C" void kernel_launch(void* const* d_in, const int* in_sizes, int n_in,
                              void* d_out, int out_size)
{
    (void)in_sizes; (void)n_in; (void)out_size;
    const float* x   = (const float*)d_in[0];
    const float* wf  = (const float*)d_in[1];
    const float* bf_ = (const float*)d_in[2];
    const float* wi  = (const float*)d_in[3];
    const float* bi_ = (const float*)d_in[4];
    const float* wg  = (const float*)d_in[5];
    const float* bg_ = (const float*)d_in[6];
    const float* wo  = (const float*)d_in[7];
    const float* bo_ = (const float*)d_in[8];
    const float* h0  = (const float*)d_in[9];
    const float* n1w = (const float*)d_in[10];
    const float* n2w = (const float*)d_in[11];
    const float* wfc = (const float*)d_in[12];
    const float* bfc = (const float*)d_in[13];
    const float* wfa = (const float*)d_in[14];
    const float* bfa = (const float*)d_in[15];
    const float* wou = (const float*)d_in[16];
    const float* bou = (const float*)d_in[17];
    float* out = (float*)d_out;

    float *ga, *gbv, *go, *x1, *P, *H, *I, *bg4, *bff;
    cudaGetSymbolAddress((void**)&ga,  g_a);
    cudaGetSymbolAddress((void**)&gbv, g_bv);
    cudaGetSymbolAddress((void**)&go,  g_o);
    cudaGetSymbolAddress((void**)&x1,  g_x1);
    cudaGetSymbolAddress((void**)&P,   g_P);
    cudaGetSymbolAddress((void**)&H,   g_H);
    cudaGetSymbolAddress((void**)&I,   g_I);
    cudaGetSymbolAddress((void**)&bg4, g_bg);
    cudaGetSymbolAddress((void**)&bff, g_bff);

    __half *xn, *xn2, *hff, *wgt, *wff, *wout_;
    cudaGetSymbolAddress((void**)&xn,   g_xn);
    cudaGetSymbolAddress((void**)&xn2,  g_xn2);
    cudaGetSymbolAddress((void**)&hff,  g_hff);
    cudaGetSymbolAddress((void**)&wgt,  g_wgt);
    cudaGetSymbolAddress((void**)&wff,  g_wff);
    cudaGetSymbolAddress((void**)&wout_,g_wout);

    cudaFuncSetAttribute(tc_gemm<4>, cudaFuncAttributeMaxDynamicSharedMemorySize, GSMEM);
    cudaFuncSetAttribute(tc_gemm<5>, cudaFuncAttributeMaxDynamicSharedMemorySize, GSMEM);
    cudaFuncSetAttribute(tc_gemm<6>, cudaFuncAttributeMaxDynamicSharedMemorySize, GSMEM);

    // 0) weight/bias packing
    dim3 tb(32, 8);
    wt_h   <<<dim3(DD/32,        DD/32),   tb>>>(wf,       wgt,              DD,   DD);
    wt_pair<<<dim3((2*DD)/32,    DD/32),   tb>>>(wi, wg,   wgt + 1024*DD,    DD,   DD);
    wt_h   <<<dim3(DD/32,        DD/32),   tb>>>(wo,       wgt + 3072*DD,    DD,   DD);
    wt_pair<<<dim3((2*DFF_)/32,  DD/32),   tb>>>(wfc, wfa, wff,              DD,   DFF_);
    wt_h   <<<dim3(DD/32,        DFF_/32), tb>>>(wou,      wout_,            DFF_, DD);
    pack_bias<<<(2*DFF_)/256, 256>>>(bf_, bi_, bg_, bo_, bfc, bfa, bg4, bff);

    // 1) norm1 -> fp16
    rmsnorm_h<<<MM, 256>>>(x, n1w, xn);

    // 2) gate GEMM (N=4096) -> a, bv, o
    int gGates = (MM/BM) * ((4*DD)/BN);
    tc_gemm<5><<<gGates, NT, GSMEM>>>(xn, wgt, bg4, nullptr, ga, nullptr, gbv, go,
                                      MM, 4*DD, DD);

    // 3) scan + output gate + residual -> x1
    scan_pass1<<<(BB*NCH*DD)/256, 256>>>(ga, gbv, P, H);
    scan_pass2<<<(BB*DD)/256, 256>>>(P, H, h0, I);
    scan_pass3<<<(BB*NCH*DD)/256, 256>>>(ga, gbv, go, x, I, x1);

    // 4) norm2 -> fp16
    rmsnorm_h<<<MM, 256>>>(x1, n2w, xn2);

    // 5) fused FFN-up (N=8192, interleaved) -> hff fp16
    int gFF = (MM/BM) * ((2*DFF_)/BN);
    tc_gemm<6><<<gFF, NT, GSMEM>>>(xn2, wff, bff, nullptr, nullptr, hff, nullptr, nullptr,
                                   MM, 2*DFF_, DD);

    // 6) down-proj + b_out + x1 -> d_out
    int gOut = (MM/BM) * (DD/BN);
    tc_gemm<4><<<gOut, NT, GSMEM>>>(hff, wout_, bou, x1, out, nullptr, nullptr, nullptr,
                                    MM, DD, DFF_);
}

// round 7
// speedup vs baseline: 10.1895x; 1.0015x over previous
#include <cuda_runtime.h>
#include <cuda_fp16.h>
#include <cstdint>

// Problem shape (fixed)
#define BB   4
#define LL   4096
#define DD   1024
#define DFF_ 4096
#define MM   (BB*LL)        // 16384 token rows
#define NCH  32
#define CHUNK 128

// ---------------- scratch (device globals: allocation-free) ----------------
__device__ float  g_a  [MM*DD];     // sigmoid(forget)  (fp32: 1/(1-a) error amplification)
__device__ __half g_bvh[MM*DD];     // tanh(input)*sigmoid(igate)
__device__ __half g_oh [MM*DD];     // sigmoid(ogate)
__device__ float  g_x1 [MM*DD];
__device__ float  g_P  [BB*NCH*DD];
__device__ float  g_H  [BB*NCH*DD];
__device__ float  g_I  [BB*NCH*DD];
__device__ float  g_bg [4*DD];      // gate bias, layout [f | i,g interleaved | o]
__device__ float  g_bff[2*DFF_];    // ffn bias, interleaved [bfc_j, bfa_j]

__device__ __half g_xn [MM*DD];
__device__ __half g_xn2[MM*DD];
__device__ __half g_hff[MM*DFF_];
__device__ __half g_wgt[4*DD*DD];   // [4096,1024] K-major, rows [f | i,g ilv | o]
__device__ __half g_wff[2*DFF_*DD]; // [8192,1024] K-major, rows interleaved (fc,fca)
__device__ __half g_wout[DD*DFF_];  // [1024,4096] K-major

// ---------------- asm helpers ----------------
__device__ __forceinline__ uint32_t smem_to_u32(const void* p) {
    uint32_t a;
    asm("{ .reg .u64 t; cvta.to.shared.u64 t, %1; cvt.u32.u64 %0, t; }" : "=r"(a) : "l"(p));
    return a;
}
__device__ __forceinline__ void cp_async16(uint32_t sa, const void* gp) {
    asm volatile("cp.async.cg.shared.global [%0], [%1], 16;" :: "r"(sa), "l"(gp));
}
__device__ __forceinline__ void cp_commit() {
    asm volatile("cp.async.commit_group;" ::: "memory");
}
__device__ __forceinline__ void ldsm4(uint32_t* d, uint32_t addr) {
    asm volatile("ldmatrix.sync.aligned.m8n8.x4.shared.b16 {%0,%1,%2,%3}, [%4];"
        : "=r"(d[0]), "=r"(d[1]), "=r"(d[2]), "=r"(d[3]) : "r"(addr));
}
__device__ __forceinline__ void mma_f16(float* c, const uint32_t* a, const uint32_t* b) {
    asm volatile("mma.sync.aligned.m16n8k16.row.col.f32.f16.f16.f32 "
        "{%0,%1,%2,%3}, {%4,%5,%6,%7}, {%8,%9}, {%0,%1,%2,%3};"
        : "+f"(c[0]), "+f"(c[1]), "+f"(c[2]), "+f"(c[3])
        : "r"(a[0]), "r"(a[1]), "r"(a[2]), "r"(a[3]), "r"(b[0]), "r"(b[1]));
}
__device__ __forceinline__ float sigmoidf_(float v) { return 1.f / (1.f + expf(-v)); }

// SW128-style swizzle for [rows][64 fp16] tiles (128B rows, 8 x 16B chunks)
__device__ __forceinline__ uint32_t swz(int row, int c) {
    return (uint32_t)(row * 128 + (((c) ^ (row & 7)) << 4));
}

// ---------------- RMSNorm -> fp16 ----------------
__global__ void rmsnorm_h(const float* __restrict__ x, const float* __restrict__ w,
                          __half* __restrict__ o)
{
    int row = blockIdx.x;
    int tid = threadIdx.x; // 256 threads x 4 floats
    const float4* xv = reinterpret_cast<const float4*>(x + (size_t)row * DD);
    const float4* wv = reinterpret_cast<const float4*>(w);
    float4 v = xv[tid];
    float ss = v.x*v.x + v.y*v.y + v.z*v.z + v.w*v.w;
    #pragma unroll
    for (int of = 16; of > 0; of >>= 1) ss += __shfl_xor_sync(0xffffffffu, ss, of);
    __shared__ float red[8];
    __shared__ float s_scale;
    if ((tid & 31) == 0) red[tid >> 5] = ss;
    __syncthreads();
    if (tid == 0) {
        float t = 0.f;
        #pragma unroll
        for (int i = 0; i < 8; i++) t += red[i];
        s_scale = rsqrtf(t / (float)DD + 1e-6f);
    }
    __syncthreads();
    float s = s_scale;
    float4 w4 = wv[tid];
    __half2* ov = reinterpret_cast<__half2*>(o + (size_t)row * DD);
    ov[tid*2]   = __floats2half2_rn(v.x*s*w4.x, v.y*s*w4.y);
    ov[tid*2+1] = __floats2half2_rn(v.z*s*w4.z, v.w*s*w4.w);
}

// ---------------- single fused weight/bias packing kernel ----------------
// block ranges (32x32 transpose tiles, block=(32,8)):
//  [0,1024)      wf  -> wgt[0]          (N=1024, Nsrc=1024, K=1024)
//  [1024,3072)   wi,wg ilv -> wgt+1024K (N=2048, Nsrc=1024, K=1024)
//  [3072,4096)   wo  -> wgt+3072K       (N=1024, Nsrc=1024, K=1024)
//  [4096,12288)  wfc,wfa ilv -> wff     (N=8192, Nsrc=4096, K=1024)
//  [12288,16384) wou -> wout            (N=1024, Nsrc=1024, K=4096)
//  [16384,16416) bias packing
__global__ void pack_all(const float* __restrict__ wf,  const float* __restrict__ wi,
                         const float* __restrict__ wg,  const float* __restrict__ wo,
                         const float* __restrict__ wfc, const float* __restrict__ wfa,
                         const float* __restrict__ wou,
                         const float* __restrict__ bf,  const float* __restrict__ bi,
                         const float* __restrict__ bg,  const float* __restrict__ bo,
                         const float* __restrict__ bfc, const float* __restrict__ bfa,
                         __half* __restrict__ WGT, __half* __restrict__ WFF,
                         __half* __restrict__ WOUT,
                         float* __restrict__ BG, float* __restrict__ BFF)
{
    int bid = blockIdx.x;
    int tx = threadIdx.x, ty = threadIdx.y;

    if (bid >= 16384) { // bias pack: 32 blocks x 256 threads = 8192
        int n = (bid - 16384) * 256 + ty * 32 + tx;
        if (n < 4 * DD) {
            float v;
            if (n < DD)            v = bf[n];
            else if (n < 3 * DD) { int t = n - DD; v = (t & 1) ? bg[t >> 1] : bi[t >> 1]; }
            else                   v = bo[n - 3 * DD];
            BG[n] = v;
        }
        BFF[n] = (n & 1) ? bfa[n >> 1] : bfc[n >> 1];
        return;
    }

    const float *S0, *S1; __half* T; int Kd, Ns, bx, by; bool pair;
    if (bid < 1024)       { S0 = wf;  S1 = nullptr; T = WGT;             Kd = DD;   Ns = DD;   pair = false; int l = bid;          bx = l % 32;  by = l / 32; }
    else if (bid < 3072)  { S0 = wi;  S1 = wg;      T = WGT + 1024 * DD; Kd = DD;   Ns = DD;   pair = true;  int l = bid - 1024;   bx = l % 64;  by = l / 64; }
    else if (bid < 4096)  { S0 = wo;  S1 = nullptr; T = WGT + 3072 * DD; Kd = DD;   Ns = DD;   pair = false; int l = bid - 3072;   bx = l % 32;  by = l / 32; }
    else if (bid < 12288) { S0 = wfc; S1 = wfa;     T = WFF;             Kd = DD;   Ns = DFF_; pair = true;  int l = bid - 4096;   bx = l % 256; by = l / 256; }
    else                  { S0 = wou; S1 = nullptr; T = WOUT;            Kd = DFF_; Ns = DD;   pair = false; int l = bid - 12288;  bx = l % 32;  by = l / 32; }

    __shared__ float t[32][33];
    int n0 = bx * 32, k0 = by * 32;
    const float* S = S0; int col = n0 + tx;
    if (pair) { S = ((n0 + tx) & 1) ? S1 : S0; col = (n0 + tx) >> 1; }
    #pragma unroll
    for (int i = 0; i < 32; i += 8)
        t[ty + i][tx] = S[(size_t)(k0 + ty + i) * Ns + col];
    __syncthreads();
    #pragma unroll
    for (int i = 0; i < 32; i += 8)
        T[(size_t)(n0 + ty + i) * Kd + k0 + tx] = __float2half_rn(t[tx][ty + i]);
}

// ---------------- pipelined HMMA GEMM: 256 threads, 2 CTAs/SM ----------------
// C[M,N] = ACT(A @ B'^T + bias)  A fp16 [M,K] row-major, B' fp16 [N,K] row-major
// ACT 4: v+aux -> C (down-proj, fp32 out)
// ACT 5: gates, N=4096 layout [f | i,g ilv | o]: a->C fp32, bv->C1h fp16, o->C2h fp16
// ACT 6: fused FFN-up, N=8192 ilv (fc,fca): hff=fc*silu(fca) -> Ch fp16
constexpr int BM = 128, BN = 128, BK = 64, STAGES = 3, NT = 256;
constexpr int ASTG = BM * BK * 2;     // 16 KB
constexpr int BSTG = BN * BK * 2;     // 16 KB
constexpr int STG  = ASTG + BSTG;     // 32 KB
constexpr int GSMEM = STAGES * STG;   // 96 KB -> 2 CTAs/SM

template<int ACT>
__global__ __launch_bounds__(NT, 2) void tc_gemm(
    const __half* __restrict__ A, const __half* __restrict__ Bw,
    const float* __restrict__ bias, const float* __restrict__ aux,
    float* __restrict__ C, __half* __restrict__ Ch,
    __half* __restrict__ C1h, __half* __restrict__ C2h,
    int M, int N, int K)
{
    extern __shared__ __align__(128) char smem[];
    uint32_t su = smem_to_u32(smem);
    int tid = threadIdx.x, wid = tid >> 5, lane = tid & 31;

    // supertile raster (8 m-tiles per group) for L2 reuse
    int tn = N / BN;
    int per = 8 * tn, grp = blockIdx.x / per, rr = blockIdx.x % per;
    int m0 = (grp * 8 + (rr % 8)) * BM;
    int n0 = (rr / 8) * BN;

    const __half* Ab = A  + (size_t)m0 * K;
    const __half* Bb = Bw + (size_t)n0 * K;

    // cp.async offsets: A 4 chunks/thread, B 4 chunks/thread (16B chunks)
    uint32_t sAo[4], gAo[4];
    #pragma unroll
    for (int j = 0; j < 4; j++) {
        int idx = tid + j * NT, r = idx >> 3, c = idx & 7;
        sAo[j] = swz(r, c); gAo[j] = (uint32_t)(r * K + c * 8);
    }

    // warp layout: 2 (m) x 4 (n); warp tile 64x32
    int wm = (wid & 1) * 64, wn = (wid >> 1) * 32;
    int rA128[4], rA7[4], rB128[2], rB7[2];
    int cA = lane >> 4;           // 0..1
    int cB = (lane >> 3) & 1;     // 0..1
    #pragma unroll
    for (int i = 0; i < 4; i++) {
        int ra = wm + i * 16 + (lane & 15);
        rA128[i] = ra * 128; rA7[i] = ra & 7;
    }
    #pragma unroll
    for (int p = 0; p < 2; p++) {
        int rb = wn + p * 16 + (lane & 7) + ((lane >> 4) << 3);
        rB128[p] = rb * 128; rB7[p] = rb & 7;
    }

    float acc[4][4][4];
    #pragma unroll
    for (int i = 0; i < 4; i++)
        #pragma unroll
        for (int j = 0; j < 4; j++)
            #pragma unroll
            for (int q = 0; q < 4; q++) acc[i][j][q] = 0.f;

    const int NK = K / BK;

    #pragma unroll
    for (int s = 0; s < STAGES - 1; s++) {
        uint32_t sA = su + s * STG, sB = sA + ASTG;
        int k0 = s * BK;
        #pragma unroll
        for (int j = 0; j < 4; j++) {
            cp_async16(sA + sAo[j], Ab + gAo[j] + k0);
            cp_async16(sB + sAo[j], Bb + gAo[j] + k0);
        }
        cp_commit();
    }

    int cs = 0, ls = STAGES - 1;
    for (int kt = 0; kt < NK; kt++) {
        asm volatile("cp.async.wait_group %0;" :: "n"(STAGES - 2) : "memory");
        __syncthreads();

        int lt = kt + STAGES - 1;
        if (lt < NK) {
            uint32_t sA = su + ls * STG, sB = sA + ASTG;
            int k0 = lt * BK;
            #pragma unroll
            for (int j = 0; j < 4; j++) {
                cp_async16(sA + sAo[j], Ab + gAo[j] + k0);
                cp_async16(sB + sAo[j], Bb + gAo[j] + k0);
            }
        }
        cp_commit();
        if (++ls == STAGES) ls = 0;

        uint32_t sA = su + cs * STG, sB = sA + ASTG;
        if (++cs == STAGES) cs = 0;
        #pragma unroll
        for (int kk = 0; kk < 4; kk++) {
            uint32_t a[4][4], b[2][4];
            #pragma unroll
            for (int i = 0; i < 4; i++)
                ldsm4(a[i], sA + rA128[i] + (((kk * 2 + cA) ^ rA7[i]) << 4));
            #pragma unroll
            for (int p = 0; p < 2; p++)
                ldsm4(b[p], sB + rB128[p] + (((kk * 2 + cB) ^ rB7[p]) << 4));
            #pragma unroll
            for (int p = 0; p < 2; p++)
                #pragma unroll
                for (int i = 0; i < 4; i++) {
                    mma_f16(acc[i][2*p],     a[i], b[p]);
                    mma_f16(acc[i][2*p + 1], a[i], b[p] + 2);
                }
        }
    }

    // ---- fused epilogue ----
    #pragma unroll
    for (int i = 0; i < 4; i++) {
        int r0 = m0 + wm + i * 16 + (lane >> 2);
        #pragma unroll
        for (int j = 0; j < 4; j++) {
            int c0 = n0 + wn + j * 8 + (lane & 3) * 2;
            float b0 = bias[c0], b1 = bias[c0 + 1];
            #pragma unroll
            for (int h = 0; h < 2; h++) {
                int r = r0 + h * 8;
                float v0 = acc[i][j][2*h]     + b0;
                float v1 = acc[i][j][2*h + 1] + b1;
                if (ACT == 4) {
                    size_t idx = (size_t)r * N + c0;
                    float2 au = *reinterpret_cast<const float2*>(&aux[idx]);
                    *reinterpret_cast<float2*>(&C[idx]) = make_float2(v0 + au.x, v1 + au.y);
                } else if (ACT == 5) {
                    if (c0 < 1024) {
                        *reinterpret_cast<float2*>(&C[(size_t)r * DD + c0]) =
                            make_float2(sigmoidf_(v0), sigmoidf_(v1));
                    } else if (c0 < 3072) {
                        C1h[(size_t)r * DD + ((c0 - 1024) >> 1)] =
                            __float2half_rn(tanhf(v0) * sigmoidf_(v1));
                    } else {
                        *reinterpret_cast<__half2*>(&C2h[(size_t)r * DD + (c0 - 3072)]) =
                            __floats2half2_rn(sigmoidf_(v0), sigmoidf_(v1));
                    }
                } else if (ACT == 6) {
                    Ch[(size_t)r * DFF_ + (c0 >> 1)] =
                        __float2half_rn(v0 * (v1 * sigmoidf_(v1)));
                }
            }
        }
    }
}

// ---------------- chunked linear-recurrence scan (2 d's per thread) ----------------
__global__ void scan_pass1(const float* __restrict__ aG, const __half* __restrict__ bVh,
                           float* __restrict__ Pb, float* __restrict__ Hb)
{
    int g = blockIdx.x * blockDim.x + threadIdx.x;    // BB*NCH*DD/2 threads
    int d2 = g & (DD/2 - 1);
    int c  = (g >> 9) & (NCH - 1);
    int b  = g >> 14;
    size_t base = ((size_t)b * LL + (size_t)c * CHUNK) * DD + d2 * 2;
    float2 P = make_float2(1.f, 1.f), hh = make_float2(0.f, 0.f);
    #pragma unroll 4
    for (int t = 0; t < CHUNK; t++) {
        size_t idx = base + (size_t)t * DD;
        float2 a  = *reinterpret_cast<const float2*>(aG + idx);
        float2 bv = __half22float2(*reinterpret_cast<const __half2*>(bVh + idx));
        P.x *= a.x; P.y *= a.y;
        hh.x = fmaf(a.x, hh.x, bv.x);
        hh.y = fmaf(a.y, hh.y, bv.y);
    }
    *reinterpret_cast<float2*>(Pb + (size_t)g * 2) = P;
    *reinterpret_cast<float2*>(Hb + (size_t)g * 2) = hh;
}

__global__ void scan_pass2(const float* __restrict__ Pb, const float* __restrict__ Hb,
                           const float* __restrict__ h0, float* __restrict__ Ib)
{
    int g = blockIdx.x * blockDim.x + threadIdx.x;   // B*D threads
    int d = g & (DD - 1);
    int b = g >> 10;
    float h = h0[d];
    #pragma unroll
    for (int c = 0; c < NCH; c++) {
        int j = (b * NCH + c) * DD + d;
        Ib[j] = h;
        h = fmaf(Pb[j], h, Hb[j]);
    }
}

__global__ void scan_pass3(const float* __restrict__ aG, const __half* __restrict__ bVh,
                           const __half* __restrict__ oSh, const float* __restrict__ x,
                           const float* __restrict__ Ib, float* __restrict__ x1)
{
    int g = blockIdx.x * blockDim.x + threadIdx.x;    // BB*NCH*DD/2 threads
    int d2 = g & (DD/2 - 1);
    int c  = (g >> 9) & (NCH - 1);
    int b  = g >> 14;
    size_t base = ((size_t)b * LL + (size_t)c * CHUNK) * DD + d2 * 2;
    float2 hh = *reinterpret_cast<const float2*>(Ib + (size_t)g * 2);
    #pragma unroll 4
    for (int t = 0; t < CHUNK; t++) {
        size_t idx = base + (size_t)t * DD;
        float2 a  = *reinterpret_cast<const float2*>(aG + idx);
        float2 bv = __half22float2(*reinterpret_cast<const __half2*>(bVh + idx));
        float2 os = __half22float2(*reinterpret_cast<const __half2*>(oSh + idx));
        float2 xv = *reinterpret_cast<const float2*>(x + idx);
        hh.x = fmaf(a.x, hh.x, bv.x);
        hh.y = fmaf(a.y, hh.y, bv.y);
        float2 r;
        r.x = tanhf(hh.x) * os.x + xv.x;
        r.y = tanhf(hh.y) * os.y + xv.y;
        *reinterpret_cast<float2*>(x1 + idx) = r;
    }
}

// ---------------- launcher ----------------
extern "C" void kernel_launch(void* const* d_in, const int* in_sizes, int n_in,
                              void* d_out, int out_size)
{
    (void)in_sizes; (void)n_in; (void)out_size;
    const float* x   = (const float*)d_in[0];
    const float* wf  = (const float*)d_in[1];
    const float* bf_ = (const float*)d_in[2];
    const float* wi  = (const float*)d_in[3];
    const float* bi_ = (const float*)d_in[4];
    const float* wg  = (const float*)d_in[5];
    const float* bg_ = (const float*)d_in[6];
    const float* wo  = (const float*)d_in[7];
    const float* bo_ = (const float*)d_in[8];
    const float* h0  = (const float*)d_in[9];
    const float* n1w = (const float*)d_in[10];
    const float* n2w = (const float*)d_in[11];
    const float* wfc = (const float*)d_in[12];
    const float* bfc = (const float*)d_in[13];
    const float* wfa = (const float*)d_in[14];
    const float* bfa = (const float*)d_in[15];
    const float* wou = (const float*)d_in[16];
    const float* bou = (const float*)d_in[17];
    float* out = (float*)d_out;

    float *ga, *x1, *P, *H, *I, *bg4, *bff;
    cudaGetSymbolAddress((void**)&ga,  g_a);
    cudaGetSymbolAddress((void**)&x1,  g_x1);
    cudaGetSymbolAddress((void**)&P,   g_P);
    cudaGetSymbolAddress((void**)&H,   g_H);
    cudaGetSymbolAddress((void**)&I,   g_I);
    cudaGetSymbolAddress((void**)&bg4, g_bg);
    cudaGetSymbolAddress((void**)&bff, g_bff);

    __half *gbvh, *goh, *xn, *xn2, *hff, *wgt, *wff, *wout_;
    cudaGetSymbolAddress((void**)&gbvh, g_bvh);
    cudaGetSymbolAddress((void**)&goh,  g_oh);
    cudaGetSymbolAddress((void**)&xn,   g_xn);
    cudaGetSymbolAddress((void**)&xn2,  g_xn2);
    cudaGetSymbolAddress((void**)&hff,  g_hff);
    cudaGetSymbolAddress((void**)&wgt,  g_wgt);
    cudaGetSymbolAddress((void**)&wff,  g_wff);
    cudaGetSymbolAddress((void**)&wout_,g_wout);

    cudaFuncSetAttribute(tc_gemm<4>, cudaFuncAttributeMaxDynamicSharedMemorySize, GSMEM);
    cudaFuncSetAttribute(tc_gemm<5>, cudaFuncAttributeMaxDynamicSharedMemorySize, GSMEM);
    cudaFuncSetAttribute(tc_gemm<6>, cudaFuncAttributeMaxDynamicSharedMemorySize, GSMEM);

    // 0) fused weight/bias packing (single launch)
    pack_all<<<16416, dim3(32, 8)>>>(wf, wi, wg, wo, wfc, wfa, wou,
                                     bf_, bi_, bg_, bo_, bfc, bfa,
                                     wgt, wff, wout_, bg4, bff);

    // 1) norm1 -> fp16
    rmsnorm_h<<<MM, 256>>>(x, n1w, xn);

    // 2) gate GEMM (N=4096) -> a (fp32), bv (fp16), o (fp16)
    int gGates = (MM/BM) * ((4*DD)/BN);
    tc_gemm<5><<<gGates, NT, GSMEM>>>(xn, wgt, bg4, nullptr, ga, nullptr, gbvh, goh,
                                      MM, 4*DD, DD);

    // 3) scan + output gate + residual -> x1
    scan_pass1<<<(BB*NCH*DD/2)/256, 256>>>(ga, gbvh, P, H);
    scan_pass2<<<(BB*DD)/256, 256>>>(P, H, h0, I);
    scan_pass3<<<(BB*NCH*DD/2)/256, 256>>>(ga, gbvh, goh, x, I, x1);

    // 4) norm2 -> fp16
    rmsnorm_h<<<MM, 256>>>(x1, n2w, xn2);

    // 5) fused FFN-up (N=8192, interleaved) -> hff fp16
    int gFF = (MM/BM) * ((2*DFF_)/BN);
    tc_gemm<6><<<gFF, NT, GSMEM>>>(xn2, wff, bff, nullptr, nullptr, hff, nullptr, nullptr,
                                   MM, 2*DFF_, DD);

    // 6) down-proj + b_out + x1 -> d_out
    int gOut = (MM/BM) * (DD/BN);
    tc_gemm<4><<<gOut, NT, GSMEM>>>(hff, wout_, bou, x1, out, nullptr, nullptr, nullptr,
                                    MM, DD, DFF_);
}

// round 9
// speedup vs baseline: 10.4046x; 1.0211x over previous
#include <cuda_runtime.h>
#include <cuda_fp16.h>
#include <cstdint>

// Problem shape (fixed)
#define BB   4
#define LL   4096
#define DD   1024
#define DFF_ 4096
#define MM   (BB*LL)        // 16384 token rows
#define NCH  64
#define CHUNK 64

// ---------------- scratch (device globals: allocation-free) ----------------
__device__ float  g_a  [MM*DD];     // sigmoid(forget)  (fp32: 1/(1-a) error amplification)
__device__ __half g_bvh[MM*DD];     // tanh(input)*sigmoid(igate)
__device__ __half g_oh [MM*DD];     // sigmoid(ogate)
__device__ float  g_x1 [MM*DD];
__device__ float  g_P  [BB*NCH*DD];
__device__ float  g_H  [BB*NCH*DD];
__device__ float  g_I  [BB*NCH*DD];
__device__ float  g_bg [4*DD];      // gate bias, layout [f | i,g interleaved | o]
__device__ float  g_bff[2*DFF_];    // ffn bias, interleaved [bfc_j, bfa_j]

__device__ __half g_xn [MM*DD];
__device__ __half g_xn2[MM*DD];
__device__ __half g_hff[MM*DFF_];
__device__ __half g_wgt[4*DD*DD];   // [4096,1024] K-major, rows [f | i,g ilv | o]
__device__ __half g_wff[2*DFF_*DD]; // [8192,1024] K-major, rows interleaved (fc,fca)
__device__ __half g_wout[DD*DFF_];  // [1024,4096] K-major

// ---------------- asm helpers ----------------
__device__ __forceinline__ uint32_t smem_to_u32(const void* p) {
    uint32_t a;
    asm("{ .reg .u64 t; cvta.to.shared.u64 t, %1; cvt.u32.u64 %0, t; }" : "=r"(a) : "l"(p));
    return a;
}
__device__ __forceinline__ void cp_async16(uint32_t sa, const void* gp) {
    asm volatile("cp.async.cg.shared.global [%0], [%1], 16;" :: "r"(sa), "l"(gp));
}
__device__ __forceinline__ void cp_commit() {
    asm volatile("cp.async.commit_group;" ::: "memory");
}
__device__ __forceinline__ void ldsm4(uint32_t* d, uint32_t addr) {
    asm volatile("ldmatrix.sync.aligned.m8n8.x4.shared.b16 {%0,%1,%2,%3}, [%4];"
        : "=r"(d[0]), "=r"(d[1]), "=r"(d[2]), "=r"(d[3]) : "r"(addr));
}
__device__ __forceinline__ void mma_f16(float* c, const uint32_t* a, const uint32_t* b) {
    asm volatile("mma.sync.aligned.m16n8k16.row.col.f32.f16.f16.f32 "
        "{%0,%1,%2,%3}, {%4,%5,%6,%7}, {%8,%9}, {%0,%1,%2,%3};"
        : "+f"(c[0]), "+f"(c[1]), "+f"(c[2]), "+f"(c[3])
        : "r"(a[0]), "r"(a[1]), "r"(a[2]), "r"(a[3]), "r"(b[0]), "r"(b[1]));
}
__device__ __forceinline__ float sigmoidf_(float v) { return 1.f / (1.f + expf(-v)); }

// SW128-style swizzle for [rows][64 fp16] tiles (128B rows, 8 x 16B chunks)
__device__ __forceinline__ uint32_t swz(int row, int c) {
    return (uint32_t)(row * 128 + (((c) ^ (row & 7)) << 4));
}

// ---------------- RMSNorm -> fp16 ----------------
__global__ void rmsnorm_h(const float* __restrict__ x, const float* __restrict__ w,
                          __half* __restrict__ o)
{
    int row = blockIdx.x;
    int tid = threadIdx.x; // 256 threads x 4 floats
    const float4* xv = reinterpret_cast<const float4*>(x + (size_t)row * DD);
    const float4* wv = reinterpret_cast<const float4*>(w);
    float4 v = xv[tid];
    float ss = v.x*v.x + v.y*v.y + v.z*v.z + v.w*v.w;
    #pragma unroll
    for (int of = 16; of > 0; of >>= 1) ss += __shfl_xor_sync(0xffffffffu, ss, of);
    __shared__ float red[8];
    __shared__ float s_scale;
    if ((tid & 31) == 0) red[tid >> 5] = ss;
    __syncthreads();
    if (tid == 0) {
        float t = 0.f;
        #pragma unroll
        for (int i = 0; i < 8; i++) t += red[i];
        s_scale = rsqrtf(t / (float)DD + 1e-6f);
    }
    __syncthreads();
    float s = s_scale;
    float4 w4 = wv[tid];
    __half2* ov = reinterpret_cast<__half2*>(o + (size_t)row * DD);
    ov[tid*2]   = __floats2half2_rn(v.x*s*w4.x, v.y*s*w4.y);
    ov[tid*2+1] = __floats2half2_rn(v.z*s*w4.z, v.w*s*w4.w);
}

// ---------------- single fused weight/bias packing kernel ----------------
__global__ void pack_all(const float* __restrict__ wf,  const float* __restrict__ wi,
                         const float* __restrict__ wg,  const float* __restrict__ wo,
                         const float* __restrict__ wfc, const float* __restrict__ wfa,
                         const float* __restrict__ wou,
                         const float* __restrict__ bf,  const float* __restrict__ bi,
                         const float* __restrict__ bg,  const float* __restrict__ bo,
                         const float* __restrict__ bfc, const float* __restrict__ bfa,
                         __half* __restrict__ WGT, __half* __restrict__ WFF,
                         __half* __restrict__ WOUT,
                         float* __restrict__ BG, float* __restrict__ BFF)
{
    int bid = blockIdx.x;
    int tx = threadIdx.x, ty = threadIdx.y;

    if (bid >= 16384) { // bias pack: 32 blocks x 256 threads = 8192
        int n = (bid - 16384) * 256 + ty * 32 + tx;
        if (n < 4 * DD) {
            float v;
            if (n < DD)            v = bf[n];
            else if (n < 3 * DD) { int t = n - DD; v = (t & 1) ? bg[t >> 1] : bi[t >> 1]; }
            else                   v = bo[n - 3 * DD];
            BG[n] = v;
        }
        BFF[n] = (n & 1) ? bfa[n >> 1] : bfc[n >> 1];
        return;
    }

    const float *S0, *S1; __half* T; int Kd, Ns, bx, by; bool pair;
    if (bid < 1024)       { S0 = wf;  S1 = nullptr; T = WGT;             Kd = DD;   Ns = DD;   pair = false; int l = bid;          bx = l % 32;  by = l / 32; }
    else if (bid < 3072)  { S0 = wi;  S1 = wg;      T = WGT + 1024 * DD; Kd = DD;   Ns = DD;   pair = true;  int l = bid - 1024;   bx = l % 64;  by = l / 64; }
    else if (bid < 4096)  { S0 = wo;  S1 = nullptr; T = WGT + 3072 * DD; Kd = DD;   Ns = DD;   pair = false; int l = bid - 3072;   bx = l % 32;  by = l / 32; }
    else if (bid < 12288) { S0 = wfc; S1 = wfa;     T = WFF;             Kd = DD;   Ns = DFF_; pair = true;  int l = bid - 4096;   bx = l % 256; by = l / 256; }
    else                  { S0 = wou; S1 = nullptr; T = WOUT;            Kd = DFF_; Ns = DD;   pair = false; int l = bid - 12288;  bx = l % 32;  by = l / 32; }

    __shared__ float t[32][33];
    int n0 = bx * 32, k0 = by * 32;
    const float* S = S0; int col = n0 + tx;
    if (pair) { S = ((n0 + tx) & 1) ? S1 : S0; col = (n0 + tx) >> 1; }
    #pragma unroll
    for (int i = 0; i < 32; i += 8)
        t[ty + i][tx] = S[(size_t)(k0 + ty + i) * Ns + col];
    __syncthreads();
    #pragma unroll
    for (int i = 0; i < 32; i += 8)
        T[(size_t)(n0 + ty + i) * Kd + k0 + tx] = __float2half_rn(t[tx][ty + i]);
}

// ---------------- pipelined HMMA GEMM: 256 threads, 2 CTAs/SM ----------------
// C[M,N] = ACT(A @ B'^T + bias)  A fp16 [M,K] row-major, B' fp16 [N,K] row-major
// ACT 4: v+aux -> C (down-proj, fp32 out)
// ACT 5: gates, N=4096 layout [f | i,g ilv | o]: a->C fp32, bv->C1h fp16, o->C2h fp16
// ACT 6: fused FFN-up, N=8192 ilv (fc,fca): hff=fc*silu(fca) -> Ch fp16
constexpr int BM = 128, BN = 128, BK = 64, STAGES = 3, NT = 256;
constexpr int ASTG = BM * BK * 2;     // 16 KB
constexpr int BSTG = BN * BK * 2;     // 16 KB
constexpr int STG  = ASTG + BSTG;     // 32 KB
constexpr int GSMEM = STAGES * STG;   // 96 KB -> 2 CTAs/SM

template<int ACT>
__global__ __launch_bounds__(NT, 2) void tc_gemm(
    const __half* __restrict__ A, const __half* __restrict__ Bw,
    const float* __restrict__ bias, const float* __restrict__ aux,
    float* __restrict__ C, __half* __restrict__ Ch,
    __half* __restrict__ C1h, __half* __restrict__ C2h,
    int M, int N, int K)
{
    extern __shared__ __align__(128) char smem[];
    uint32_t su = smem_to_u32(smem);
    int tid = threadIdx.x, wid = tid >> 5, lane = tid & 31;

    // supertile raster (8 m-tiles per group) for L2 reuse
    int tn = N / BN;
    int per = 8 * tn, grp = blockIdx.x / per, rr = blockIdx.x % per;
    int m0 = (grp * 8 + (rr % 8)) * BM;
    int n0 = (rr / 8) * BN;

    const __half* Ab = A  + (size_t)m0 * K;
    const __half* Bb = Bw + (size_t)n0 * K;

    // cp.async offsets: A 4 chunks/thread, B 4 chunks/thread (16B chunks)
    uint32_t sAo[4], gAo[4];
    #pragma unroll
    for (int j = 0; j < 4; j++) {
        int idx = tid + j * NT, r = idx >> 3, c = idx & 7;
        sAo[j] = swz(r, c); gAo[j] = (uint32_t)(r * K + c * 8);
    }

    // warp layout: 2 (m) x 4 (n); warp tile 64x32
    int wm = (wid & 1) * 64, wn = (wid >> 1) * 32;
    int rA128[4], rA7[4], rB128[2], rB7[2];
    int cA = lane >> 4;           // 0..1
    int cB = (lane >> 3) & 1;     // 0..1
    #pragma unroll
    for (int i = 0; i < 4; i++) {
        int ra = wm + i * 16 + (lane & 15);
        rA128[i] = ra * 128; rA7[i] = ra & 7;
    }
    #pragma unroll
    for (int p = 0; p < 2; p++) {
        int rb = wn + p * 16 + (lane & 7) + ((lane >> 4) << 3);
        rB128[p] = rb * 128; rB7[p] = rb & 7;
    }

    float acc[4][4][4];
    #pragma unroll
    for (int i = 0; i < 4; i++)
        #pragma unroll
        for (int j = 0; j < 4; j++)
            #pragma unroll
            for (int q = 0; q < 4; q++) acc[i][j][q] = 0.f;

    const int NK = K / BK;

    #pragma unroll
    for (int s = 0; s < STAGES - 1; s++) {
        uint32_t sA = su + s * STG, sB = sA + ASTG;
        int k0 = s * BK;
        #pragma unroll
        for (int j = 0; j < 4; j++) {
            cp_async16(sA + sAo[j], Ab + gAo[j] + k0);
            cp_async16(sB + sAo[j], Bb + gAo[j] + k0);
        }
        cp_commit();
    }

    int cs = 0, ls = STAGES - 1;
    for (int kt = 0; kt < NK; kt++) {
        asm volatile("cp.async.wait_group %0;" :: "n"(STAGES - 2) : "memory");
        __syncthreads();

        int lt = kt + STAGES - 1;
        if (lt < NK) {
            uint32_t sA = su + ls * STG, sB = sA + ASTG;
            int k0 = lt * BK;
            #pragma unroll
            for (int j = 0; j < 4; j++) {
                cp_async16(sA + sAo[j], Ab + gAo[j] + k0);
                cp_async16(sB + sAo[j], Bb + gAo[j] + k0);
            }
        }
        cp_commit();
        if (++ls == STAGES) ls = 0;

        uint32_t sA = su + cs * STG, sB = sA + ASTG;
        if (++cs == STAGES) cs = 0;
        #pragma unroll
        for (int kk = 0; kk < 4; kk++) {
            uint32_t a[4][4], b[2][4];
            #pragma unroll
            for (int i = 0; i < 4; i++)
                ldsm4(a[i], sA + rA128[i] + (((kk * 2 + cA) ^ rA7[i]) << 4));
            #pragma unroll
            for (int p = 0; p < 2; p++)
                ldsm4(b[p], sB + rB128[p] + (((kk * 2 + cB) ^ rB7[p]) << 4));
            #pragma unroll
            for (int p = 0; p < 2; p++)
                #pragma unroll
                for (int i = 0; i < 4; i++) {
                    mma_f16(acc[i][2*p],     a[i], b[p]);
                    mma_f16(acc[i][2*p + 1], a[i], b[p] + 2);
                }
        }
    }

    // ---- fused epilogue ----
    #pragma unroll
    for (int i = 0; i < 4; i++) {
        int r0 = m0 + wm + i * 16 + (lane >> 2);
        #pragma unroll
        for (int j = 0; j < 4; j++) {
            int c0 = n0 + wn + j * 8 + (lane & 3) * 2;
            float b0 = bias[c0], b1 = bias[c0 + 1];
            #pragma unroll
            for (int h = 0; h < 2; h++) {
                int r = r0 + h * 8;
                float v0 = acc[i][j][2*h]     + b0;
                float v1 = acc[i][j][2*h + 1] + b1;
                if (ACT == 4) {
                    size_t idx = (size_t)r * N + c0;
                    float2 au = *reinterpret_cast<const float2*>(&aux[idx]);
                    *reinterpret_cast<float2*>(&C[idx]) = make_float2(v0 + au.x, v1 + au.y);
                } else if (ACT == 5) {
                    if (c0 < 1024) {
                        *reinterpret_cast<float2*>(&C[(size_t)r * DD + c0]) =
                            make_float2(sigmoidf_(v0), sigmoidf_(v1));
                    } else if (c0 < 3072) {
                        C1h[(size_t)r * DD + ((c0 - 1024) >> 1)] =
                            __float2half_rn(tanhf(v0) * sigmoidf_(v1));
                    } else {
                        *reinterpret_cast<__half2*>(&C2h[(size_t)r * DD + (c0 - 3072)]) =
                            __floats2half2_rn(sigmoidf_(v0), sigmoidf_(v1));
                    }
                } else if (ACT == 6) {
                    Ch[(size_t)r * DFF_ + (c0 >> 1)] =
                        __float2half_rn(v0 * (v1 * sigmoidf_(v1)));
                }
            }
        }
    }
}

// ---------------- chunked linear-recurrence scan (2 d's per thread) ----------------
// NCH=64 chunks of 64 steps: 131072 threads in pass1/pass3 for memory-level parallelism
__global__ void scan_pass1(const float* __restrict__ aG, const __half* __restrict__ bVh,
                           float* __restrict__ Pb, float* __restrict__ Hb)
{
    int g = blockIdx.x * blockDim.x + threadIdx.x;    // BB*NCH*DD/2 threads
    int d2 = g & (DD/2 - 1);
    int c  = (g >> 9) & (NCH - 1);
    int b  = g >> 15;
    size_t base = ((size_t)b * LL + (size_t)c * CHUNK) * DD + d2 * 2;
    float2 P = make_float2(1.f, 1.f), hh = make_float2(0.f, 0.f);
    #pragma unroll 4
    for (int t = 0; t < CHUNK; t++) {
        size_t idx = base + (size_t)t * DD;
        float2 a  = *reinterpret_cast<const float2*>(aG + idx);
        float2 bv = __half22float2(*reinterpret_cast<const __half2*>(bVh + idx));
        P.x *= a.x; P.y *= a.y;
        hh.x = fmaf(a.x, hh.x, bv.x);
        hh.y = fmaf(a.y, hh.y, bv.y);
    }
    *reinterpret_cast<float2*>(Pb + (size_t)g * 2) = P;
    *reinterpret_cast<float2*>(Hb + (size_t)g * 2) = hh;
}

__global__ void scan_pass2(const float* __restrict__ Pb, const float* __restrict__ Hb,
                           const float* __restrict__ h0, float* __restrict__ Ib)
{
    int g = blockIdx.x * blockDim.x + threadIdx.x;   // B*D threads
    int d = g & (DD - 1);
    int b = g >> 10;
    float h = h0[d];
    #pragma unroll
    for (int c = 0; c < NCH; c++) {
        int j = (b * NCH + c) * DD + d;
        Ib[j] = h;
        h = fmaf(Pb[j], h, Hb[j]);
    }
}

__global__ void scan_pass3(const float* __restrict__ aG, const __half* __restrict__ bVh,
                           const __half* __restrict__ oSh, const float* __restrict__ x,
                           const float* __restrict__ Ib, float* __restrict__ x1)
{
    int g = blockIdx.x * blockDim.x + threadIdx.x;    // BB*NCH*DD/2 threads
    int d2 = g & (DD/2 - 1);
    int c  = (g >> 9) & (NCH - 1);
    int b  = g >> 15;
    size_t base = ((size_t)b * LL + (size_t)c * CHUNK) * DD + d2 * 2;
    float2 hh = *reinterpret_cast<const float2*>(Ib + (size_t)g * 2);
    #pragma unroll 4
    for (int t = 0; t < CHUNK; t++) {
        size_t idx = base + (size_t)t * DD;
        float2 a  = *reinterpret_cast<const float2*>(aG + idx);
        float2 bv = __half22float2(*reinterpret_cast<const __half2*>(bVh + idx));
        float2 os = __half22float2(*reinterpret_cast<const __half2*>(oSh + idx));
        float2 xv = *reinterpret_cast<const float2*>(x + idx);
        hh.x = fmaf(a.x, hh.x, bv.x);
        hh.y = fmaf(a.y, hh.y, bv.y);
        float2 r;
        r.x = tanhf(hh.x) * os.x + xv.x;
        r.y = tanhf(hh.y) * os.y + xv.y;
        *reinterpret_cast<float2*>(x1 + idx) = r;
    }
}

// ---------------- launcher ----------------
extern "C" void kernel_launch(void* const* d_in, const int* in_sizes, int n_in,
                              void* d_out, int out_size)
{
    (void)in_sizes; (void)n_in; (void)out_size;
    const float* x   = (const float*)d_in[0];
    const float* wf  = (const float*)d_in[1];
    const float* bf_ = (const float*)d_in[2];
    const float* wi  = (const float*)d_in[3];
    const float* bi_ = (const float*)d_in[4];
    const float* wg  = (const float*)d_in[5];
    const float* bg_ = (const float*)d_in[6];
    const float* wo  = (const float*)d_in[7];
    const float* bo_ = (const float*)d_in[8];
    const float* h0  = (const float*)d_in[9];
    const float* n1w = (const float*)d_in[10];
    const float* n2w = (const float*)d_in[11];
    const float* wfc = (const float*)d_in[12];
    const float* bfc = (const float*)d_in[13];
    const float* wfa = (const float*)d_in[14];
    const float* bfa = (const float*)d_in[15];
    const float* wou = (const float*)d_in[16];
    const float* bou = (const float*)d_in[17];
    float* out = (float*)d_out;

    float *ga, *x1, *P, *H, *I, *bg4, *bff;
    cudaGetSymbolAddress((void**)&ga,  g_a);
    cudaGetSymbolAddress((void**)&x1,  g_x1);
    cudaGetSymbolAddress((void**)&P,   g_P);
    cudaGetSymbolAddress((void**)&H,   g_H);
    cudaGetSymbolAddress((void**)&I,   g_I);
    cudaGetSymbolAddress((void**)&bg4, g_bg);
    cudaGetSymbolAddress((void**)&bff, g_bff);

    __half *gbvh, *goh, *xn, *xn2, *hff, *wgt, *wff, *wout_;
    cudaGetSymbolAddress((void**)&gbvh, g_bvh);
    cudaGetSymbolAddress((void**)&goh,  g_oh);
    cudaGetSymbolAddress((void**)&xn,   g_xn);
    cudaGetSymbolAddress((void**)&xn2,  g_xn2);
    cudaGetSymbolAddress((void**)&hff,  g_hff);
    cudaGetSymbolAddress((void**)&wgt,  g_wgt);
    cudaGetSymbolAddress((void**)&wff,  g_wff);
    cudaGetSymbolAddress((void**)&wout_,g_wout);

    cudaFuncSetAttribute(tc_gemm<4>, cudaFuncAttributeMaxDynamicSharedMemorySize, GSMEM);
    cudaFuncSetAttribute(tc_gemm<5>, cudaFuncAttributeMaxDynamicSharedMemorySize, GSMEM);
    cudaFuncSetAttribute(tc_gemm<6>, cudaFuncAttributeMaxDynamicSharedMemorySize, GSMEM);

    // 0) fused weight/bias packing (single launch)
    pack_all<<<16416, dim3(32, 8)>>>(wf, wi, wg, wo, wfc, wfa, wou,
                                     bf_, bi_, bg_, bo_, bfc, bfa,
                                     wgt, wff, wout_, bg4, bff);

    // 1) norm1 -> fp16
    rmsnorm_h<<<MM, 256>>>(x, n1w, xn);

    // 2) gate GEMM (N=4096) -> a (fp32), bv (fp16), o (fp16)
    int gGates = (MM/BM) * ((4*DD)/BN);
    tc_gemm<5><<<gGates, NT, GSMEM>>>(xn, wgt, bg4, nullptr, ga, nullptr, gbvh, goh,
                                      MM, 4*DD, DD);

    // 3) scan + output gate + residual -> x1
    scan_pass1<<<(BB*NCH*DD/2)/256, 256>>>(ga, gbvh, P, H);
    scan_pass2<<<(BB*DD)/256, 256>>>(P, H, h0, I);
    scan_pass3<<<(BB*NCH*DD/2)/256, 256>>>(ga, gbvh, goh, x, I, x1);

    // 4) norm2 -> fp16
    rmsnorm_h<<<MM, 256>>>(x1, n2w, xn2);

    // 5) fused FFN-up (N=8192, interleaved) -> hff fp16
    int gFF = (MM/BM) * ((2*DFF_)/BN);
    tc_gemm<6><<<gFF, NT, GSMEM>>>(xn2, wff, bff, nullptr, nullptr, hff, nullptr, nullptr,
                                   MM, 2*DFF_, DD);

    // 6) down-proj + b_out + x1 -> d_out
    int gOut = (MM/BM) * (DD/BN);
    tc_gemm<4><<<gOut, NT, GSMEM>>>(hff, wout_, bou, x1, out, nullptr, nullptr, nullptr,
                                    MM, DD, DFF_);
}

// round 10
// speedup vs baseline: 10.4486x; 1.0042x over previous
#include <cuda_runtime.h>
#include <cuda_fp16.h>
#include <cstdint>

// Problem shape (fixed)
#define BB   4
#define LL   4096
#define DD   1024
#define DFF_ 4096
#define MM   (BB*LL)        // 16384 token rows
#define NCH  128
#define CHUNK 32

// ---------------- scratch (device globals: allocation-free) ----------------
__device__ float  g_a  [MM*DD];     // sigmoid(forget)  (fp32: 1/(1-a) error amplification)
__device__ __half g_bvh[MM*DD];     // tanh(input)*sigmoid(igate)
__device__ __half g_oh [MM*DD];     // sigmoid(ogate)
__device__ float  g_x1 [MM*DD];
__device__ float  g_P  [BB*NCH*DD];
__device__ float  g_H  [BB*NCH*DD];
__device__ float  g_I  [BB*NCH*DD];
__device__ float  g_bg [4*DD];      // gate bias, layout [f | i,g interleaved | o]
__device__ float  g_bff[2*DFF_];    // ffn bias, interleaved [bfc_j, bfa_j]

__device__ __half g_xn [MM*DD];
__device__ __half g_xn2[MM*DD];
__device__ __half g_hff[MM*DFF_];
__device__ __half g_wgt[4*DD*DD];   // [4096,1024] K-major, rows [f | i,g ilv | o]
__device__ __half g_wff[2*DFF_*DD]; // [8192,1024] K-major, rows interleaved (fc,fca)
__device__ __half g_wout[DD*DFF_];  // [1024,4096] K-major

// ---------------- asm helpers ----------------
__device__ __forceinline__ uint32_t smem_to_u32(const void* p) {
    uint32_t a;
    asm("{ .reg .u64 t; cvta.to.shared.u64 t, %1; cvt.u32.u64 %0, t; }" : "=r"(a) : "l"(p));
    return a;
}
__device__ __forceinline__ void cp_async16(uint32_t sa, const void* gp) {
    asm volatile("cp.async.cg.shared.global [%0], [%1], 16;" :: "r"(sa), "l"(gp));
}
__device__ __forceinline__ void cp_commit() {
    asm volatile("cp.async.commit_group;" ::: "memory");
}
__device__ __forceinline__ void ldsm4(uint32_t* d, uint32_t addr) {
    asm volatile("ldmatrix.sync.aligned.m8n8.x4.shared.b16 {%0,%1,%2,%3}, [%4];"
        : "=r"(d[0]), "=r"(d[1]), "=r"(d[2]), "=r"(d[3]) : "r"(addr));
}
__device__ __forceinline__ void mma_f16(float* c, const uint32_t* a, const uint32_t* b) {
    asm volatile("mma.sync.aligned.m16n8k16.row.col.f32.f16.f16.f32 "
        "{%0,%1,%2,%3}, {%4,%5,%6,%7}, {%8,%9}, {%0,%1,%2,%3};"
        : "+f"(c[0]), "+f"(c[1]), "+f"(c[2]), "+f"(c[3])
        : "r"(a[0]), "r"(a[1]), "r"(a[2]), "r"(a[3]), "r"(b[0]), "r"(b[1]));
}
__device__ __forceinline__ float sigmoidf_(float v) { return 1.f / (1.f + expf(-v)); }

// SW128-style swizzle for [rows][64 fp16] tiles (128B rows, 8 x 16B chunks)
__device__ __forceinline__ uint32_t swz(int row, int c) {
    return (uint32_t)(row * 128 + (((c) ^ (row & 7)) << 4));
}

// ---------------- RMSNorm -> fp16 (used for norm1 only) ----------------
__global__ void rmsnorm_h(const float* __restrict__ x, const float* __restrict__ w,
                          __half* __restrict__ o)
{
    int row = blockIdx.x;
    int tid = threadIdx.x; // 256 threads x 4 floats
    const float4* xv = reinterpret_cast<const float4*>(x + (size_t)row * DD);
    const float4* wv = reinterpret_cast<const float4*>(w);
    float4 v = xv[tid];
    float ss = v.x*v.x + v.y*v.y + v.z*v.z + v.w*v.w;
    #pragma unroll
    for (int of = 16; of > 0; of >>= 1) ss += __shfl_xor_sync(0xffffffffu, ss, of);
    __shared__ float red[8];
    __shared__ float s_scale;
    if ((tid & 31) == 0) red[tid >> 5] = ss;
    __syncthreads();
    if (tid == 0) {
        float t = 0.f;
        #pragma unroll
        for (int i = 0; i < 8; i++) t += red[i];
        s_scale = rsqrtf(t / (float)DD + 1e-6f);
    }
    __syncthreads();
    float s = s_scale;
    float4 w4 = wv[tid];
    __half2* ov = reinterpret_cast<__half2*>(o + (size_t)row * DD);
    ov[tid*2]   = __floats2half2_rn(v.x*s*w4.x, v.y*s*w4.y);
    ov[tid*2+1] = __floats2half2_rn(v.z*s*w4.z, v.w*s*w4.w);
}

// ---------------- single fused weight/bias packing kernel ----------------
__global__ void pack_all(const float* __restrict__ wf,  const float* __restrict__ wi,
                         const float* __restrict__ wg,  const float* __restrict__ wo,
                         const float* __restrict__ wfc, const float* __restrict__ wfa,
                         const float* __restrict__ wou,
                         const float* __restrict__ bf,  const float* __restrict__ bi,
                         const float* __restrict__ bg,  const float* __restrict__ bo,
                         const float* __restrict__ bfc, const float* __restrict__ bfa,
                         __half* __restrict__ WGT, __half* __restrict__ WFF,
                         __half* __restrict__ WOUT,
                         float* __restrict__ BG, float* __restrict__ BFF)
{
    int bid = blockIdx.x;
    int tx = threadIdx.x, ty = threadIdx.y;

    if (bid >= 16384) { // bias pack: 32 blocks x 256 threads = 8192
        int n = (bid - 16384) * 256 + ty * 32 + tx;
        if (n < 4 * DD) {
            float v;
            if (n < DD)            v = bf[n];
            else if (n < 3 * DD) { int t = n - DD; v = (t & 1) ? bg[t >> 1] : bi[t >> 1]; }
            else                   v = bo[n - 3 * DD];
            BG[n] = v;
        }
        BFF[n] = (n & 1) ? bfa[n >> 1] : bfc[n >> 1];
        return;
    }

    const float *S0, *S1; __half* T; int Kd, Ns, bx, by; bool pair;
    if (bid < 1024)       { S0 = wf;  S1 = nullptr; T = WGT;             Kd = DD;   Ns = DD;   pair = false; int l = bid;          bx = l % 32;  by = l / 32; }
    else if (bid < 3072)  { S0 = wi;  S1 = wg;      T = WGT + 1024 * DD; Kd = DD;   Ns = DD;   pair = true;  int l = bid - 1024;   bx = l % 64;  by = l / 64; }
    else if (bid < 4096)  { S0 = wo;  S1 = nullptr; T = WGT + 3072 * DD; Kd = DD;   Ns = DD;   pair = false; int l = bid - 3072;   bx = l % 32;  by = l / 32; }
    else if (bid < 12288) { S0 = wfc; S1 = wfa;     T = WFF;             Kd = DD;   Ns = DFF_; pair = true;  int l = bid - 4096;   bx = l % 256; by = l / 256; }
    else                  { S0 = wou; S1 = nullptr; T = WOUT;            Kd = DFF_; Ns = DD;   pair = false; int l = bid - 12288;  bx = l % 32;  by = l / 32; }

    __shared__ float t[32][33];
    int n0 = bx * 32, k0 = by * 32;
    const float* S = S0; int col = n0 + tx;
    if (pair) { S = ((n0 + tx) & 1) ? S1 : S0; col = (n0 + tx) >> 1; }
    #pragma unroll
    for (int i = 0; i < 32; i += 8)
        t[ty + i][tx] = S[(size_t)(k0 + ty + i) * Ns + col];
    __syncthreads();
    #pragma unroll
    for (int i = 0; i < 32; i += 8)
        T[(size_t)(n0 + ty + i) * Kd + k0 + tx] = __float2half_rn(t[tx][ty + i]);
}

// ---------------- pipelined HMMA GEMM: 256 threads, 2 CTAs/SM ----------------
// C[M,N] = ACT(A @ B'^T + bias)  A fp16 [M,K] row-major, B' fp16 [N,K] row-major
// ACT 4: v+aux -> C (down-proj, fp32 out)
// ACT 5: gates, N=4096 layout [f | i,g ilv | o]: a->C fp32, bv->C1h fp16, o->C2h fp16
// ACT 6: fused FFN-up, N=8192 ilv (fc,fca): hff=fc*silu(fca) -> Ch fp16
constexpr int BM = 128, BN = 128, BK = 64, STAGES = 3, NT = 256;
constexpr int ASTG = BM * BK * 2;     // 16 KB
constexpr int BSTG = BN * BK * 2;     // 16 KB
constexpr int STG  = ASTG + BSTG;     // 32 KB
constexpr int GSMEM = STAGES * STG;   // 96 KB -> 2 CTAs/SM

template<int ACT>
__global__ __launch_bounds__(NT, 2) void tc_gemm(
    const __half* __restrict__ A, const __half* __restrict__ Bw,
    const float* __restrict__ bias, const float* __restrict__ aux,
    float* __restrict__ C, __half* __restrict__ Ch,
    __half* __restrict__ C1h, __half* __restrict__ C2h,
    int M, int N, int K)
{
    extern __shared__ __align__(128) char smem[];
    uint32_t su = smem_to_u32(smem);
    int tid = threadIdx.x, wid = tid >> 5, lane = tid & 31;

    // supertile raster (8 m-tiles per group) for L2 reuse
    int tn = N / BN;
    int per = 8 * tn, grp = blockIdx.x / per, rr = blockIdx.x % per;
    int m0 = (grp * 8 + (rr % 8)) * BM;
    int n0 = (rr / 8) * BN;

    const __half* Ab = A  + (size_t)m0 * K;
    const __half* Bb = Bw + (size_t)n0 * K;

    // cp.async offsets: A 4 chunks/thread, B 4 chunks/thread (16B chunks)
    uint32_t sAo[4], gAo[4];
    #pragma unroll
    for (int j = 0; j < 4; j++) {
        int idx = tid + j * NT, r = idx >> 3, c = idx & 7;
        sAo[j] = swz(r, c); gAo[j] = (uint32_t)(r * K + c * 8);
    }

    // warp layout: 2 (m) x 4 (n); warp tile 64x32
    int wm = (wid & 1) * 64, wn = (wid >> 1) * 32;
    int rA128[4], rA7[4], rB128[2], rB7[2];
    int cA = lane >> 4;           // 0..1
    int cB = (lane >> 3) & 1;     // 0..1
    #pragma unroll
    for (int i = 0; i < 4; i++) {
        int ra = wm + i * 16 + (lane & 15);
        rA128[i] = ra * 128; rA7[i] = ra & 7;
    }
    #pragma unroll
    for (int p = 0; p < 2; p++) {
        int rb = wn + p * 16 + (lane & 7) + ((lane >> 4) << 3);
        rB128[p] = rb * 128; rB7[p] = rb & 7;
    }

    float acc[4][4][4];
    #pragma unroll
    for (int i = 0; i < 4; i++)
        #pragma unroll
        for (int j = 0; j < 4; j++)
            #pragma unroll
            for (int q = 0; q < 4; q++) acc[i][j][q] = 0.f;

    const int NK = K / BK;

    #pragma unroll
    for (int s = 0; s < STAGES - 1; s++) {
        uint32_t sA = su + s * STG, sB = sA + ASTG;
        int k0 = s * BK;
        #pragma unroll
        for (int j = 0; j < 4; j++) {
            cp_async16(sA + sAo[j], Ab + gAo[j] + k0);
            cp_async16(sB + sAo[j], Bb + gAo[j] + k0);
        }
        cp_commit();
    }

    int cs = 0, ls = STAGES - 1;
    for (int kt = 0; kt < NK; kt++) {
        asm volatile("cp.async.wait_group %0;" :: "n"(STAGES - 2) : "memory");
        __syncthreads();

        int lt = kt + STAGES - 1;
        if (lt < NK) {
            uint32_t sA = su + ls * STG, sB = sA + ASTG;
            int k0 = lt * BK;
            #pragma unroll
            for (int j = 0; j < 4; j++) {
                cp_async16(sA + sAo[j], Ab + gAo[j] + k0);
                cp_async16(sB + sAo[j], Bb + gAo[j] + k0);
            }
        }
        cp_commit();
        if (++ls == STAGES) ls = 0;

        uint32_t sA = su + cs * STG, sB = sA + ASTG;
        if (++cs == STAGES) cs = 0;
        #pragma unroll
        for (int kk = 0; kk < 4; kk++) {
            uint32_t a[4][4], b[2][4];
            #pragma unroll
            for (int i = 0; i < 4; i++)
                ldsm4(a[i], sA + rA128[i] + (((kk * 2 + cA) ^ rA7[i]) << 4));
            #pragma unroll
            for (int p = 0; p < 2; p++)
                ldsm4(b[p], sB + rB128[p] + (((kk * 2 + cB) ^ rB7[p]) << 4));
            #pragma unroll
            for (int p = 0; p < 2; p++)
                #pragma unroll
                for (int i = 0; i < 4; i++) {
                    mma_f16(acc[i][2*p],     a[i], b[p]);
                    mma_f16(acc[i][2*p + 1], a[i], b[p] + 2);
                }
        }
    }

    // ---- fused epilogue ----
    #pragma unroll
    for (int i = 0; i < 4; i++) {
        int r0 = m0 + wm + i * 16 + (lane >> 2);
        #pragma unroll
        for (int j = 0; j < 4; j++) {
            int c0 = n0 + wn + j * 8 + (lane & 3) * 2;
            float b0 = bias[c0], b1 = bias[c0 + 1];
            #pragma unroll
            for (int h = 0; h < 2; h++) {
                int r = r0 + h * 8;
                float v0 = acc[i][j][2*h]     + b0;
                float v1 = acc[i][j][2*h + 1] + b1;
                if (ACT == 4) {
                    size_t idx = (size_t)r * N + c0;
                    float2 au = *reinterpret_cast<const float2*>(&aux[idx]);
                    *reinterpret_cast<float2*>(&C[idx]) = make_float2(v0 + au.x, v1 + au.y);
                } else if (ACT == 5) {
                    if (c0 < 1024) {
                        *reinterpret_cast<float2*>(&C[(size_t)r * DD + c0]) =
                            make_float2(sigmoidf_(v0), sigmoidf_(v1));
                    } else if (c0 < 3072) {
                        C1h[(size_t)r * DD + ((c0 - 1024) >> 1)] =
                            __float2half_rn(tanhf(v0) * sigmoidf_(v1));
                    } else {
                        *reinterpret_cast<__half2*>(&C2h[(size_t)r * DD + (c0 - 3072)]) =
                            __floats2half2_rn(sigmoidf_(v0), sigmoidf_(v1));
                    }
                } else if (ACT == 6) {
                    Ch[(size_t)r * DFF_ + (c0 >> 1)] =
                        __float2half_rn(v0 * (v1 * sigmoidf_(v1)));
                }
            }
        }
    }
}

// ---------------- chunked linear-recurrence scan ----------------
// NCH=128 chunks of 32 steps: 262144 threads in pass1 for memory-level parallelism
__global__ void scan_pass1(const float* __restrict__ aG, const __half* __restrict__ bVh,
                           float* __restrict__ Pb, float* __restrict__ Hb)
{
    int g = blockIdx.x * blockDim.x + threadIdx.x;    // BB*NCH*DD/2 threads
    int d2 = g & (DD/2 - 1);
    int c  = (g >> 9) & (NCH - 1);
    int b  = g >> 16;
    size_t base = ((size_t)b * LL + (size_t)c * CHUNK) * DD + d2 * 2;
    float2 P = make_float2(1.f, 1.f), hh = make_float2(0.f, 0.f);
    #pragma unroll 4
    for (int t = 0; t < CHUNK; t++) {
        size_t idx = base + (size_t)t * DD;
        float2 a  = *reinterpret_cast<const float2*>(aG + idx);
        float2 bv = __half22float2(*reinterpret_cast<const __half2*>(bVh + idx));
        P.x *= a.x; P.y *= a.y;
        hh.x = fmaf(a.x, hh.x, bv.x);
        hh.y = fmaf(a.y, hh.y, bv.y);
    }
    *reinterpret_cast<float2*>(Pb + (size_t)g * 2) = P;
    *reinterpret_cast<float2*>(Hb + (size_t)g * 2) = hh;
}

__global__ void scan_pass2(const float* __restrict__ Pb, const float* __restrict__ Hb,
                           const float* __restrict__ h0, float* __restrict__ Ib)
{
    int g = blockIdx.x * blockDim.x + threadIdx.x;   // B*D threads
    int d = g & (DD - 1);
    int b = g >> 10;
    float h = h0[d];
    #pragma unroll
    for (int c = 0; c < NCH; c++) {
        int j = (b * NCH + c) * DD + d;
        Ib[j] = h;
        h = fmaf(Pb[j], h, Hb[j]);
    }
}

// pass3 fused with RMSNorm2: one block (512 threads) owns a full D=1024 row
// for one (b, chunk). Writes x1 (fp32) AND xn2 (fp16, normalized) directly.
__global__ __launch_bounds__(512) void scan_pass3n(
    const float* __restrict__ aG, const __half* __restrict__ bVh,
    const __half* __restrict__ oSh, const float* __restrict__ x,
    const float* __restrict__ Ib, const float* __restrict__ w2,
    float* __restrict__ x1, __half* __restrict__ xn2)
{
    int b = blockIdx.x >> 7;            // 4 batches
    int c = blockIdx.x & 127;           // 128 chunks
    int tid = threadIdx.x;              // 512 threads, 2 d's each
    int d0 = tid * 2;

    __shared__ float red[16];
    __shared__ float s_scale;

    size_t base = ((size_t)b * LL + (size_t)c * CHUNK) * DD + d0;
    float2 hh = *reinterpret_cast<const float2*>(Ib + ((size_t)(b * NCH + c) * DD + d0));
    float2 w  = *reinterpret_cast<const float2*>(w2 + d0);

    for (int t = 0; t < CHUNK; t++) {
        size_t idx = base + (size_t)t * DD;
        float2 a  = *reinterpret_cast<const float2*>(aG + idx);
        float2 bv = __half22float2(*reinterpret_cast<const __half2*>(bVh + idx));
        float2 os = __half22float2(*reinterpret_cast<const __half2*>(oSh + idx));
        float2 xv = *reinterpret_cast<const float2*>(x + idx);
        hh.x = fmaf(a.x, hh.x, bv.x);
        hh.y = fmaf(a.y, hh.y, bv.y);
        float y0 = tanhf(hh.x) * os.x + xv.x;
        float y1 = tanhf(hh.y) * os.y + xv.y;
        *reinterpret_cast<float2*>(x1 + idx) = make_float2(y0, y1);

        // block-reduce sum of squares over D=1024 (512 threads x 2)
        float ss = y0 * y0 + y1 * y1;
        #pragma unroll
        for (int of = 16; of > 0; of >>= 1) ss += __shfl_xor_sync(0xffffffffu, ss, of);
        if ((tid & 31) == 0) red[tid >> 5] = ss;
        __syncthreads();
        if (tid < 32) {
            float v = (tid < 16) ? red[tid] : 0.f;
            #pragma unroll
            for (int of = 8; of > 0; of >>= 1) v += __shfl_xor_sync(0xffffffffu, v, of);
            if (tid == 0) s_scale = rsqrtf(v / (float)DD + 1e-6f);
        }
        __syncthreads();
        float s = s_scale;
        *reinterpret_cast<__half2*>(xn2 + idx) =
            __floats2half2_rn(y0 * s * w.x, y1 * s * w.y);
        __syncthreads();   // protect s_scale for next t
    }
}

// ---------------- launcher ----------------
extern "C" void kernel_launch(void* const* d_in, const int* in_sizes, int n_in,
                              void* d_out, int out_size)
{
    (void)in_sizes; (void)n_in; (void)out_size;
    const float* x   = (const float*)d_in[0];
    const float* wf  = (const float*)d_in[1];
    const float* bf_ = (const float*)d_in[2];
    const float* wi  = (const float*)d_in[3];
    const float* bi_ = (const float*)d_in[4];
    const float* wg  = (const float*)d_in[5];
    const float* bg_ = (const float*)d_in[6];
    const float* wo  = (const float*)d_in[7];
    const float* bo_ = (const float*)d_in[8];
    const float* h0  = (const float*)d_in[9];
    const float* n1w = (const float*)d_in[10];
    const float* n2w = (const float*)d_in[11];
    const float* wfc = (const float*)d_in[12];
    const float* bfc = (const float*)d_in[13];
    const float* wfa = (const float*)d_in[14];
    const float* bfa = (const float*)d_in[15];
    const float* wou = (const float*)d_in[16];
    const float* bou = (const float*)d_in[17];
    float* out = (float*)d_out;

    float *ga, *x1, *P, *H, *I, *bg4, *bff;
    cudaGetSymbolAddress((void**)&ga,  g_a);
    cudaGetSymbolAddress((void**)&x1,  g_x1);
    cudaGetSymbolAddress((void**)&P,   g_P);
    cudaGetSymbolAddress((void**)&H,   g_H);
    cudaGetSymbolAddress((void**)&I,   g_I);
    cudaGetSymbolAddress((void**)&bg4, g_bg);
    cudaGetSymbolAddress((void**)&bff, g_bff);

    __half *gbvh, *goh, *xn, *xn2, *hff, *wgt, *wff, *wout_;
    cudaGetSymbolAddress((void**)&gbvh, g_bvh);
    cudaGetSymbolAddress((void**)&goh,  g_oh);
    cudaGetSymbolAddress((void**)&xn,   g_xn);
    cudaGetSymbolAddress((void**)&xn2,  g_xn2);
    cudaGetSymbolAddress((void**)&hff,  g_hff);
    cudaGetSymbolAddress((void**)&wgt,  g_wgt);
    cudaGetSymbolAddress((void**)&wff,  g_wff);
    cudaGetSymbolAddress((void**)&wout_,g_wout);

    cudaFuncSetAttribute(tc_gemm<4>, cudaFuncAttributeMaxDynamicSharedMemorySize, GSMEM);
    cudaFuncSetAttribute(tc_gemm<5>, cudaFuncAttributeMaxDynamicSharedMemorySize, GSMEM);
    cudaFuncSetAttribute(tc_gemm<6>, cudaFuncAttributeMaxDynamicSharedMemorySize, GSMEM);

    // 0) fused weight/bias packing (single launch)
    pack_all<<<16416, dim3(32, 8)>>>(wf, wi, wg, wo, wfc, wfa, wou,
                                     bf_, bi_, bg_, bo_, bfc, bfa,
                                     wgt, wff, wout_, bg4, bff);

    // 1) norm1 -> fp16
    rmsnorm_h<<<MM, 256>>>(x, n1w, xn);

    // 2) gate GEMM (N=4096) -> a (fp32), bv (fp16), o (fp16)
    int gGates = (MM/BM) * ((4*DD)/BN);
    tc_gemm<5><<<gGates, NT, GSMEM>>>(xn, wgt, bg4, nullptr, ga, nullptr, gbvh, goh,
                                      MM, 4*DD, DD);

    // 3) scan + output gate + residual + fused RMSNorm2 -> x1 (fp32), xn2 (fp16)
    scan_pass1<<<(BB*NCH*DD/2)/256, 256>>>(ga, gbvh, P, H);
    scan_pass2<<<(BB*DD)/256, 256>>>(P, H, h0, I);
    scan_pass3n<<<BB*NCH, 512>>>(ga, gbvh, goh, x, I, n2w, x1, xn2);

    // 4) fused FFN-up (N=8192, interleaved) -> hff fp16
    int gFF = (MM/BM) * ((2*DFF_)/BN);
    tc_gemm<6><<<gFF, NT, GSMEM>>>(xn2, wff, bff, nullptr, nullptr, hff, nullptr, nullptr,
                                   MM, 2*DFF_, DD);

    // 5) down-proj + b_out + x1 -> d_out
    int gOut = (MM/BM) * (DD/BN);
    tc_gemm<4><<<gOut, NT, GSMEM>>>(hff, wout_, bou, x1, out, nullptr, nullptr, nullptr,
                                    MM, DD, DFF_);
}

// round 11
// speedup vs baseline: 10.5051x; 1.0054x over previous
#include <cuda_runtime.h>
#include <cuda_fp16.h>
#include <cstdint>

// Problem shape (fixed)
#define BB   4
#define LL   4096
#define DD   1024
#define DFF_ 4096
#define MM   (BB*LL)        // 16384 token rows
#define NCH  128
#define CHUNK 32

// ---------------- scratch (device globals: allocation-free) ----------------
__device__ float  g_a  [MM*DD];     // sigmoid(forget)  (fp32: 1/(1-a) error amplification)
__device__ __half g_bvh[MM*DD];     // tanh(input)*sigmoid(igate)
__device__ __half g_oh [MM*DD];     // sigmoid(ogate)
__device__ float  g_x1 [MM*DD];
__device__ float  g_P  [BB*NCH*DD];
__device__ float  g_H  [BB*NCH*DD];
__device__ float  g_I  [BB*NCH*DD];
__device__ float  g_bg [4*DD];      // gate bias, layout [f | i,g interleaved | o]
__device__ float  g_bff[2*DFF_];    // ffn bias, interleaved [bfc_j, bfa_j]

__device__ __half g_xn [MM*DD];
__device__ __half g_xn2[MM*DD];
__device__ __half g_hff[MM*DFF_];
__device__ __half g_wgt[4*DD*DD];   // [4096,1024] K-major, rows [f | i,g ilv | o]
__device__ __half g_wff[2*DFF_*DD]; // [8192,1024] K-major, rows interleaved (fc,fca)
__device__ __half g_wout[DD*DFF_];  // [1024,4096] K-major

// ---------------- asm helpers ----------------
__device__ __forceinline__ uint32_t smem_to_u32(const void* p) {
    uint32_t a;
    asm("{ .reg .u64 t; cvta.to.shared.u64 t, %1; cvt.u32.u64 %0, t; }" : "=r"(a) : "l"(p));
    return a;
}
__device__ __forceinline__ void cp_async16(uint32_t sa, const void* gp) {
    asm volatile("cp.async.cg.shared.global [%0], [%1], 16;" :: "r"(sa), "l"(gp));
}
__device__ __forceinline__ void cp_commit() {
    asm volatile("cp.async.commit_group;" ::: "memory");
}
__device__ __forceinline__ void ldsm4(uint32_t* d, uint32_t addr) {
    asm volatile("ldmatrix.sync.aligned.m8n8.x4.shared.b16 {%0,%1,%2,%3}, [%4];"
        : "=r"(d[0]), "=r"(d[1]), "=r"(d[2]), "=r"(d[3]) : "r"(addr));
}
__device__ __forceinline__ void mma_f16(float* c, const uint32_t* a, const uint32_t* b) {
    asm volatile("mma.sync.aligned.m16n8k16.row.col.f32.f16.f16.f32 "
        "{%0,%1,%2,%3}, {%4,%5,%6,%7}, {%8,%9}, {%0,%1,%2,%3};"
        : "+f"(c[0]), "+f"(c[1]), "+f"(c[2]), "+f"(c[3])
        : "r"(a[0]), "r"(a[1]), "r"(a[2]), "r"(a[3]), "r"(b[0]), "r"(b[1]));
}
__device__ __forceinline__ float sigmoidf_(float v) { return 1.f / (1.f + expf(-v)); }

// SW128-style swizzle for [rows][64 fp16] tiles (128B rows, 8 x 16B chunks)
__device__ __forceinline__ uint32_t swz(int row, int c) {
    return (uint32_t)(row * 128 + (((c) ^ (row & 7)) << 4));
}

// ---------------- fused packing + RMSNorm1 kernel ----------------
// bids [0,16384):      weight transpose tiles (pack)
// bids [16384,16416):  bias packing
// bids [16416,32800):  rmsnorm1 rows (row = bid - 16416)
#define PACK_BLKS 16416
__global__ void pack_norm(const float* __restrict__ wf,  const float* __restrict__ wi,
                          const float* __restrict__ wg,  const float* __restrict__ wo,
                          const float* __restrict__ wfc, const float* __restrict__ wfa,
                          const float* __restrict__ wou,
                          const float* __restrict__ bf,  const float* __restrict__ bi,
                          const float* __restrict__ bg,  const float* __restrict__ bo,
                          const float* __restrict__ bfc, const float* __restrict__ bfa,
                          const float* __restrict__ x,   const float* __restrict__ n1w,
                          __half* __restrict__ WGT, __half* __restrict__ WFF,
                          __half* __restrict__ WOUT,
                          float* __restrict__ BG, float* __restrict__ BFF,
                          __half* __restrict__ XN)
{
    int bid = blockIdx.x;
    int tid = threadIdx.x;        // 256 flat

    __shared__ float t[32][33];   // pack path
    __shared__ float red[8];      // norm path
    __shared__ float s_scale;

    if (bid >= PACK_BLKS) {
        // ---- RMSNorm1 row ----
        int row = bid - PACK_BLKS;
        const float4* xv = reinterpret_cast<const float4*>(x + (size_t)row * DD);
        const float4* wv = reinterpret_cast<const float4*>(n1w);
        float4 v = xv[tid];
        float ss = v.x*v.x + v.y*v.y + v.z*v.z + v.w*v.w;
        #pragma unroll
        for (int of = 16; of > 0; of >>= 1) ss += __shfl_xor_sync(0xffffffffu, ss, of);
        if ((tid & 31) == 0) red[tid >> 5] = ss;
        __syncthreads();
        if (tid == 0) {
            float s = 0.f;
            #pragma unroll
            for (int i = 0; i < 8; i++) s += red[i];
            s_scale = rsqrtf(s / (float)DD + 1e-6f);
        }
        __syncthreads();
        float s = s_scale;
        float4 w4 = wv[tid];
        __half2* ov = reinterpret_cast<__half2*>(XN + (size_t)row * DD);
        ov[tid*2]   = __floats2half2_rn(v.x*s*w4.x, v.y*s*w4.y);
        ov[tid*2+1] = __floats2half2_rn(v.z*s*w4.z, v.w*s*w4.w);
        return;
    }

    if (bid >= 16384) {
        // ---- bias pack: 32 blocks x 256 threads = 8192 ----
        int n = (bid - 16384) * 256 + tid;
        if (n < 4 * DD) {
            float v;
            if (n < DD)            v = bf[n];
            else if (n < 3 * DD) { int q = n - DD; v = (q & 1) ? bg[q >> 1] : bi[q >> 1]; }
            else                   v = bo[n - 3 * DD];
            BG[n] = v;
        }
        BFF[n] = (n & 1) ? bfa[n >> 1] : bfc[n >> 1];
        return;
    }

    // ---- weight transpose tile ----
    int tx = tid & 31, ty = tid >> 5;   // (32, 8)
    const float *S0, *S1; __half* T; int Kd, Ns, bx, by; bool pair;
    if (bid < 1024)       { S0 = wf;  S1 = nullptr; T = WGT;             Kd = DD;   Ns = DD;   pair = false; int l = bid;          bx = l % 32;  by = l / 32; }
    else if (bid < 3072)  { S0 = wi;  S1 = wg;      T = WGT + 1024 * DD; Kd = DD;   Ns = DD;   pair = true;  int l = bid - 1024;   bx = l % 64;  by = l / 64; }
    else if (bid < 4096)  { S0 = wo;  S1 = nullptr; T = WGT + 3072 * DD; Kd = DD;   Ns = DD;   pair = false; int l = bid - 3072;   bx = l % 32;  by = l / 32; }
    else if (bid < 12288) { S0 = wfc; S1 = wfa;     T = WFF;             Kd = DD;   Ns = DFF_; pair = true;  int l = bid - 4096;   bx = l % 256; by = l / 256; }
    else                  { S0 = wou; S1 = nullptr; T = WOUT;            Kd = DFF_; Ns = DD;   pair = false; int l = bid - 12288;  bx = l % 32;  by = l / 32; }

    int n0 = bx * 32, k0 = by * 32;
    const float* S = S0; int col = n0 + tx;
    if (pair) { S = ((n0 + tx) & 1) ? S1 : S0; col = (n0 + tx) >> 1; }
    #pragma unroll
    for (int i = 0; i < 32; i += 8)
        t[ty + i][tx] = S[(size_t)(k0 + ty + i) * Ns + col];
    __syncthreads();
    #pragma unroll
    for (int i = 0; i < 32; i += 8)
        T[(size_t)(n0 + ty + i) * Kd + k0 + tx] = __float2half_rn(t[tx][ty + i]);
}

// ---------------- pipelined HMMA GEMM: 256 threads, 2 CTAs/SM ----------------
// C[M,N] = ACT(A @ B'^T + bias)  A fp16 [M,K] row-major, B' fp16 [N,K] row-major
// ACT 4: v+aux -> C (down-proj, fp32 out)
// ACT 5: gates, N=4096 layout [f | i,g ilv | o]: a->C fp32, bv->C1h fp16, o->C2h fp16
// ACT 6: fused FFN-up, N=8192 ilv (fc,fca): hff=fc*silu(fca) -> Ch fp16
constexpr int BM = 128, BN = 128, BK = 64, STAGES = 3, NT = 256;
constexpr int ASTG = BM * BK * 2;     // 16 KB
constexpr int BSTG = BN * BK * 2;     // 16 KB
constexpr int STG  = ASTG + BSTG;     // 32 KB
constexpr int GSMEM = STAGES * STG;   // 96 KB -> 2 CTAs/SM

template<int ACT>
__global__ __launch_bounds__(NT, 2) void tc_gemm(
    const __half* __restrict__ A, const __half* __restrict__ Bw,
    const float* __restrict__ bias, const float* __restrict__ aux,
    float* __restrict__ C, __half* __restrict__ Ch,
    __half* __restrict__ C1h, __half* __restrict__ C2h,
    int M, int N, int K)
{
    extern __shared__ __align__(128) char smem[];
    uint32_t su = smem_to_u32(smem);
    int tid = threadIdx.x, wid = tid >> 5, lane = tid & 31;

    // supertile raster (8 m-tiles per group) for L2 reuse
    int tn = N / BN;
    int per = 8 * tn, grp = blockIdx.x / per, rr = blockIdx.x % per;
    int m0 = (grp * 8 + (rr % 8)) * BM;
    int n0 = (rr / 8) * BN;

    const __half* Ab = A  + (size_t)m0 * K;
    const __half* Bb = Bw + (size_t)n0 * K;

    // cp.async offsets: A 4 chunks/thread, B 4 chunks/thread (16B chunks)
    uint32_t sAo[4], gAo[4];
    #pragma unroll
    for (int j = 0; j < 4; j++) {
        int idx = tid + j * NT, r = idx >> 3, c = idx & 7;
        sAo[j] = swz(r, c); gAo[j] = (uint32_t)(r * K + c * 8);
    }

    // warp layout: 2 (m) x 4 (n); warp tile 64x32
    int wm = (wid & 1) * 64, wn = (wid >> 1) * 32;
    int rA128[4], rA7[4], rB128[2], rB7[2];
    int cA = lane >> 4;           // 0..1
    int cB = (lane >> 3) & 1;     // 0..1
    #pragma unroll
    for (int i = 0; i < 4; i++) {
        int ra = wm + i * 16 + (lane & 15);
        rA128[i] = ra * 128; rA7[i] = ra & 7;
    }
    #pragma unroll
    for (int p = 0; p < 2; p++) {
        int rb = wn + p * 16 + (lane & 7) + ((lane >> 4) << 3);
        rB128[p] = rb * 128; rB7[p] = rb & 7;
    }

    float acc[4][4][4];
    #pragma unroll
    for (int i = 0; i < 4; i++)
        #pragma unroll
        for (int j = 0; j < 4; j++)
            #pragma unroll
            for (int q = 0; q < 4; q++) acc[i][j][q] = 0.f;

    const int NK = K / BK;

    #pragma unroll
    for (int s = 0; s < STAGES - 1; s++) {
        uint32_t sA = su + s * STG, sB = sA + ASTG;
        int k0 = s * BK;
        #pragma unroll
        for (int j = 0; j < 4; j++) {
            cp_async16(sA + sAo[j], Ab + gAo[j] + k0);
            cp_async16(sB + sAo[j], Bb + gAo[j] + k0);
        }
        cp_commit();
    }

    int cs = 0, ls = STAGES - 1;
    for (int kt = 0; kt < NK; kt++) {
        asm volatile("cp.async.wait_group %0;" :: "n"(STAGES - 2) : "memory");
        __syncthreads();

        int lt = kt + STAGES - 1;
        if (lt < NK) {
            uint32_t sA = su + ls * STG, sB = sA + ASTG;
            int k0 = lt * BK;
            #pragma unroll
            for (int j = 0; j < 4; j++) {
                cp_async16(sA + sAo[j], Ab + gAo[j] + k0);
                cp_async16(sB + sAo[j], Bb + gAo[j] + k0);
            }
        }
        cp_commit();
        if (++ls == STAGES) ls = 0;

        uint32_t sA = su + cs * STG, sB = sA + ASTG;
        if (++cs == STAGES) cs = 0;
        #pragma unroll
        for (int kk = 0; kk < 4; kk++) {
            uint32_t a[4][4], b[2][4];
            #pragma unroll
            for (int i = 0; i < 4; i++)
                ldsm4(a[i], sA + rA128[i] + (((kk * 2 + cA) ^ rA7[i]) << 4));
            #pragma unroll
            for (int p = 0; p < 2; p++)
                ldsm4(b[p], sB + rB128[p] + (((kk * 2 + cB) ^ rB7[p]) << 4));
            #pragma unroll
            for (int p = 0; p < 2; p++)
                #pragma unroll
                for (int i = 0; i < 4; i++) {
                    mma_f16(acc[i][2*p],     a[i], b[p]);
                    mma_f16(acc[i][2*p + 1], a[i], b[p] + 2);
                }
        }
    }

    // ---- fused epilogue ----
    #pragma unroll
    for (int i = 0; i < 4; i++) {
        int r0 = m0 + wm + i * 16 + (lane >> 2);
        #pragma unroll
        for (int j = 0; j < 4; j++) {
            int c0 = n0 + wn + j * 8 + (lane & 3) * 2;
            float b0 = bias[c0], b1 = bias[c0 + 1];
            #pragma unroll
            for (int h = 0; h < 2; h++) {
                int r = r0 + h * 8;
                float v0 = acc[i][j][2*h]     + b0;
                float v1 = acc[i][j][2*h + 1] + b1;
                if (ACT == 4) {
                    size_t idx = (size_t)r * N + c0;
                    float2 au = *reinterpret_cast<const float2*>(&aux[idx]);
                    *reinterpret_cast<float2*>(&C[idx]) = make_float2(v0 + au.x, v1 + au.y);
                } else if (ACT == 5) {
                    if (c0 < 1024) {
                        *reinterpret_cast<float2*>(&C[(size_t)r * DD + c0]) =
                            make_float2(sigmoidf_(v0), sigmoidf_(v1));
                    } else if (c0 < 3072) {
                        C1h[(size_t)r * DD + ((c0 - 1024) >> 1)] =
                            __float2half_rn(tanhf(v0) * sigmoidf_(v1));
                    } else {
                        *reinterpret_cast<__half2*>(&C2h[(size_t)r * DD + (c0 - 3072)]) =
                            __floats2half2_rn(sigmoidf_(v0), sigmoidf_(v1));
                    }
                } else if (ACT == 6) {
                    Ch[(size_t)r * DFF_ + (c0 >> 1)] =
                        __float2half_rn(v0 * (v1 * sigmoidf_(v1)));
                }
            }
        }
    }
}

// ---------------- chunked linear-recurrence scan ----------------
// NCH=128 chunks of 32 steps: 262144 threads in pass1 for memory-level parallelism
__global__ void scan_pass1(const float* __restrict__ aG, const __half* __restrict__ bVh,
                           float* __restrict__ Pb, float* __restrict__ Hb)
{
    int g = blockIdx.x * blockDim.x + threadIdx.x;    // BB*NCH*DD/2 threads
    int d2 = g & (DD/2 - 1);
    int c  = (g >> 9) & (NCH - 1);
    int b  = g >> 16;
    size_t base = ((size_t)b * LL + (size_t)c * CHUNK) * DD + d2 * 2;
    float2 P = make_float2(1.f, 1.f), hh = make_float2(0.f, 0.f);
    #pragma unroll 4
    for (int t = 0; t < CHUNK; t++) {
        size_t idx = base + (size_t)t * DD;
        float2 a  = *reinterpret_cast<const float2*>(aG + idx);
        float2 bv = __half22float2(*reinterpret_cast<const __half2*>(bVh + idx));
        P.x *= a.x; P.y *= a.y;
        hh.x = fmaf(a.x, hh.x, bv.x);
        hh.y = fmaf(a.y, hh.y, bv.y);
    }
    *reinterpret_cast<float2*>(Pb + (size_t)g * 2) = P;
    *reinterpret_cast<float2*>(Hb + (size_t)g * 2) = hh;
}

__global__ void scan_pass2(const float* __restrict__ Pb, const float* __restrict__ Hb,
                           const float* __restrict__ h0, float* __restrict__ Ib)
{
    int g = blockIdx.x * blockDim.x + threadIdx.x;   // B*D threads
    int d = g & (DD - 1);
    int b = g >> 10;
    float h = h0[d];
    #pragma unroll
    for (int c = 0; c < NCH; c++) {
        int j = (b * NCH + c) * DD + d;
        Ib[j] = h;
        h = fmaf(Pb[j], h, Hb[j]);
    }
}

// pass3 fused with RMSNorm2: one block (512 threads) owns a full D=1024 row
// for one (b, chunk). Writes x1 (fp32) AND xn2 (fp16, normalized) directly.
__global__ __launch_bounds__(512) void scan_pass3n(
    const float* __restrict__ aG, const __half* __restrict__ bVh,
    const __half* __restrict__ oSh, const float* __restrict__ x,
    const float* __restrict__ Ib, const float* __restrict__ w2,
    float* __restrict__ x1, __half* __restrict__ xn2)
{
    int b = blockIdx.x >> 7;            // 4 batches
    int c = blockIdx.x & 127;           // 128 chunks
    int tid = threadIdx.x;              // 512 threads, 2 d's each
    int d0 = tid * 2;

    __shared__ float red[16];
    __shared__ float s_scale;

    size_t base = ((size_t)b * LL + (size_t)c * CHUNK) * DD + d0;
    float2 hh = *reinterpret_cast<const float2*>(Ib + ((size_t)(b * NCH + c) * DD + d0));
    float2 w  = *reinterpret_cast<const float2*>(w2 + d0);

    for (int t = 0; t < CHUNK; t++) {
        size_t idx = base + (size_t)t * DD;
        float2 a  = *reinterpret_cast<const float2*>(aG + idx);
        float2 bv = __half22float2(*reinterpret_cast<const __half2*>(bVh + idx));
        float2 os = __half22float2(*reinterpret_cast<const __half2*>(oSh + idx));
        float2 xv = *reinterpret_cast<const float2*>(x + idx);
        hh.x = fmaf(a.x, hh.x, bv.x);
        hh.y = fmaf(a.y, hh.y, bv.y);
        float y0 = tanhf(hh.x) * os.x + xv.x;
        float y1 = tanhf(hh.y) * os.y + xv.y;
        *reinterpret_cast<float2*>(x1 + idx) = make_float2(y0, y1);

        // block-reduce sum of squares over D=1024 (512 threads x 2)
        float ss = y0 * y0 + y1 * y1;
        #pragma unroll
        for (int of = 16; of > 0; of >>= 1) ss += __shfl_xor_sync(0xffffffffu, ss, of);
        if ((tid & 31) == 0) red[tid >> 5] = ss;
        __syncthreads();
        if (tid < 32) {
            float v = (tid < 16) ? red[tid] : 0.f;
            #pragma unroll
            for (int of = 8; of > 0; of >>= 1) v += __shfl_xor_sync(0xffffffffu, v, of);
            if (tid == 0) s_scale = rsqrtf(v / (float)DD + 1e-6f);
        }
        __syncthreads();
        float s = s_scale;
        *reinterpret_cast<__half2*>(xn2 + idx) =
            __floats2half2_rn(y0 * s * w.x, y1 * s * w.y);
        __syncthreads();   // protect s_scale for next t
    }
}

// ---------------- launcher ----------------
extern "C" void kernel_launch(void* const* d_in, const int* in_sizes, int n_in,
                              void* d_out, int out_size)
{
    (void)in_sizes; (void)n_in; (void)out_size;
    const float* x   = (const float*)d_in[0];
    const float* wf  = (const float*)d_in[1];
    const float* bf_ = (const float*)d_in[2];
    const float* wi  = (const float*)d_in[3];
    const float* bi_ = (const float*)d_in[4];
    const float* wg  = (const float*)d_in[5];
    const float* bg_ = (const float*)d_in[6];
    const float* wo  = (const float*)d_in[7];
    const float* bo_ = (const float*)d_in[8];
    const float* h0  = (const float*)d_in[9];
    const float* n1w = (const float*)d_in[10];
    const float* n2w = (const float*)d_in[11];
    const float* wfc = (const float*)d_in[12];
    const float* bfc = (const float*)d_in[13];
    const float* wfa = (const float*)d_in[14];
    const float* bfa = (const float*)d_in[15];
    const float* wou = (const float*)d_in[16];
    const float* bou = (const float*)d_in[17];
    float* out = (float*)d_out;

    float *ga, *x1, *P, *H, *I, *bg4, *bff;
    cudaGetSymbolAddress((void**)&ga,  g_a);
    cudaGetSymbolAddress((void**)&x1,  g_x1);
    cudaGetSymbolAddress((void**)&P,   g_P);
    cudaGetSymbolAddress((void**)&H,   g_H);
    cudaGetSymbolAddress((void**)&I,   g_I);
    cudaGetSymbolAddress((void**)&bg4, g_bg);
    cudaGetSymbolAddress((void**)&bff, g_bff);

    __half *gbvh, *goh, *xn, *xn2, *hff, *wgt, *wff, *wout_;
    cudaGetSymbolAddress((void**)&gbvh, g_bvh);
    cudaGetSymbolAddress((void**)&goh,  g_oh);
    cudaGetSymbolAddress((void**)&xn,   g_xn);
    cudaGetSymbolAddress((void**)&xn2,  g_xn2);
    cudaGetSymbolAddress((void**)&hff,  g_hff);
    cudaGetSymbolAddress((void**)&wgt,  g_wgt);
    cudaGetSymbolAddress((void**)&wff,  g_wff);
    cudaGetSymbolAddress((void**)&wout_,g_wout);

    cudaFuncSetAttribute(tc_gemm<4>, cudaFuncAttributeMaxDynamicSharedMemorySize, GSMEM);
    cudaFuncSetAttribute(tc_gemm<5>, cudaFuncAttributeMaxDynamicSharedMemorySize, GSMEM);
    cudaFuncSetAttribute(tc_gemm<6>, cudaFuncAttributeMaxDynamicSharedMemorySize, GSMEM);

    // 0) fused weight/bias packing + RMSNorm1 (single launch, overlapped)
    pack_norm<<<PACK_BLKS + MM, 256>>>(wf, wi, wg, wo, wfc, wfa, wou,
                                       bf_, bi_, bg_, bo_, bfc, bfa,
                                       x, n1w,
                                       wgt, wff, wout_, bg4, bff, xn);

    // 1) gate GEMM (N=4096) -> a (fp32), bv (fp16), o (fp16)
    int gGates = (MM/BM) * ((4*DD)/BN);
    tc_gemm<5><<<gGates, NT, GSMEM>>>(xn, wgt, bg4, nullptr, ga, nullptr, gbvh, goh,
                                      MM, 4*DD, DD);

    // 2) scan + output gate + residual + fused RMSNorm2 -> x1 (fp32), xn2 (fp16)
    scan_pass1<<<(BB*NCH*DD/2)/256, 256>>>(ga, gbvh, P, H);
    scan_pass2<<<(BB*DD)/256, 256>>>(P, H, h0, I);
    scan_pass3n<<<BB*NCH, 512>>>(ga, gbvh, goh, x, I, n2w, x1, xn2);

    // 3) fused FFN-up (N=8192, interleaved) -> hff fp16
    int gFF = (MM/BM) * ((2*DFF_)/BN);
    tc_gemm<6><<<gFF, NT, GSMEM>>>(xn2, wff, bff, nullptr, nullptr, hff, nullptr, nullptr,
                                   MM, 2*DFF_, DD);

    // 4) down-proj + b_out + x1 -> d_out
    int gOut = (MM/BM) * (DD/BN);
    tc_gemm<4><<<gOut, NT, GSMEM>>>(hff, wout_, bou, x1, out, nullptr, nullptr, nullptr,
                                    MM, DD, DFF_);
}

// round 12
// speedup vs baseline: 10.5179x; 1.0012x over previous
#include <cuda_runtime.h>
#include <cuda_fp16.h>
#include <cstdint>

// Problem shape (fixed)
#define BB   4
#define LL   4096
#define DD   1024
#define DFF_ 4096
#define MM   (BB*LL)        // 16384 token rows
#define NCH  128
#define CHUNK 32

// ---------------- scratch (device globals: allocation-free) ----------------
__device__ float  g_a  [MM*DD];     // sigmoid(forget)  (fp32: 1/(1-a) error amplification)
__device__ __half g_bvh[MM*DD];     // tanh(input)*sigmoid(igate)
__device__ __half g_oh [MM*DD];     // sigmoid(ogate)
__device__ float  g_x1 [MM*DD];
__device__ float  g_P  [BB*NCH*DD];
__device__ float  g_H  [BB*NCH*DD];
__device__ float  g_I  [BB*NCH*DD];
__device__ float  g_bg [4*DD];      // gate bias, layout [f | i,g interleaved | o]
__device__ float  g_bff[2*DFF_];    // ffn bias, interleaved [bfc_j, bfa_j]

__device__ __half g_xn [MM*DD];
__device__ __half g_xn2[MM*DD];
__device__ __half g_hff[MM*DFF_];
__device__ __half g_wgt[4*DD*DD];   // [4096,1024] K-major, rows [f | i,g ilv | o]
__device__ __half g_wff[2*DFF_*DD]; // [8192,1024] K-major, rows interleaved (fc,fca)
__device__ __half g_wout[DD*DFF_];  // [1024,4096] K-major

// ---------------- asm helpers ----------------
__device__ __forceinline__ uint32_t smem_to_u32(const void* p) {
    uint32_t a;
    asm("{ .reg .u64 t; cvta.to.shared.u64 t, %1; cvt.u32.u64 %0, t; }" : "=r"(a) : "l"(p));
    return a;
}
__device__ __forceinline__ void cp_async16(uint32_t sa, const void* gp) {
    asm volatile("cp.async.cg.shared.global [%0], [%1], 16;" :: "r"(sa), "l"(gp));
}
__device__ __forceinline__ void cp_commit() {
    asm volatile("cp.async.commit_group;" ::: "memory");
}
__device__ __forceinline__ void ldsm4(uint32_t* d, uint32_t addr) {
    asm volatile("ldmatrix.sync.aligned.m8n8.x4.shared.b16 {%0,%1,%2,%3}, [%4];"
        : "=r"(d[0]), "=r"(d[1]), "=r"(d[2]), "=r"(d[3]) : "r"(addr));
}
__device__ __forceinline__ void mma_f16(float* c, const uint32_t* a, const uint32_t* b) {
    asm volatile("mma.sync.aligned.m16n8k16.row.col.f32.f16.f16.f32 "
        "{%0,%1,%2,%3}, {%4,%5,%6,%7}, {%8,%9}, {%0,%1,%2,%3};"
        : "+f"(c[0]), "+f"(c[1]), "+f"(c[2]), "+f"(c[3])
        : "r"(a[0]), "r"(a[1]), "r"(a[2]), "r"(a[3]), "r"(b[0]), "r"(b[1]));
}
__device__ __forceinline__ float sigmoidf_(float v) { return 1.f / (1.f + expf(-v)); }

// SW128-style swizzle for [rows][64 fp16] tiles (128B rows, 8 x 16B chunks)
__device__ __forceinline__ uint32_t swz(int row, int c) {
    return (uint32_t)(row * 128 + (((c) ^ (row & 7)) << 4));
}

// ---------------- fused packing + RMSNorm1 kernel ----------------
// bids [0,16384):      weight transpose tiles (pack)
// bids [16384,16416):  bias packing
// bids [16416,32800):  rmsnorm1 rows (row = bid - 16416)
#define PACK_BLKS 16416
__global__ void pack_norm(const float* __restrict__ wf,  const float* __restrict__ wi,
                          const float* __restrict__ wg,  const float* __restrict__ wo,
                          const float* __restrict__ wfc, const float* __restrict__ wfa,
                          const float* __restrict__ wou,
                          const float* __restrict__ bf,  const float* __restrict__ bi,
                          const float* __restrict__ bg,  const float* __restrict__ bo,
                          const float* __restrict__ bfc, const float* __restrict__ bfa,
                          const float* __restrict__ x,   const float* __restrict__ n1w,
                          __half* __restrict__ WGT, __half* __restrict__ WFF,
                          __half* __restrict__ WOUT,
                          float* __restrict__ BG, float* __restrict__ BFF,
                          __half* __restrict__ XN)
{
    int bid = blockIdx.x;
    int tid = threadIdx.x;        // 256 flat

    __shared__ float t[32][33];   // pack path
    __shared__ float red[8];      // norm path
    __shared__ float s_scale;

    if (bid >= PACK_BLKS) {
        // ---- RMSNorm1 row ----
        int row = bid - PACK_BLKS;
        const float4* xv = reinterpret_cast<const float4*>(x + (size_t)row * DD);
        const float4* wv = reinterpret_cast<const float4*>(n1w);
        float4 v = xv[tid];
        float ss = v.x*v.x + v.y*v.y + v.z*v.z + v.w*v.w;
        #pragma unroll
        for (int of = 16; of > 0; of >>= 1) ss += __shfl_xor_sync(0xffffffffu, ss, of);
        if ((tid & 31) == 0) red[tid >> 5] = ss;
        __syncthreads();
        if (tid == 0) {
            float s = 0.f;
            #pragma unroll
            for (int i = 0; i < 8; i++) s += red[i];
            s_scale = rsqrtf(s / (float)DD + 1e-6f);
        }
        __syncthreads();
        float s = s_scale;
        float4 w4 = wv[tid];
        __half2* ov = reinterpret_cast<__half2*>(XN + (size_t)row * DD);
        ov[tid*2]   = __floats2half2_rn(v.x*s*w4.x, v.y*s*w4.y);
        ov[tid*2+1] = __floats2half2_rn(v.z*s*w4.z, v.w*s*w4.w);
        return;
    }

    if (bid >= 16384) {
        // ---- bias pack: 32 blocks x 256 threads = 8192 ----
        int n = (bid - 16384) * 256 + tid;
        if (n < 4 * DD) {
            float v;
            if (n < DD)            v = bf[n];
            else if (n < 3 * DD) { int q = n - DD; v = (q & 1) ? bg[q >> 1] : bi[q >> 1]; }
            else                   v = bo[n - 3 * DD];
            BG[n] = v;
        }
        BFF[n] = (n & 1) ? bfa[n >> 1] : bfc[n >> 1];
        return;
    }

    // ---- weight transpose tile ----
    int tx = tid & 31, ty = tid >> 5;   // (32, 8)
    const float *S0, *S1; __half* T; int Kd, Ns, bx, by; bool pair;
    if (bid < 1024)       { S0 = wf;  S1 = nullptr; T = WGT;             Kd = DD;   Ns = DD;   pair = false; int l = bid;          bx = l % 32;  by = l / 32; }
    else if (bid < 3072)  { S0 = wi;  S1 = wg;      T = WGT + 1024 * DD; Kd = DD;   Ns = DD;   pair = true;  int l = bid - 1024;   bx = l % 64;  by = l / 64; }
    else if (bid < 4096)  { S0 = wo;  S1 = nullptr; T = WGT + 3072 * DD; Kd = DD;   Ns = DD;   pair = false; int l = bid - 3072;   bx = l % 32;  by = l / 32; }
    else if (bid < 12288) { S0 = wfc; S1 = wfa;     T = WFF;             Kd = DD;   Ns = DFF_; pair = true;  int l = bid - 4096;   bx = l % 256; by = l / 256; }
    else                  { S0 = wou; S1 = nullptr; T = WOUT;            Kd = DFF_; Ns = DD;   pair = false; int l = bid - 12288;  bx = l % 32;  by = l / 32; }

    int n0 = bx * 32, k0 = by * 32;
    const float* S = S0; int col = n0 + tx;
    if (pair) { S = ((n0 + tx) & 1) ? S1 : S0; col = (n0 + tx) >> 1; }
    #pragma unroll
    for (int i = 0; i < 32; i += 8)
        t[ty + i][tx] = S[(size_t)(k0 + ty + i) * Ns + col];
    __syncthreads();
    #pragma unroll
    for (int i = 0; i < 32; i += 8)
        T[(size_t)(n0 + ty + i) * Kd + k0 + tx] = __float2half_rn(t[tx][ty + i]);
}

// ---------------- pipelined HMMA GEMM: 256 threads, 2 CTAs/SM ----------------
// C[M,N] = ACT(A @ B'^T + bias)  A fp16 [M,K] row-major, B' fp16 [N,K] row-major
// ACT 4: v+aux -> C (down-proj, fp32 out)
// ACT 5: gates, N=4096 layout [f | i,g ilv | o]: a->C fp32, bv->C1h fp16, o->C2h fp16
// ACT 6: fused FFN-up, N=8192 ilv (fc,fca): hff=fc*silu(fca) -> Ch fp16
constexpr int BM = 128, BN = 128, BK = 64, STAGES = 3, NT = 256;
constexpr int ASTG = BM * BK * 2;     // 16 KB
constexpr int BSTG = BN * BK * 2;     // 16 KB
constexpr int STG  = ASTG + BSTG;     // 32 KB
constexpr int GSMEM = STAGES * STG;   // 96 KB -> 2 CTAs/SM

template<int ACT>
__global__ __launch_bounds__(NT, 2) void tc_gemm(
    const __half* __restrict__ A, const __half* __restrict__ Bw,
    const float* __restrict__ bias, const float* __restrict__ aux,
    float* __restrict__ C, __half* __restrict__ Ch,
    __half* __restrict__ C1h, __half* __restrict__ C2h,
    int M, int N, int K)
{
    extern __shared__ __align__(128) char smem[];
    uint32_t su = smem_to_u32(smem);
    int tid = threadIdx.x, wid = tid >> 5, lane = tid & 31;

    // supertile raster (8 m-tiles per group) for L2 reuse
    int tn = N / BN;
    int per = 8 * tn, grp = blockIdx.x / per, rr = blockIdx.x % per;
    int m0 = (grp * 8 + (rr % 8)) * BM;
    int n0 = (rr / 8) * BN;

    const __half* Ab = A  + (size_t)m0 * K;
    const __half* Bb = Bw + (size_t)n0 * K;

    // cp.async offsets: A 4 chunks/thread, B 4 chunks/thread (16B chunks)
    uint32_t sAo[4], gAo[4];
    #pragma unroll
    for (int j = 0; j < 4; j++) {
        int idx = tid + j * NT, r = idx >> 3, c = idx & 7;
        sAo[j] = swz(r, c); gAo[j] = (uint32_t)(r * K + c * 8);
    }

    // warp layout: 2 (m) x 4 (n); warp tile 64x32
    int wm = (wid & 1) * 64, wn = (wid >> 1) * 32;
    int rA128[4], rA7[4], rB128[2], rB7[2];
    int cA = lane >> 4;           // 0..1
    int cB = (lane >> 3) & 1;     // 0..1
    #pragma unroll
    for (int i = 0; i < 4; i++) {
        int ra = wm + i * 16 + (lane & 15);
        rA128[i] = ra * 128; rA7[i] = ra & 7;
    }
    #pragma unroll
    for (int p = 0; p < 2; p++) {
        int rb = wn + p * 16 + (lane & 7) + ((lane >> 4) << 3);
        rB128[p] = rb * 128; rB7[p] = rb & 7;
    }

    float acc[4][4][4];
    #pragma unroll
    for (int i = 0; i < 4; i++)
        #pragma unroll
        for (int j = 0; j < 4; j++)
            #pragma unroll
            for (int q = 0; q < 4; q++) acc[i][j][q] = 0.f;

    const int NK = K / BK;

    #pragma unroll
    for (int s = 0; s < STAGES - 1; s++) {
        uint32_t sA = su + s * STG, sB = sA + ASTG;
        int k0 = s * BK;
        #pragma unroll
        for (int j = 0; j < 4; j++) {
            cp_async16(sA + sAo[j], Ab + gAo[j] + k0);
            cp_async16(sB + sAo[j], Bb + gAo[j] + k0);
        }
        cp_commit();
    }

    int cs = 0, ls = STAGES - 1;
    for (int kt = 0; kt < NK; kt++) {
        asm volatile("cp.async.wait_group %0;" :: "n"(STAGES - 2) : "memory");
        __syncthreads();

        int lt = kt + STAGES - 1;
        if (lt < NK) {
            uint32_t sA = su + ls * STG, sB = sA + ASTG;
            int k0 = lt * BK;
            #pragma unroll
            for (int j = 0; j < 4; j++) {
                cp_async16(sA + sAo[j], Ab + gAo[j] + k0);
                cp_async16(sB + sAo[j], Bb + gAo[j] + k0);
            }
        }
        cp_commit();
        if (++ls == STAGES) ls = 0;

        uint32_t sA = su + cs * STG, sB = sA + ASTG;
        if (++cs == STAGES) cs = 0;
        #pragma unroll
        for (int kk = 0; kk < 4; kk++) {
            uint32_t a[4][4], b[2][4];
            #pragma unroll
            for (int i = 0; i < 4; i++)
                ldsm4(a[i], sA + rA128[i] + (((kk * 2 + cA) ^ rA7[i]) << 4));
            #pragma unroll
            for (int p = 0; p < 2; p++)
                ldsm4(b[p], sB + rB128[p] + (((kk * 2 + cB) ^ rB7[p]) << 4));
            #pragma unroll
            for (int p = 0; p < 2; p++)
                #pragma unroll
                for (int i = 0; i < 4; i++) {
                    mma_f16(acc[i][2*p],     a[i], b[p]);
                    mma_f16(acc[i][2*p + 1], a[i], b[p] + 2);
                }
        }
    }

    // ---- fused epilogue ----
    #pragma unroll
    for (int i = 0; i < 4; i++) {
        int r0 = m0 + wm + i * 16 + (lane >> 2);
        #pragma unroll
        for (int j = 0; j < 4; j++) {
            int c0 = n0 + wn + j * 8 + (lane & 3) * 2;
            float b0 = bias[c0], b1 = bias[c0 + 1];
            #pragma unroll
            for (int h = 0; h < 2; h++) {
                int r = r0 + h * 8;
                float v0 = acc[i][j][2*h]     + b0;
                float v1 = acc[i][j][2*h + 1] + b1;
                if (ACT == 4) {
                    size_t idx = (size_t)r * N + c0;
                    float2 au = *reinterpret_cast<const float2*>(&aux[idx]);
                    *reinterpret_cast<float2*>(&C[idx]) = make_float2(v0 + au.x, v1 + au.y);
                } else if (ACT == 5) {
                    if (c0 < 1024) {
                        *reinterpret_cast<float2*>(&C[(size_t)r * DD + c0]) =
                            make_float2(sigmoidf_(v0), sigmoidf_(v1));
                    } else if (c0 < 3072) {
                        C1h[(size_t)r * DD + ((c0 - 1024) >> 1)] =
                            __float2half_rn(tanhf(v0) * sigmoidf_(v1));
                    } else {
                        *reinterpret_cast<__half2*>(&C2h[(size_t)r * DD + (c0 - 3072)]) =
                            __floats2half2_rn(sigmoidf_(v0), sigmoidf_(v1));
                    }
                } else if (ACT == 6) {
                    Ch[(size_t)r * DFF_ + (c0 >> 1)] =
                        __float2half_rn(v0 * (v1 * sigmoidf_(v1)));
                }
            }
        }
    }
}

// ---------------- chunked linear-recurrence scan ----------------
// NCH=128 chunks of 32 steps: 262144 threads in pass1 for memory-level parallelism
__global__ void scan_pass1(const float* __restrict__ aG, const __half* __restrict__ bVh,
                           float* __restrict__ Pb, float* __restrict__ Hb)
{
    int g = blockIdx.x * blockDim.x + threadIdx.x;    // BB*NCH*DD/2 threads
    int d2 = g & (DD/2 - 1);
    int c  = (g >> 9) & (NCH - 1);
    int b  = g >> 16;
    size_t base = ((size_t)b * LL + (size_t)c * CHUNK) * DD + d2 * 2;
    float2 P = make_float2(1.f, 1.f), hh = make_float2(0.f, 0.f);
    #pragma unroll 4
    for (int t = 0; t < CHUNK; t++) {
        size_t idx = base + (size_t)t * DD;
        float2 a  = *reinterpret_cast<const float2*>(aG + idx);
        float2 bv = __half22float2(*reinterpret_cast<const __half2*>(bVh + idx));
        P.x *= a.x; P.y *= a.y;
        hh.x = fmaf(a.x, hh.x, bv.x);
        hh.y = fmaf(a.y, hh.y, bv.y);
    }
    *reinterpret_cast<float2*>(Pb + (size_t)g * 2) = P;
    *reinterpret_cast<float2*>(Hb + (size_t)g * 2) = hh;
}

// pass2: parallel Kogge-Stone scan over the 128 chunks.
// One 128-thread block per (b,d): thread c holds chunk c's (P,H).
// combine (P1,H1)∘(P2,H2) = (P1*P2, H1*P2 + H2); Ib = exclusive ∘ h0.
__global__ __launch_bounds__(128) void scan_pass2(
    const float* __restrict__ Pb, const float* __restrict__ Hb,
    const float* __restrict__ h0, float* __restrict__ Ib)
{
    int bd = blockIdx.x;            // 0..BB*DD-1
    int b = bd >> 10, d = bd & (DD - 1);
    int c = threadIdx.x;            // chunk 0..127
    int lane = c & 31, w = c >> 5;

    size_t j = ((size_t)(b * NCH + c)) * DD + d;
    float P = Pb[j], H = Hb[j];

    // warp-inclusive scan
    #pragma unroll
    for (int s = 1; s < 32; s <<= 1) {
        float Po = __shfl_up_sync(0xffffffffu, P, s);
        float Ho = __shfl_up_sync(0xffffffffu, H, s);
        if (lane >= s) { H = fmaf(Ho, P, H); P = Po * P; }
    }

    // cross-warp prefix
    __shared__ float wp[4], wh[4];
    if (lane == 31) { wp[w] = P; wh[w] = H; }
    __syncthreads();
    float Pp = 1.f, Hp = 0.f;
    #pragma unroll
    for (int i = 0; i < 3; i++)
        if (i < w) { Hp = fmaf(Hp, wp[i], wh[i]); Pp *= wp[i]; }

    // exclusive within warp
    float Pe = __shfl_up_sync(0xffffffffu, P, 1);
    float He = __shfl_up_sync(0xffffffffu, H, 1);
    if (lane == 0) { Pe = 1.f; He = 0.f; }

    // total exclusive = warp-prefix ∘ warp-exclusive
    float Pt = Pp * Pe;
    float Ht = fmaf(Hp, Pe, He);
    Ib[j] = fmaf(Pt, h0[d], Ht);
}

// pass3 fused with RMSNorm2: one block (512 threads) owns a full D=1024 row
// for one (b, chunk). Writes x1 (fp32) AND xn2 (fp16, normalized) directly.
__global__ __launch_bounds__(512) void scan_pass3n(
    const float* __restrict__ aG, const __half* __restrict__ bVh,
    const __half* __restrict__ oSh, const float* __restrict__ x,
    const float* __restrict__ Ib, const float* __restrict__ w2,
    float* __restrict__ x1, __half* __restrict__ xn2)
{
    int b = blockIdx.x >> 7;            // 4 batches
    int c = blockIdx.x & 127;           // 128 chunks
    int tid = threadIdx.x;              // 512 threads, 2 d's each
    int d0 = tid * 2;

    __shared__ float red[16];
    __shared__ float s_scale;

    size_t base = ((size_t)b * LL + (size_t)c * CHUNK) * DD + d0;
    float2 hh = *reinterpret_cast<const float2*>(Ib + ((size_t)(b * NCH + c) * DD + d0));
    float2 w  = *reinterpret_cast<const float2*>(w2 + d0);

    for (int t = 0; t < CHUNK; t++) {
        size_t idx = base + (size_t)t * DD;
        float2 a  = *reinterpret_cast<const float2*>(aG + idx);
        float2 bv = __half22float2(*reinterpret_cast<const __half2*>(bVh + idx));
        float2 os = __half22float2(*reinterpret_cast<const __half2*>(oSh + idx));
        float2 xv = *reinterpret_cast<const float2*>(x + idx);
        hh.x = fmaf(a.x, hh.x, bv.x);
        hh.y = fmaf(a.y, hh.y, bv.y);
        float y0 = tanhf(hh.x) * os.x + xv.x;
        float y1 = tanhf(hh.y) * os.y + xv.y;
        *reinterpret_cast<float2*>(x1 + idx) = make_float2(y0, y1);

        // block-reduce sum of squares over D=1024 (512 threads x 2)
        float ss = y0 * y0 + y1 * y1;
        #pragma unroll
        for (int of = 16; of > 0; of >>= 1) ss += __shfl_xor_sync(0xffffffffu, ss, of);
        if ((tid & 31) == 0) red[tid >> 5] = ss;
        __syncthreads();
        if (tid < 32) {
            float v = (tid < 16) ? red[tid] : 0.f;
            #pragma unroll
            for (int of = 8; of > 0; of >>= 1) v += __shfl_xor_sync(0xffffffffu, v, of);
            if (tid == 0) s_scale = rsqrtf(v / (float)DD + 1e-6f);
        }
        __syncthreads();
        float s = s_scale;
        *reinterpret_cast<__half2*>(xn2 + idx) =
            __floats2half2_rn(y0 * s * w.x, y1 * s * w.y);
        __syncthreads();   // protect s_scale for next t
    }
}

// ---------------- launcher ----------------
extern "C" void kernel_launch(void* const* d_in, const int* in_sizes, int n_in,
                              void* d_out, int out_size)
{
    (void)in_sizes; (void)n_in; (void)out_size;
    const float* x   = (const float*)d_in[0];
    const float* wf  = (const float*)d_in[1];
    const float* bf_ = (const float*)d_in[2];
    const float* wi  = (const float*)d_in[3];
    const float* bi_ = (const float*)d_in[4];
    const float* wg  = (const float*)d_in[5];
    const float* bg_ = (const float*)d_in[6];
    const float* wo  = (const float*)d_in[7];
    const float* bo_ = (const float*)d_in[8];
    const float* h0  = (const float*)d_in[9];
    const float* n1w = (const float*)d_in[10];
    const float* n2w = (const float*)d_in[11];
    const float* wfc = (const float*)d_in[12];
    const float* bfc = (const float*)d_in[13];
    const float* wfa = (const float*)d_in[14];
    const float* bfa = (const float*)d_in[15];
    const float* wou = (const float*)d_in[16];
    const float* bou = (const float*)d_in[17];
    float* out = (float*)d_out;

    float *ga, *x1, *P, *H, *I, *bg4, *bff;
    cudaGetSymbolAddress((void**)&ga,  g_a);
    cudaGetSymbolAddress((void**)&x1,  g_x1);
    cudaGetSymbolAddress((void**)&P,   g_P);
    cudaGetSymbolAddress((void**)&H,   g_H);
    cudaGetSymbolAddress((void**)&I,   g_I);
    cudaGetSymbolAddress((void**)&bg4, g_bg);
    cudaGetSymbolAddress((void**)&bff, g_bff);

    __half *gbvh, *goh, *xn, *xn2, *hff, *wgt, *wff, *wout_;
    cudaGetSymbolAddress((void**)&gbvh, g_bvh);
    cudaGetSymbolAddress((void**)&goh,  g_oh);
    cudaGetSymbolAddress((void**)&xn,   g_xn);
    cudaGetSymbolAddress((void**)&xn2,  g_xn2);
    cudaGetSymbolAddress((void**)&hff,  g_hff);
    cudaGetSymbolAddress((void**)&wgt,  g_wgt);
    cudaGetSymbolAddress((void**)&wff,  g_wff);
    cudaGetSymbolAddress((void**)&wout_,g_wout);

    cudaFuncSetAttribute(tc_gemm<4>, cudaFuncAttributeMaxDynamicSharedMemorySize, GSMEM);
    cudaFuncSetAttribute(tc_gemm<5>, cudaFuncAttributeMaxDynamicSharedMemorySize, GSMEM);
    cudaFuncSetAttribute(tc_gemm<6>, cudaFuncAttributeMaxDynamicSharedMemorySize, GSMEM);

    // 0) fused weight/bias packing + RMSNorm1 (single launch, overlapped)
    pack_norm<<<PACK_BLKS + MM, 256>>>(wf, wi, wg, wo, wfc, wfa, wou,
                                       bf_, bi_, bg_, bo_, bfc, bfa,
                                       x, n1w,
                                       wgt, wff, wout_, bg4, bff, xn);

    // 1) gate GEMM (N=4096) -> a (fp32), bv (fp16), o (fp16)
    int gGates = (MM/BM) * ((4*DD)/BN);
    tc_gemm<5><<<gGates, NT, GSMEM>>>(xn, wgt, bg4, nullptr, ga, nullptr, gbvh, goh,
                                      MM, 4*DD, DD);

    // 2) scan + output gate + residual + fused RMSNorm2 -> x1 (fp32), xn2 (fp16)
    scan_pass1<<<(BB*NCH*DD/2)/256, 256>>>(ga, gbvh, P, H);
    scan_pass2<<<BB*DD, 128>>>(P, H, h0, I);
    scan_pass3n<<<BB*NCH, 512>>>(ga, gbvh, goh, x, I, n2w, x1, xn2);

    // 3) fused FFN-up (N=8192, interleaved) -> hff fp16
    int gFF = (MM/BM) * ((2*DFF_)/BN);
    tc_gemm<6><<<gFF, NT, GSMEM>>>(xn2, wff, bff, nullptr, nullptr, hff, nullptr, nullptr,
                                   MM, 2*DFF_, DD);

    // 4) down-proj + b_out + x1 -> d_out
    int gOut = (MM/BM) * (DD/BN);
    tc_gemm<4><<<gOut, NT, GSMEM>>>(hff, wout_, bou, x1, out, nullptr, nullptr, nullptr,
                                    MM, DD, DFF_);
}